// round 1
// baseline (speedup 1.0000x reference)
#include <cuda_runtime.h>
#include <math.h>

// ---------------- problem constants ----------------
#define B_    16
#define T_    12
#define N_    2048
#define D_    128
#define INNER_ 256
#define KC_   4
#define BT_   (B_*T_)          // 192
#define ROWS_ (B_*T_*N_)       // 393216 tokens
#define BN_   (B_*N_)          // 32768

// ---------------- scratch (device globals; allocation-free path) ----------------
#define SZ_H  ((size_t)ROWS_*D_)        // 50331648
#define SZ_PR ((size_t)ROWS_*512)       // 201326592
#define SZ_I  ((size_t)ROWS_*INNER_)    // 100663296

__device__ __align__(16) float g_hidA[SZ_H];
__device__ __align__(16) float g_hidB[SZ_H];
__device__ __align__(16) float g_sp  [SZ_H];
__device__ __align__(16) float g_h2  [SZ_H];
__device__ __align__(16) float g_x   [SZ_H];
__device__ __align__(16) float g_tp  [SZ_H];
__device__ __align__(16) float g_pr  [SZ_PR];
__device__ __align__(16) float g_sig [SZ_I];
__device__ __align__(16) float g_dl  [SZ_I];
__device__ __align__(16) float g_si  [SZ_I];
__device__ __align__(16) float g_so  [SZ_I];
__device__ __align__(16) float g_y   [SZ_I];

// ---------------- helpers ----------------
__device__ __forceinline__ float sigmoidf_(float x) { return 1.f / (1.f + expf(-x)); }
__device__ __forceinline__ float softplusf_(float x) {
    return fmaxf(x, 0.f) + log1pf(expf(-fabsf(x)));
}
__device__ __forceinline__ float geluf_(float x) {
    return 0.5f * x * (1.f + erff(x * 0.7071067811865475f));
}

// 8x8 per-thread microtile over a 16-deep k-slab.
// As/Bs layout: [k][128], thread (ty,tx) covers rows {ty*4+i, 64+ty*4+i},
// cols {tx*4+j, 64+tx*4+j} -> conflict-free float4 LDS.
__device__ __forceinline__ void mma_tile(const float* __restrict__ As,
                                         const float* __restrict__ Bs,
                                         int ty, int tx, float (&acc)[8][8])
{
#pragma unroll
    for (int kk = 0; kk < 16; kk++) {
        const float* ar = As + kk * 128;
        const float* br = Bs + kk * 128;
        float4 a0 = *(const float4*)(ar + ty * 4);
        float4 a1 = *(const float4*)(ar + 64 + ty * 4);
        float4 b0 = *(const float4*)(br + tx * 4);
        float4 b1 = *(const float4*)(br + 64 + tx * 4);
        float a[8] = {a0.x, a0.y, a0.z, a0.w, a1.x, a1.y, a1.z, a1.w};
        float b[8] = {b0.x, b0.y, b0.z, b0.w, b1.x, b1.y, b1.z, b1.w};
#pragma unroll
        for (int i = 0; i < 8; i++)
#pragma unroll
            for (int j = 0; j < 8; j++)
                acc[i][j] = fmaf(a[i], b[j], acc[i][j]);
    }
}

// ---------------- einsum GEMM: C[z,m,d] = sum_n S[n,m] * H[z,n,d] ----------------
// grid: (N/128, 1, BT). A tile is k-major (S rows are contiguous in m).
__global__ void __launch_bounds__(256) gemm_support_kernel(
    const float* __restrict__ S, const float* __restrict__ H, float* __restrict__ C)
{
    __shared__ float As[2][16 * 128];
    __shared__ float Bs[2][16 * 128];
    const int z  = blockIdx.z;
    const int m0 = blockIdx.x * 128;
    const float* Hz = H + (size_t)z * N_ * D_;
    float*       Cz = C + (size_t)z * N_ * D_;
    const int tid = threadIdx.x;
    const int tx = tid & 15, ty = tid >> 4;

    float acc[8][8] = {};
    const int NT = N_ / 16;  // 128 k-tiles

    auto loadG = [&](int k0, float4 (&ra)[2], float4 (&rb)[2]) {
#pragma unroll
        for (int i = 0; i < 2; i++) {
            int f = tid + i * 256;
            int k = f >> 5, q = f & 31;
            ra[i] = *(const float4*)(S  + (size_t)(k0 + k) * N_ + m0 + q * 4);
            rb[i] = *(const float4*)(Hz + (size_t)(k0 + k) * D_ + q * 4);
        }
    };
    auto storeS = [&](int p, const float4 (&ra)[2], const float4 (&rb)[2]) {
#pragma unroll
        for (int i = 0; i < 2; i++) {
            int f = tid + i * 256;
            int k = f >> 5, q = f & 31;
            *(float4*)&As[p][k * 128 + q * 4] = ra[i];
            *(float4*)&Bs[p][k * 128 + q * 4] = rb[i];
        }
    };

    float4 ra[2], rb[2];
    loadG(0, ra, rb);
    storeS(0, ra, rb);
    __syncthreads();
    int p = 0;
    for (int kt = 0; kt < NT; kt++) {
        bool more = (kt + 1 < NT);
        if (more) loadG((kt + 1) * 16, ra, rb);
        mma_tile(As[p], Bs[p], ty, tx, acc);
        if (more) {
            storeS(p ^ 1, ra, rb);
            __syncthreads();
            p ^= 1;
        }
    }
#pragma unroll
    for (int ih = 0; ih < 2; ih++)
#pragma unroll
        for (int i = 0; i < 4; i++) {
            int m = m0 + ih * 64 + ty * 4 + i;
            float* crow = Cz + (size_t)m * D_;
#pragma unroll
            for (int jh = 0; jh < 2; jh++) {
                int jj = jh * 64 + tx * 4;
                float4 v = make_float4(acc[ih * 4 + i][jh * 4 + 0], acc[ih * 4 + i][jh * 4 + 1],
                                       acc[ih * 4 + i][jh * 4 + 2], acc[ih * 4 + i][jh * 4 + 3]);
                *(float4*)(crow + jj) = v;
            }
        }
}

// ---------------- generic row GEMM: C[r,j] = act( X[r,:]·W[:,j] + bias[j] ) ------
// ACT: 0 none, 1 softplus, 2 tanh.  ACC: C += dot (no bias/act).
template <int ACT, bool ACC, bool BIAS>
__global__ void __launch_bounds__(256) gemm_rows_kernel(
    const float* __restrict__ X, const float* __restrict__ W,
    const float* __restrict__ bias, float* __restrict__ C,
    int Kdim, int ldw, int ldc)
{
    __shared__ float As[2][16 * 128];
    __shared__ float Bs[2][16 * 128];
    const int r0 = blockIdx.y * 128;
    const int j0 = blockIdx.x * 128;
    const int tid = threadIdx.x;
    const int tx = tid & 15, ty = tid >> 4;

    float acc[8][8] = {};
    const int NT = Kdim >> 4;

    auto loadG = [&](int k0, float4 (&ra)[2], float4 (&rb)[2]) {
#pragma unroll
        for (int i = 0; i < 2; i++) {
            int f = tid + i * 256;
            int r = f >> 2, kq = f & 3;
            ra[i] = *(const float4*)(X + (size_t)(r0 + r) * Kdim + k0 + kq * 4);
            int k = f >> 5, q = f & 31;
            rb[i] = *(const float4*)(W + (size_t)(k0 + k) * ldw + j0 + q * 4);
        }
    };
    auto storeS = [&](int p, const float4 (&ra)[2], const float4 (&rb)[2]) {
#pragma unroll
        for (int i = 0; i < 2; i++) {
            int f = tid + i * 256;
            int r = f >> 2, kq = f & 3;
            const float v[4] = {ra[i].x, ra[i].y, ra[i].z, ra[i].w};
#pragma unroll
            for (int u = 0; u < 4; u++) As[p][(kq * 4 + u) * 128 + r] = v[u];
            int k = f >> 5, q = f & 31;
            *(float4*)&Bs[p][k * 128 + q * 4] = rb[i];
        }
    };

    float4 ra[2], rb[2];
    loadG(0, ra, rb);
    storeS(0, ra, rb);
    __syncthreads();
    int p = 0;
    for (int kt = 0; kt < NT; kt++) {
        bool more = (kt + 1 < NT);
        if (more) loadG((kt + 1) * 16, ra, rb);
        mma_tile(As[p], Bs[p], ty, tx, acc);
        if (more) {
            storeS(p ^ 1, ra, rb);
            __syncthreads();
            p ^= 1;
        }
    }
#pragma unroll
    for (int ih = 0; ih < 2; ih++)
#pragma unroll
        for (int i = 0; i < 4; i++) {
            int r = r0 + ih * 64 + ty * 4 + i;
            float* crow = C + (size_t)r * ldc + j0;
#pragma unroll
            for (int jh = 0; jh < 2; jh++) {
                int jj = jh * 64 + tx * 4;
                float4 v = make_float4(acc[ih * 4 + i][jh * 4 + 0], acc[ih * 4 + i][jh * 4 + 1],
                                       acc[ih * 4 + i][jh * 4 + 2], acc[ih * 4 + i][jh * 4 + 3]);
                if (BIAS) {
                    float4 bv = *(const float4*)(bias + j0 + jj);
                    v.x += bv.x; v.y += bv.y; v.z += bv.z; v.w += bv.w;
                }
                if (ACC) {
                    float4 o = *(const float4*)(crow + jj);
                    v.x += o.x; v.y += o.y; v.z += o.z; v.w += o.w;
                }
                if (ACT == 1) {
                    v.x = softplusf_(v.x); v.y = softplusf_(v.y);
                    v.z = softplusf_(v.z); v.w = softplusf_(v.w);
                } else if (ACT == 2) {
                    v.x = tanhf(v.x); v.y = tanhf(v.y);
                    v.z = tanhf(v.z); v.w = tanhf(v.w);
                }
                *(float4*)(crow + jj) = v;
            }
        }
}

// ---------------- transpose h(b,t,n,d) -> x(b*n, t, d) ----------------
__global__ void transpose_bt_kernel(const float* __restrict__ h, float* __restrict__ x)
{
    size_t gid = (size_t)blockIdx.x * blockDim.x + threadIdx.x;
    if (gid >= (size_t)ROWS_ * 32) return;
    int q = (int)(gid & 31);
    int r = (int)(gid >> 5);          // bn*T + t
    int t = r % T_;
    int bn = r / T_;
    int n = bn % N_;
    int b = bn / N_;
    size_t src = ((size_t)((b * T_ + t) * N_) + n) * D_ + q * 4;
    *(float4*)(x + (size_t)r * D_ + q * 4) = *(const float4*)(h + src);
}

// ---------------- causal depthwise conv (K=4) + SiLU ----------------
// reads signal half of pr (cols 0..255), writes g_sig (bn,t,c)
__global__ void conv_silu_kernel(const float* __restrict__ pr, const float* __restrict__ cw,
                                 const float* __restrict__ cb, float* __restrict__ sig)
{
    int idx = blockIdx.x * blockDim.x + threadIdx.x;   // BN_*INNER_ threads exactly
    int c = idx & (INNER_ - 1);
    int bn = idx >> 8;
    float w0 = cw[c * 4 + 0], w1 = cw[c * 4 + 1], w2 = cw[c * 4 + 2], w3 = cw[c * 4 + 3];
    float b = cb[c];
    float s[T_];
    size_t base = (size_t)bn * T_ * 512 + c;
#pragma unroll
    for (int t = 0; t < T_; t++) s[t] = pr[base + (size_t)t * 512];
    size_t ob = (size_t)bn * T_ * INNER_ + c;
#pragma unroll
    for (int t = 0; t < T_; t++) {
        float a = b + w3 * s[t];
        if (t >= 1) a += w2 * s[t - 1];
        if (t >= 2) a += w1 * s[t - 2];
        if (t >= 3) a += w0 * s[t - 3];
        sig[ob + (size_t)t * INNER_] = a * sigmoidf_(a);
    }
}

// ---------------- selective-scan over T + sigmoid gating ----------------
__global__ void scan_kernel(const float* __restrict__ sig, const float* __restrict__ dl,
                            const float* __restrict__ si, const float* __restrict__ so,
                            const float* __restrict__ pr, const float* __restrict__ a_log,
                            const float* __restrict__ d_skip, float* __restrict__ y)
{
    int idx = blockIdx.x * blockDim.x + threadIdx.x;
    int c = idx & (INNER_ - 1);
    int bn = idx >> 8;
    float a = -softplusf_(a_log[c]);
    float dsk = d_skip[c];
    float state = 0.f;
    size_t b256 = (size_t)bn * T_ * INNER_ + c;
    size_t bpr  = (size_t)bn * T_ * 512 + INNER_ + c;
#pragma unroll
    for (int t = 0; t < T_; t++) {
        float x  = sig[b256 + (size_t)t * INNER_];
        float d  = dl [b256 + (size_t)t * INNER_];
        float iv = si [b256 + (size_t)t * INNER_];
        float ov = so [b256 + (size_t)t * INNER_];
        state = expf(d * a) * state + iv * x;
        float yy = ov * state + dsk * x;
        float g = pr[bpr + (size_t)t * 512];
        y[b256 + (size_t)t * INNER_] = yy * sigmoidf_(g);
    }
}

// ---------------- fusion (h + sp + tp + sp*tp) + LayerNorm ----------------
// sp arrives pre-activation: apply gcn bias + exact GELU here.
__global__ void fuse_ln_kernel(const float* __restrict__ h_in, const float* __restrict__ sp_pre,
                               const float* __restrict__ gcn_b, const float* __restrict__ tp,
                               const float* __restrict__ ln_g, const float* __restrict__ ln_b,
                               float* __restrict__ h_out)
{
    int token = blockIdx.x;           // (b*T+t)*N + n
    int d = threadIdx.x;              // 128
    int n  = token % N_;
    int bt = token / N_;
    int t  = bt % T_;
    int b  = bt / T_;
    size_t row    = (size_t)token * D_;
    size_t row_tp = ((size_t)(b * N_ + n) * T_ + t) * D_;

    float hv = h_in[row + d];
    float s = sp_pre[row + d] + gcn_b[d];
    s = geluf_(s);
    float tv = tp[row_tp + d];
    float f = hv + s + tv + s * tv;

    __shared__ float red[8];
    float v = f;
#pragma unroll
    for (int o = 16; o > 0; o >>= 1) v += __shfl_xor_sync(0xffffffffu, v, o);
    if ((d & 31) == 0) red[d >> 5] = v;
    __syncthreads();
    float mu = (red[0] + red[1] + red[2] + red[3]) * (1.f / 128.f);
    float dv = f - mu;
    v = dv * dv;
#pragma unroll
    for (int o = 16; o > 0; o >>= 1) v += __shfl_xor_sync(0xffffffffu, v, o);
    if ((d & 31) == 0) red[4 + (d >> 5)] = v;
    __syncthreads();
    float var = (red[4] + red[5] + red[6] + red[7]) * (1.f / 128.f);
    h_out[row + d] = dv * rsqrtf(var + 1e-5f) * ln_g[d] + ln_b[d];
}

// ---------------- host launcher ----------------
extern "C" void kernel_launch(void* const* d_in, const int* in_sizes, int n_in,
                              void* d_out, int out_size)
{
    (void)in_sizes; (void)n_in; (void)out_size;
    const float* inputs   = (const float*)d_in[0];
    const float* supports = (const float*)d_in[1];
    const float* gcn_w    = (const float*)d_in[2];
    const float* gcn_b    = (const float*)d_in[3];
    const float* in_w     = (const float*)d_in[4];
    const float* in_b     = (const float*)d_in[5];
    const float* conv_w   = (const float*)d_in[6];
    const float* conv_b   = (const float*)d_in[7];
    const float* delta_w  = (const float*)d_in[8];
    const float* delta_b  = (const float*)d_in[9];
    const float* si_w     = (const float*)d_in[10];
    const float* si_b     = (const float*)d_in[11];
    const float* so_w     = (const float*)d_in[12];
    const float* so_b     = (const float*)d_in[13];
    const float* a_log    = (const float*)d_in[14];
    const float* d_skip   = (const float*)d_in[15];
    const float* out_w    = (const float*)d_in[16];
    const float* out_b    = (const float*)d_in[17];
    const float* ln_g     = (const float*)d_in[18];
    const float* ln_b     = (const float*)d_in[19];

    float *hidA, *hidB, *sp, *h2, *x, *tp, *pr, *sig, *dl, *si, *so, *y;
    cudaGetSymbolAddress((void**)&hidA, g_hidA);
    cudaGetSymbolAddress((void**)&hidB, g_hidB);
    cudaGetSymbolAddress((void**)&sp,   g_sp);
    cudaGetSymbolAddress((void**)&h2,   g_h2);
    cudaGetSymbolAddress((void**)&x,    g_x);
    cudaGetSymbolAddress((void**)&tp,   g_tp);
    cudaGetSymbolAddress((void**)&pr,   g_pr);
    cudaGetSymbolAddress((void**)&sig,  g_sig);
    cudaGetSymbolAddress((void**)&dl,   g_dl);
    cudaGetSymbolAddress((void**)&si,   g_si);
    cudaGetSymbolAddress((void**)&so,   g_so);
    cudaGetSymbolAddress((void**)&y,    g_y);

    const dim3 blk(256);
    const dim3 gsup(N_ / 128, 1, BT_);     // (16,1,192)
    const dim3 g128(1, ROWS_ / 128);       // J=128
    const dim3 g256(2, ROWS_ / 128);       // J=256
    const dim3 g512(4, ROWS_ / 128);       // J=512
    const int ew_blocks = (BN_ * INNER_) / 256;   // 32768

    for (int l = 0; l < 2; l++) {
        const float* h_in  = (l == 0) ? inputs : h2;
        float*       h_out = (l == 0) ? h2 : (float*)d_out;
        const float* gw  = gcn_w  + (size_t)l * 640 * 128;
        const float* gb  = gcn_b  + l * 128;
        const float* iw  = in_w   + (size_t)l * 128 * 512;
        const float* ib  = in_b   + l * 512;
        const float* cw  = conv_w + (size_t)l * INNER_ * KC_;
        const float* cb  = conv_b + l * INNER_;
        const float* dw  = delta_w + (size_t)l * INNER_ * INNER_;
        const float* db  = delta_b + l * INNER_;
        const float* siw = si_w + (size_t)l * INNER_ * INNER_;
        const float* sib = si_b + l * INNER_;
        const float* sow = so_w + (size_t)l * INNER_ * INNER_;
        const float* sob = so_b + l * INNER_;
        const float* al  = a_log  + l * INNER_;
        const float* dsk = d_skip + l * INNER_;
        const float* ow  = out_w + (size_t)l * INNER_ * 128;
        const float* ob  = out_b + l * 128;
        const float* lg  = ln_g + l * 128;
        const float* lb  = ln_b + l * 128;
        const float* s0 = supports;
        const float* s1 = supports + (size_t)N_ * N_;

        // --- spatial (GCN) branch: sp_pre = h@W0 + A0h@W1 + A0^2h@W2 + A1h@W3 + A1^2h@W4
        gemm_rows_kernel<0, false, false><<<g128, blk>>>(h_in, gw,                nullptr, sp, 128, 128, 128);
        gemm_support_kernel<<<gsup, blk>>>(s0, h_in, hidA);
        gemm_rows_kernel<0, true,  false><<<g128, blk>>>(hidA, gw + 1 * 128 * 128, nullptr, sp, 128, 128, 128);
        gemm_support_kernel<<<gsup, blk>>>(s0, hidA, hidB);
        gemm_rows_kernel<0, true,  false><<<g128, blk>>>(hidB, gw + 2 * 128 * 128, nullptr, sp, 128, 128, 128);
        gemm_support_kernel<<<gsup, blk>>>(s1, h_in, hidA);
        gemm_rows_kernel<0, true,  false><<<g128, blk>>>(hidA, gw + 3 * 128 * 128, nullptr, sp, 128, 128, 128);
        gemm_support_kernel<<<gsup, blk>>>(s1, hidA, hidB);
        gemm_rows_kernel<0, true,  false><<<g128, blk>>>(hidB, gw + 4 * 128 * 128, nullptr, sp, 128, 128, 128);

        // --- temporal branch
        transpose_bt_kernel<<<(ROWS_ * 32) / 256, 256>>>(h_in, x);
        gemm_rows_kernel<0, false, true><<<g512, blk>>>(x, iw, ib, pr, 128, 512, 512);
        conv_silu_kernel<<<ew_blocks, 256>>>(pr, cw, cb, sig);
        gemm_rows_kernel<1, false, true><<<g256, blk>>>(sig, dw,  db,  dl, 256, 256, 256);
        gemm_rows_kernel<2, false, true><<<g256, blk>>>(sig, siw, sib, si, 256, 256, 256);
        gemm_rows_kernel<2, false, true><<<g256, blk>>>(sig, sow, sob, so, 256, 256, 256);
        scan_kernel<<<ew_blocks, 256>>>(sig, dl, si, so, pr, al, dsk, y);
        gemm_rows_kernel<0, false, true><<<g128, blk>>>(y, ow, ob, tp, 256, 128, 128);

        // --- fusion + layernorm
        fuse_ln_kernel<<<ROWS_, 128>>>(h_in, sp, gb, tp, lg, lb, h_out);
    }
}

// round 4
// speedup vs baseline: 1.3664x; 1.3664x over previous
#include <cuda_runtime.h>
#include <cuda_bf16.h>
#include <math.h>
#include <stdint.h>

// ---------------- problem constants ----------------
#define B_    16
#define T_    12
#define N_    2048
#define D_    128
#define INNER_ 256
#define KC_   4
#define BT_   (B_*T_)          // 192
#define ROWS_ (B_*T_*N_)       // 393216 tokens
#define BN_   (B_*N_)          // 32768
#define NN_   ((size_t)N_*N_)

// ---------------- scratch (device globals; ~3.26 GB total, below reloc limit) ----
#define SZ_H  ((size_t)ROWS_*D_)
#define SZ_PR ((size_t)ROWS_*512)
#define SZ_I  ((size_t)ROWS_*INNER_)

__device__ __align__(16) float g_hidA[SZ_H];
__device__ __align__(16) float g_hidB[SZ_H];
__device__ __align__(16) float g_sp  [SZ_H];
__device__ __align__(16) float g_h2  [SZ_H];
__device__ __align__(16) float g_x   [SZ_H];    // also used as tp
__device__ __align__(16) float g_pr  [SZ_PR];   // cols 0..255 reused for si after conv
__device__ __align__(16) float g_sig [SZ_I];
__device__ __align__(16) float g_dl  [SZ_I];    // also used as y
__device__ __align__(16) float g_so  [SZ_I];

// bf16 split buffers for HMMA einsum
__device__ __align__(16) __nv_bfloat16 g_Sthi[2*NN_];                 // S^T hi  [i][m][k]
__device__ __align__(16) __nv_bfloat16 g_Stlo[2*NN_];                 // S^T lo
__device__ __align__(16) __nv_bfloat16 g_Hthi[(size_t)BT_*D_*N_];     // H^T hi  [z][d][k]
__device__ __align__(16) __nv_bfloat16 g_Htlo[(size_t)BT_*D_*N_];     // H^T lo

// ---------------- helpers ----------------
__device__ __forceinline__ float sigmoidf_(float x) { return 1.f / (1.f + expf(-x)); }
__device__ __forceinline__ float softplusf_(float x) {
    return fmaxf(x, 0.f) + log1pf(expf(-fabsf(x)));
}
__device__ __forceinline__ float geluf_(float x) {
    return 0.5f * x * (1.f + erff(x * 0.7071067811865475f));
}
__device__ __forceinline__ uint32_t smem_u32_(const void* p) {
    uint32_t a;
    asm("{ .reg .u64 t; cvta.to.shared.u64 t, %1; cvt.u32.u64 %0, t; }" : "=r"(a) : "l"(p));
    return a;
}
__device__ __forceinline__ void ldsm4_(uint32_t* r, uint32_t a) {
    asm volatile("ldmatrix.sync.aligned.m8n8.x4.shared.b16 {%0,%1,%2,%3}, [%4];"
        : "=r"(r[0]), "=r"(r[1]), "=r"(r[2]), "=r"(r[3]) : "r"(a));
}
__device__ __forceinline__ void mma16816_(float* d, const uint32_t* a, uint32_t b0, uint32_t b1) {
    asm volatile(
        "mma.sync.aligned.m16n8k16.row.col.f32.bf16.bf16.f32 "
        "{%0,%1,%2,%3}, {%4,%5,%6,%7}, {%8,%9}, {%0,%1,%2,%3};"
        : "+f"(d[0]), "+f"(d[1]), "+f"(d[2]), "+f"(d[3])
        : "r"(a[0]), "r"(a[1]), "r"(a[2]), "r"(a[3]), "r"(b0), "r"(b1));
}

// ---------------- bf16-split conversions (with transpose) ----------------
// St[i][m][k] = S[i][k][m]
__global__ void convt_S(const float* __restrict__ S,
                        __nv_bfloat16* __restrict__ hi, __nv_bfloat16* __restrict__ lo)
{
    __shared__ float t[32][33];
    const int k0 = blockIdx.x * 32, m0 = blockIdx.y * 32, i = blockIdx.z;
    const int tx = threadIdx.x & 31, ty = threadIdx.x >> 5;
    const float* Si = S + (size_t)i * NN_;
    for (int r = ty; r < 32; r += 8)
        t[r][tx] = Si[(size_t)(k0 + r) * N_ + m0 + tx];
    __syncthreads();
    for (int r = ty; r < 32; r += 8) {
        float v = t[tx][r];
        size_t o = (size_t)i * NN_ + (size_t)(m0 + r) * N_ + k0 + tx;
        __nv_bfloat16 h = __float2bfloat16(v);
        hi[o] = h;
        lo[o] = __float2bfloat16(v - __bfloat162float(h));
    }
}
// Ht[z][d][n] = H[z][n][d]
__global__ void convt_H(const float* __restrict__ H,
                        __nv_bfloat16* __restrict__ hi, __nv_bfloat16* __restrict__ lo)
{
    __shared__ float t[32][33];
    const int n0 = blockIdx.x * 32, d0 = blockIdx.y * 32, z = blockIdx.z;
    const int tx = threadIdx.x & 31, ty = threadIdx.x >> 5;
    const float* Hz = H + (size_t)z * N_ * D_;
    for (int r = ty; r < 32; r += 8)
        t[r][tx] = Hz[(size_t)(n0 + r) * D_ + d0 + tx];
    __syncthreads();
    for (int r = ty; r < 32; r += 8) {
        float v = t[tx][r];
        size_t o = ((size_t)z * D_ + d0 + r) * N_ + n0 + tx;
        __nv_bfloat16 h = __float2bfloat16(v);
        hi[o] = h;
        lo[o] = __float2bfloat16(v - __bfloat162float(h));
    }
}

// ---------------- HMMA support einsum ----------------
// C[z][m][d] = sum_k St[m][k] * Ht[z][d][k]; M-tile 128, N(d)=128, K=2048, k-chunk 32.
// Split-2 bf16: acc += Ahi*Bhi + Ahi*Blo + Alo*Bhi.
#define STRD_ 80
#define TILEB_ (128 * STRD_)          // 10240 bytes per operand tile
#define STAGEB_ (4 * TILEB_)          // 40960 bytes per stage
#define SMEM_MMA (2 * STAGEB_)        // 81920

__global__ void __launch_bounds__(256)
gemm_support_mma(const __nv_bfloat16* __restrict__ Ah, const __nv_bfloat16* __restrict__ Al,
                 const __nv_bfloat16* __restrict__ Bh, const __nv_bfloat16* __restrict__ Bl,
                 float* __restrict__ C)
{
    extern __shared__ char smem[];
    const uint32_t sbase = smem_u32_(smem);
    const int m0  = blockIdx.x * 128;
    const int z   = blockIdx.y;
    const int tid = threadIdx.x;
    const int wid = tid >> 5, lid = tid & 31;
    const int wm = wid & 3, wn = wid >> 2;       // 4 x 2 warp grid
    const int m_off = wm * 32, n_off = wn * 64;

    const __nv_bfloat16* gp[4] = {
        Ah + (size_t)m0 * N_, Al + (size_t)m0 * N_,
        Bh + (size_t)z * D_ * N_, Bl + (size_t)z * D_ * N_ };

    auto load_stage = [&](int buf, int k0) {
        uint32_t base = sbase + buf * STAGEB_;
#pragma unroll
        for (int i = 0; i < 8; i++) {
            int idx = i * 256 + tid;          // 0..2047
            int tile = idx >> 9;
            int rem = idx & 511;
            int r = rem >> 2, c = rem & 3;
            uint32_t dst = base + tile * TILEB_ + r * STRD_ + c * 16;
            const void* src = gp[tile] + (size_t)r * N_ + k0 + c * 8;
            asm volatile("cp.async.cg.shared.global [%0], [%1], 16;" :: "r"(dst), "l"(src));
        }
        asm volatile("cp.async.commit_group;" ::: "memory");
    };

    float acc[2][8][4];
#pragma unroll
    for (int mt = 0; mt < 2; mt++)
#pragma unroll
        for (int nt = 0; nt < 8; nt++)
#pragma unroll
            for (int q = 0; q < 4; q++) acc[mt][nt][q] = 0.f;

    const int a_row = m_off + (lid & 15);
    const int a_kc  = (lid >> 4) << 3;
    const int b_row = n_off + ((lid >> 4) << 3) + (lid & 7);
    const int b_kc  = ((lid >> 3) & 1) << 3;

    const int NT = N_ / 32;   // 64
    load_stage(0, 0);
    for (int kt = 0; kt < NT; kt++) {
        if (kt + 1 < NT) {
            load_stage((kt + 1) & 1, (kt + 1) * 32);
            asm volatile("cp.async.wait_group 1;" ::: "memory");
        } else {
            asm volatile("cp.async.wait_group 0;" ::: "memory");
        }
        __syncthreads();

        const uint32_t stg = sbase + (kt & 1) * STAGEB_;
        const uint32_t bAH = stg, bAL = stg + TILEB_, bBH = stg + 2 * TILEB_, bBL = stg + 3 * TILEB_;
#pragma unroll
        for (int k16 = 0; k16 < 2; k16++) {
            const int kb = k16 * 16;
            uint32_t ah[2][4], al[2][4];
#pragma unroll
            for (int mt = 0; mt < 2; mt++) {
                uint32_t ao = (uint32_t)((a_row + mt * 16) * STRD_ + (kb + a_kc) * 2);
                ldsm4_(ah[mt], bAH + ao);
                ldsm4_(al[mt], bAL + ao);
            }
#pragma unroll
            for (int pt = 0; pt < 4; pt++) {
                uint32_t bo = (uint32_t)((b_row + pt * 16) * STRD_ + (kb + b_kc) * 2);
                uint32_t bh[4], bl[4];
                ldsm4_(bh, bBH + bo);
                ldsm4_(bl, bBL + bo);
#pragma unroll
                for (int mt = 0; mt < 2; mt++) {
#pragma unroll
                    for (int sub = 0; sub < 2; sub++) {
                        const int nt = pt * 2 + sub;
                        mma16816_(acc[mt][nt], ah[mt], bh[2 * sub], bh[2 * sub + 1]);
                        mma16816_(acc[mt][nt], ah[mt], bl[2 * sub], bl[2 * sub + 1]);
                        mma16816_(acc[mt][nt], al[mt], bh[2 * sub], bh[2 * sub + 1]);
                    }
                }
            }
        }
        __syncthreads();
    }

    // epilogue
#pragma unroll
    for (int mt = 0; mt < 2; mt++) {
        const int r0 = m0 + m_off + mt * 16 + (lid >> 2);
        float* c0 = C + ((size_t)z * N_ + r0) * D_;
        float* c1 = C + ((size_t)z * N_ + r0 + 8) * D_;
#pragma unroll
        for (int nt = 0; nt < 8; nt++) {
            const int cc = n_off + nt * 8 + (lid & 3) * 2;
            *(float2*)(c0 + cc) = make_float2(acc[mt][nt][0], acc[mt][nt][1]);
            *(float2*)(c1 + cc) = make_float2(acc[mt][nt][2], acc[mt][nt][3]);
        }
    }
}

// ---------------- SIMT 8x8 microtile GEMM ----------------
__device__ __forceinline__ void mma_tile(const float* __restrict__ As,
                                         const float* __restrict__ Bs,
                                         int ty, int tx, float (&acc)[8][8])
{
#pragma unroll
    for (int kk = 0; kk < 16; kk++) {
        const float* ar = As + kk * 128;
        const float* br = Bs + kk * 128;
        float4 a0 = *(const float4*)(ar + ty * 4);
        float4 a1 = *(const float4*)(ar + 64 + ty * 4);
        float4 b0 = *(const float4*)(br + tx * 4);
        float4 b1 = *(const float4*)(br + 64 + tx * 4);
        float a[8] = {a0.x, a0.y, a0.z, a0.w, a1.x, a1.y, a1.z, a1.w};
        float b[8] = {b0.x, b0.y, b0.z, b0.w, b1.x, b1.y, b1.z, b1.w};
#pragma unroll
        for (int i = 0; i < 8; i++)
#pragma unroll
            for (int j = 0; j < 8; j++)
                acc[i][j] = fmaf(a[i], b[j], acc[i][j]);
    }
}

template <int ACT, bool ACC, bool BIAS>
__global__ void __launch_bounds__(256) gemm_rows_kernel(
    const float* __restrict__ X, const float* __restrict__ W,
    const float* __restrict__ bias, float* __restrict__ C,
    int Kdim, int ldw, int ldc)
{
    __shared__ float As[2][16 * 128];
    __shared__ float Bs[2][16 * 128];
    const int r0 = blockIdx.y * 128;
    const int j0 = blockIdx.x * 128;
    const int tid = threadIdx.x;
    const int tx = tid & 15, ty = tid >> 4;

    float acc[8][8] = {};
    const int NT = Kdim >> 4;

    auto loadG = [&](int k0, float4 (&ra)[2], float4 (&rb)[2]) {
#pragma unroll
        for (int i = 0; i < 2; i++) {
            int f = tid + i * 256;
            int r = f >> 2, kq = f & 3;
            ra[i] = *(const float4*)(X + (size_t)(r0 + r) * Kdim + k0 + kq * 4);
            int k = f >> 5, q = f & 31;
            rb[i] = *(const float4*)(W + (size_t)(k0 + k) * ldw + j0 + q * 4);
        }
    };
    auto storeS = [&](int p, const float4 (&ra)[2], const float4 (&rb)[2]) {
#pragma unroll
        for (int i = 0; i < 2; i++) {
            int f = tid + i * 256;
            int r = f >> 2, kq = f & 3;
            const float v[4] = {ra[i].x, ra[i].y, ra[i].z, ra[i].w};
#pragma unroll
            for (int u = 0; u < 4; u++) As[p][(kq * 4 + u) * 128 + r] = v[u];
            int k = f >> 5, q = f & 31;
            *(float4*)&Bs[p][k * 128 + q * 4] = rb[i];
        }
    };

    float4 ra[2], rb[2];
    loadG(0, ra, rb);
    storeS(0, ra, rb);
    __syncthreads();
    int p = 0;
    for (int kt = 0; kt < NT; kt++) {
        bool more = (kt + 1 < NT);
        if (more) loadG((kt + 1) * 16, ra, rb);
        mma_tile(As[p], Bs[p], ty, tx, acc);
        if (more) {
            storeS(p ^ 1, ra, rb);
            __syncthreads();
            p ^= 1;
        }
    }
#pragma unroll
    for (int ih = 0; ih < 2; ih++)
#pragma unroll
        for (int i = 0; i < 4; i++) {
            int r = r0 + ih * 64 + ty * 4 + i;
            float* crow = C + (size_t)r * ldc + j0;
#pragma unroll
            for (int jh = 0; jh < 2; jh++) {
                int jj = jh * 64 + tx * 4;
                float4 v = make_float4(acc[ih * 4 + i][jh * 4 + 0], acc[ih * 4 + i][jh * 4 + 1],
                                       acc[ih * 4 + i][jh * 4 + 2], acc[ih * 4 + i][jh * 4 + 3]);
                if (BIAS) {
                    float4 bv = *(const float4*)(bias + j0 + jj);
                    v.x += bv.x; v.y += bv.y; v.z += bv.z; v.w += bv.w;
                }
                if (ACC) {
                    float4 o = *(const float4*)(crow + jj);
                    v.x += o.x; v.y += o.y; v.z += o.z; v.w += o.w;
                }
                if (ACT == 1) {
                    v.x = softplusf_(v.x); v.y = softplusf_(v.y);
                    v.z = softplusf_(v.z); v.w = softplusf_(v.w);
                } else if (ACT == 2) {
                    v.x = tanhf(v.x); v.y = tanhf(v.y);
                    v.z = tanhf(v.z); v.w = tanhf(v.w);
                }
                *(float4*)(crow + jj) = v;
            }
        }
}

// ---------------- transpose h(b,t,n,d) -> x(b*n, t, d) ----------------
__global__ void transpose_bt_kernel(const float* __restrict__ h, float* __restrict__ x)
{
    size_t gid = (size_t)blockIdx.x * blockDim.x + threadIdx.x;
    if (gid >= (size_t)ROWS_ * 32) return;
    int q = (int)(gid & 31);
    int r = (int)(gid >> 5);
    int t = r % T_;
    int bn = r / T_;
    int n = bn % N_;
    int b = bn / N_;
    size_t src = ((size_t)((b * T_ + t) * N_) + n) * D_ + q * 4;
    *(float4*)(x + (size_t)r * D_ + q * 4) = *(const float4*)(h + src);
}

// ---------------- causal depthwise conv (K=4) + SiLU ----------------
__global__ void conv_silu_kernel(const float* __restrict__ pr, const float* __restrict__ cw,
                                 const float* __restrict__ cb, float* __restrict__ sig)
{
    int idx = blockIdx.x * blockDim.x + threadIdx.x;
    int c = idx & (INNER_ - 1);
    int bn = idx >> 8;
    float w0 = cw[c * 4 + 0], w1 = cw[c * 4 + 1], w2 = cw[c * 4 + 2], w3 = cw[c * 4 + 3];
    float b = cb[c];
    float s[T_];
    size_t base = (size_t)bn * T_ * 512 + c;
#pragma unroll
    for (int t = 0; t < T_; t++) s[t] = pr[base + (size_t)t * 512];
    size_t ob = (size_t)bn * T_ * INNER_ + c;
#pragma unroll
    for (int t = 0; t < T_; t++) {
        float a = b + w3 * s[t];
        if (t >= 1) a += w2 * s[t - 1];
        if (t >= 2) a += w1 * s[t - 2];
        if (t >= 3) a += w0 * s[t - 3];
        sig[ob + (size_t)t * INNER_] = a * sigmoidf_(a);
    }
}

// ---------------- selective-scan over T + sigmoid gating ----------------
// si lives in pr cols 0..255; gate in pr cols 256..511; y written over dl (dly).
__global__ void scan_kernel(const float* __restrict__ sig, float* dly,
                            const float* __restrict__ so, const float* __restrict__ pr,
                            const float* __restrict__ a_log, const float* __restrict__ d_skip)
{
    int idx = blockIdx.x * blockDim.x + threadIdx.x;
    int c = idx & (INNER_ - 1);
    int bn = idx >> 8;
    float a = -softplusf_(a_log[c]);
    float dsk = d_skip[c];
    float state = 0.f;
    size_t b256 = (size_t)bn * T_ * INNER_ + c;
    size_t b512 = (size_t)bn * T_ * 512 + c;
#pragma unroll
    for (int t = 0; t < T_; t++) {
        float x  = sig[b256 + (size_t)t * INNER_];
        float d  = dly[b256 + (size_t)t * INNER_];
        float iv = pr [b512 + (size_t)t * 512];            // si (cols 0..255)
        float ov = so [b256 + (size_t)t * INNER_];
        float g  = pr [b512 + (size_t)t * 512 + INNER_];   // gate (cols 256..511)
        state = expf(d * a) * state + iv * x;
        float yy = ov * state + dsk * x;
        dly[b256 + (size_t)t * INNER_] = yy * sigmoidf_(g);
    }
}

// ---------------- fusion (h + sp + tp + sp*tp) + LayerNorm ----------------
__global__ void fuse_ln_kernel(const float* __restrict__ h_in, const float* __restrict__ sp_pre,
                               const float* __restrict__ gcn_b, const float* __restrict__ tp,
                               const float* __restrict__ ln_g, const float* __restrict__ ln_b,
                               float* __restrict__ h_out)
{
    int token = blockIdx.x;
    int d = threadIdx.x;
    int n  = token % N_;
    int bt = token / N_;
    int t  = bt % T_;
    int b  = bt / T_;
    size_t row    = (size_t)token * D_;
    size_t row_tp = ((size_t)(b * N_ + n) * T_ + t) * D_;

    float hv = h_in[row + d];
    float s = sp_pre[row + d] + gcn_b[d];
    s = geluf_(s);
    float tv = tp[row_tp + d];
    float f = hv + s + tv + s * tv;

    __shared__ float red[8];
    float v = f;
#pragma unroll
    for (int o = 16; o > 0; o >>= 1) v += __shfl_xor_sync(0xffffffffu, v, o);
    if ((d & 31) == 0) red[d >> 5] = v;
    __syncthreads();
    float mu = (red[0] + red[1] + red[2] + red[3]) * (1.f / 128.f);
    float dv = f - mu;
    v = dv * dv;
#pragma unroll
    for (int o = 16; o > 0; o >>= 1) v += __shfl_xor_sync(0xffffffffu, v, o);
    if ((d & 31) == 0) red[4 + (d >> 5)] = v;
    __syncthreads();
    float var = (red[4] + red[5] + red[6] + red[7]) * (1.f / 128.f);
    h_out[row + d] = dv * rsqrtf(var + 1e-5f) * ln_g[d] + ln_b[d];
}

// ---------------- host launcher ----------------
extern "C" void kernel_launch(void* const* d_in, const int* in_sizes, int n_in,
                              void* d_out, int out_size)
{
    (void)in_sizes; (void)n_in; (void)out_size;
    const float* inputs   = (const float*)d_in[0];
    const float* supports = (const float*)d_in[1];
    const float* gcn_w    = (const float*)d_in[2];
    const float* gcn_b    = (const float*)d_in[3];
    const float* in_w     = (const float*)d_in[4];
    const float* in_b     = (const float*)d_in[5];
    const float* conv_w   = (const float*)d_in[6];
    const float* conv_b   = (const float*)d_in[7];
    const float* delta_w  = (const float*)d_in[8];
    const float* delta_b  = (const float*)d_in[9];
    const float* si_w     = (const float*)d_in[10];
    const float* si_b     = (const float*)d_in[11];
    const float* so_w     = (const float*)d_in[12];
    const float* so_b     = (const float*)d_in[13];
    const float* a_log    = (const float*)d_in[14];
    const float* d_skip   = (const float*)d_in[15];
    const float* out_w    = (const float*)d_in[16];
    const float* out_b    = (const float*)d_in[17];
    const float* ln_g     = (const float*)d_in[18];
    const float* ln_b     = (const float*)d_in[19];

    float *hidA, *hidB, *sp, *h2, *x, *pr, *sig, *dl, *so;
    __nv_bfloat16 *Sthi, *Stlo, *Hthi, *Htlo;
    cudaGetSymbolAddress((void**)&hidA, g_hidA);
    cudaGetSymbolAddress((void**)&hidB, g_hidB);
    cudaGetSymbolAddress((void**)&sp,   g_sp);
    cudaGetSymbolAddress((void**)&h2,   g_h2);
    cudaGetSymbolAddress((void**)&x,    g_x);
    cudaGetSymbolAddress((void**)&pr,   g_pr);
    cudaGetSymbolAddress((void**)&sig,  g_sig);
    cudaGetSymbolAddress((void**)&dl,   g_dl);
    cudaGetSymbolAddress((void**)&so,   g_so);
    cudaGetSymbolAddress((void**)&Sthi, g_Sthi);
    cudaGetSymbolAddress((void**)&Stlo, g_Stlo);
    cudaGetSymbolAddress((void**)&Hthi, g_Hthi);
    cudaGetSymbolAddress((void**)&Htlo, g_Htlo);
    float* tp = x;   // alias: x dead after in-projection

    cudaFuncSetAttribute(gemm_support_mma, cudaFuncAttributeMaxDynamicSharedMemorySize, SMEM_MMA);

    const dim3 blk(256);
    const dim3 gmma(16, BT_);              // HMMA einsum
    const dim3 gcvH(64, 4, BT_);           // H conversion
    const dim3 g128(1, ROWS_ / 128);
    const dim3 g256(2, ROWS_ / 128);
    const dim3 g512(4, ROWS_ / 128);
    const int ew_blocks = (BN_ * INNER_) / 256;

    // support conversion: St[i][m][k] = S[i][k][m], bf16 split
    convt_S<<<dim3(64, 64, 2), blk>>>(supports, Sthi, Stlo);

    for (int l = 0; l < 2; l++) {
        const float* h_in  = (l == 0) ? inputs : h2;
        float*       h_out = (l == 0) ? h2 : (float*)d_out;
        const float* gw  = gcn_w  + (size_t)l * 640 * 128;
        const float* gb  = gcn_b  + l * 128;
        const float* iw  = in_w   + (size_t)l * 128 * 512;
        const float* ib  = in_b   + l * 512;
        const float* cw  = conv_w + (size_t)l * INNER_ * KC_;
        const float* cb  = conv_b + l * INNER_;
        const float* dw  = delta_w + (size_t)l * INNER_ * INNER_;
        const float* db  = delta_b + l * INNER_;
        const float* siw = si_w + (size_t)l * INNER_ * INNER_;
        const float* sib = si_b + l * INNER_;
        const float* sow = so_w + (size_t)l * INNER_ * INNER_;
        const float* sob = so_b + l * INNER_;
        const float* al  = a_log  + l * INNER_;
        const float* dsk = d_skip + l * INNER_;
        const float* ow  = out_w + (size_t)l * INNER_ * 128;
        const float* ob  = out_b + l * 128;
        const float* lg  = ln_g + l * 128;
        const float* lb  = ln_b + l * 128;

        // --- spatial (GCN) branch on HMMA (2-buffer schedule) ---
        gemm_rows_kernel<0, false, false><<<g128, blk>>>(h_in, gw, nullptr, sp, 128, 128, 128);
        convt_H<<<gcvH, blk>>>(h_in, Hthi, Htlo);
        gemm_support_mma<<<gmma, blk, SMEM_MMA>>>(Sthi, Stlo, Hthi, Htlo, hidA);             // S0 h
        gemm_rows_kernel<0, true, false><<<g128, blk>>>(hidA, gw + 1 * 128 * 128, nullptr, sp, 128, 128, 128);
        convt_H<<<gcvH, blk>>>(hidA, Hthi, Htlo);
        gemm_support_mma<<<gmma, blk, SMEM_MMA>>>(Sthi, Stlo, Hthi, Htlo, hidB);             // S0^2 h
        gemm_rows_kernel<0, true, false><<<g128, blk>>>(hidB, gw + 2 * 128 * 128, nullptr, sp, 128, 128, 128);
        convt_H<<<gcvH, blk>>>(h_in, Hthi, Htlo);                                            // recompute
        gemm_support_mma<<<gmma, blk, SMEM_MMA>>>(Sthi + NN_, Stlo + NN_, Hthi, Htlo, hidA); // S1 h
        gemm_rows_kernel<0, true, false><<<g128, blk>>>(hidA, gw + 3 * 128 * 128, nullptr, sp, 128, 128, 128);
        convt_H<<<gcvH, blk>>>(hidA, Hthi, Htlo);
        gemm_support_mma<<<gmma, blk, SMEM_MMA>>>(Sthi + NN_, Stlo + NN_, Hthi, Htlo, hidB); // S1^2 h
        gemm_rows_kernel<0, true, false><<<g128, blk>>>(hidB, gw + 4 * 128 * 128, nullptr, sp, 128, 128, 128);

        // --- temporal branch ---
        transpose_bt_kernel<<<(ROWS_ * 32) / 256, 256>>>(h_in, x);
        gemm_rows_kernel<0, false, true><<<g512, blk>>>(x, iw, ib, pr, 128, 512, 512);
        conv_silu_kernel<<<ew_blocks, 256>>>(pr, cw, cb, sig);
        gemm_rows_kernel<1, false, true><<<g256, blk>>>(sig, dw,  db,  dl, 256, 256, 256);
        gemm_rows_kernel<2, false, true><<<g256, blk>>>(sig, sow, sob, so, 256, 256, 256);
        gemm_rows_kernel<2, false, true><<<g256, blk>>>(sig, siw, sib, pr, 256, 256, 512); // si -> pr cols 0..255
        scan_kernel<<<ew_blocks, 256>>>(sig, dl, so, pr, al, dsk);                          // y -> dl
        gemm_rows_kernel<0, false, true><<<g128, blk>>>(dl, ow, ob, tp, 256, 128, 128);

        // --- fusion + layernorm ---
        fuse_ln_kernel<<<ROWS_, 128>>>(h_in, sp, gb, tp, lg, lb, h_out);
    }
}

// round 5
// speedup vs baseline: 2.0126x; 1.4729x over previous
#include <cuda_runtime.h>
#include <cuda_bf16.h>
#include <math.h>
#include <stdint.h>

// ---------------- problem constants ----------------
#define B_    16
#define T_    12
#define N_    2048
#define D_    128
#define INNER_ 256
#define KC_   4
#define BT_   (B_*T_)          // 192
#define ROWS_ (B_*T_*N_)       // 393216 tokens
#define BN_   (B_*N_)          // 32768
#define NN_   ((size_t)N_*N_)

// ---------------- scratch (device globals; ~3.66 GB total) ----------------
#define SZ_H  ((size_t)ROWS_*D_)
#define SZ_PR ((size_t)ROWS_*512)
#define SZ_I  ((size_t)ROWS_*INNER_)

__device__ __align__(16) float g_hidA[SZ_H];
__device__ __align__(16) float g_hidB[SZ_H];
__device__ __align__(16) float g_sp  [SZ_H];
__device__ __align__(16) float g_h2  [SZ_H];
__device__ __align__(16) float g_tp  [SZ_H];
__device__ __align__(16) float g_pr  [SZ_PR];   // cols 0..255: signal then si; 256..511: gate
__device__ __align__(16) float g_sig [SZ_I];
__device__ __align__(16) float g_dl  [SZ_I];
__device__ __align__(16) float g_so  [SZ_I];

// bf16 split buffers
__device__ __align__(16) __nv_bfloat16 g_Sthi[2*NN_];                 // S^T hi [i][m][k]
__device__ __align__(16) __nv_bfloat16 g_Stlo[2*NN_];
__device__ __align__(16) __nv_bfloat16 g_Hthi[(size_t)BT_*D_*N_];     // H^T hi [z][d][k]
__device__ __align__(16) __nv_bfloat16 g_Htlo[(size_t)BT_*D_*N_];
__device__ __align__(16) __nv_bfloat16 g_Xhi[SZ_I];                   // shared act buffer [M][K<=256]
__device__ __align__(16) __nv_bfloat16 g_Xlo[SZ_I];

// transposed weights, bf16 split: per layer 376832 elements
#define WOFF_GCN(i) ((i)*16384)
#define WOFF_IN     81920
#define WOFF_DL     147456
#define WOFF_SI     212992
#define WOFF_SO     278528
#define WOFF_OUT    344064
#define WSZ_L       376832
__device__ __align__(16) __nv_bfloat16 g_Wthi[2*WSZ_L];
__device__ __align__(16) __nv_bfloat16 g_Wtlo[2*WSZ_L];

// ---------------- helpers ----------------
__device__ __forceinline__ float sigmoidf_(float x) { return 1.f / (1.f + expf(-x)); }
__device__ __forceinline__ float softplusf_(float x) {
    return fmaxf(x, 0.f) + log1pf(expf(-fabsf(x)));
}
__device__ __forceinline__ float geluf_(float x) {
    return 0.5f * x * (1.f + erff(x * 0.7071067811865475f));
}
__device__ __forceinline__ uint32_t smem_u32_(const void* p) {
    uint32_t a;
    asm("{ .reg .u64 t; cvta.to.shared.u64 t, %1; cvt.u32.u64 %0, t; }" : "=r"(a) : "l"(p));
    return a;
}
__device__ __forceinline__ void ldsm4_(uint32_t* r, uint32_t a) {
    asm volatile("ldmatrix.sync.aligned.m8n8.x4.shared.b16 {%0,%1,%2,%3}, [%4];"
        : "=r"(r[0]), "=r"(r[1]), "=r"(r[2]), "=r"(r[3]) : "r"(a));
}
__device__ __forceinline__ void mma16816_(float* d, const uint32_t* a, uint32_t b0, uint32_t b1) {
    asm volatile(
        "mma.sync.aligned.m16n8k16.row.col.f32.bf16.bf16.f32 "
        "{%0,%1,%2,%3}, {%4,%5,%6,%7}, {%8,%9}, {%0,%1,%2,%3};"
        : "+f"(d[0]), "+f"(d[1]), "+f"(d[2]), "+f"(d[3])
        : "r"(a[0]), "r"(a[1]), "r"(a[2]), "r"(a[3]), "r"(b0), "r"(b1));
}
__device__ __forceinline__ void split1_(float v, __nv_bfloat16* hi, __nv_bfloat16* lo) {
    __nv_bfloat16 h = __float2bfloat16(v);
    *hi = h;
    *lo = __float2bfloat16(v - __bfloat162float(h));
}
__device__ __forceinline__ void split2_(float v0, float v1,
                                        __nv_bfloat16* hi, __nv_bfloat16* lo) {
    __nv_bfloat16 h0 = __float2bfloat16(v0), h1 = __float2bfloat16(v1);
    __nv_bfloat162 hh; hh.x = h0; hh.y = h1;
    __nv_bfloat162 ll;
    ll.x = __float2bfloat16(v0 - __bfloat162float(h0));
    ll.y = __float2bfloat16(v1 - __bfloat162float(h1));
    *(__nv_bfloat162*)hi = hh;
    *(__nv_bfloat162*)lo = ll;
}

// ---------------- conversions ----------------
// St[i][m][k] = S[i][k][m], bf16 split
__global__ void convt_S(const float* __restrict__ S,
                        __nv_bfloat16* __restrict__ hi, __nv_bfloat16* __restrict__ lo)
{
    __shared__ float t[32][33];
    const int k0 = blockIdx.x * 32, m0 = blockIdx.y * 32, i = blockIdx.z;
    const int tx = threadIdx.x & 31, ty = threadIdx.x >> 5;
    const float* Si = S + (size_t)i * NN_;
    for (int r = ty; r < 32; r += 8)
        t[r][tx] = Si[(size_t)(k0 + r) * N_ + m0 + tx];
    __syncthreads();
    for (int r = ty; r < 32; r += 8) {
        float v = t[tx][r];
        size_t o = (size_t)i * NN_ + (size_t)(m0 + r) * N_ + k0 + tx;
        split1_(v, hi + o, lo + o);
    }
}
// Ht[z][d][n] = H[z][n][d], bf16 split
__global__ void convt_H(const float* __restrict__ H,
                        __nv_bfloat16* __restrict__ hi, __nv_bfloat16* __restrict__ lo)
{
    __shared__ float t[32][33];
    const int n0 = blockIdx.x * 32, d0 = blockIdx.y * 32, z = blockIdx.z;
    const int tx = threadIdx.x & 31, ty = threadIdx.x >> 5;
    const float* Hz = H + (size_t)z * N_ * D_;
    for (int r = ty; r < 32; r += 8)
        t[r][tx] = Hz[(size_t)(n0 + r) * D_ + d0 + tx];
    __syncthreads();
    for (int r = ty; r < 32; r += 8) {
        float v = t[tx][r];
        size_t o = ((size_t)z * D_ + d0 + r) * N_ + n0 + tx;
        split1_(v, hi + o, lo + o);
    }
}
// Wt[n][k] = W[k][n], bf16 split
__global__ void convt_W(const float* __restrict__ W, int K, int N,
                        __nv_bfloat16* __restrict__ hi, __nv_bfloat16* __restrict__ lo)
{
    __shared__ float t[32][33];
    const int k0 = blockIdx.x * 32, n0 = blockIdx.y * 32;
    const int tx = threadIdx.x & 31, ty = threadIdx.x >> 5;
    for (int r = ty; r < 32; r += 8)
        t[r][tx] = W[(size_t)(k0 + r) * N + n0 + tx];
    __syncthreads();
    for (int r = ty; r < 32; r += 8) {
        float v = t[tx][r];
        size_t o = (size_t)(n0 + r) * K + k0 + tx;
        split1_(v, hi + o, lo + o);
    }
}
// plain elementwise f32 -> bf16 split (for layer-0 h input; [M][128])
__global__ void conv_plain(const float* __restrict__ src,
                           __nv_bfloat16* __restrict__ hi, __nv_bfloat16* __restrict__ lo)
{
    size_t gid = ((size_t)blockIdx.x * blockDim.x + threadIdx.x) * 2;
    float2 v = *(const float2*)(src + gid);
    split2_(v.x, v.y, hi + gid, lo + gid);
}
// transpose h(b,t,n,d) -> X(bn*T+t, d) bf16 split
__global__ void transpose_convert_bt(const float* __restrict__ h,
                                     __nv_bfloat16* __restrict__ hi, __nv_bfloat16* __restrict__ lo)
{
    size_t gid = (size_t)blockIdx.x * blockDim.x + threadIdx.x;
    int q = (int)(gid & 31);
    int r = (int)(gid >> 5);          // bn*T + t
    int t = r % T_;
    int bn = r / T_;
    int n = bn % N_;
    int b = bn / N_;
    size_t src = ((size_t)((b * T_ + t) * N_) + n) * D_ + q * 4;
    float4 v = *(const float4*)(h + src);
    size_t o = (size_t)r * D_ + q * 4;
    split2_(v.x, v.y, hi + o, lo + o);
    split2_(v.z, v.w, hi + o + 2, lo + o + 2);
}

// ---------------- HMMA support einsum ----------------
// C[z][m][d] = sum_k St[m][k] * Ht[z][d][k]; writes f32 C and bf16-split Chi/Clo.
#define STRD_ 80
#define TILEB_ (128 * STRD_)
#define STAGEB_ (4 * TILEB_)          // 40960
#define SMEM_MMA (2 * STAGEB_)        // 81920

__global__ void __launch_bounds__(256, 2)
gemm_support_mma(const __nv_bfloat16* __restrict__ Ah, const __nv_bfloat16* __restrict__ Al,
                 const __nv_bfloat16* __restrict__ Bh, const __nv_bfloat16* __restrict__ Bl,
                 float* __restrict__ C,
                 __nv_bfloat16* __restrict__ Chi, __nv_bfloat16* __restrict__ Clo)
{
    extern __shared__ char smem[];
    const uint32_t sbase = smem_u32_(smem);
    const int m0  = blockIdx.x * 128;
    const int z   = blockIdx.y;
    const int tid = threadIdx.x;
    const int wid = tid >> 5, lid = tid & 31;
    const int wm = wid & 3, wn = wid >> 2;
    const int m_off = wm * 32, n_off = wn * 64;

    const __nv_bfloat16* gp[4] = {
        Ah + (size_t)m0 * N_, Al + (size_t)m0 * N_,
        Bh + (size_t)z * D_ * N_, Bl + (size_t)z * D_ * N_ };

    auto load_stage = [&](int buf, int k0) {
        uint32_t base = sbase + buf * STAGEB_;
#pragma unroll
        for (int i = 0; i < 8; i++) {
            int idx = i * 256 + tid;
            int tile = idx >> 9;
            int rem = idx & 511;
            int r = rem >> 2, c = rem & 3;
            uint32_t dst = base + tile * TILEB_ + r * STRD_ + c * 16;
            const void* src = gp[tile] + (size_t)r * N_ + k0 + c * 8;
            asm volatile("cp.async.cg.shared.global [%0], [%1], 16;" :: "r"(dst), "l"(src));
        }
        asm volatile("cp.async.commit_group;" ::: "memory");
    };

    float acc[2][8][4];
#pragma unroll
    for (int mt = 0; mt < 2; mt++)
#pragma unroll
        for (int nt = 0; nt < 8; nt++)
#pragma unroll
            for (int q = 0; q < 4; q++) acc[mt][nt][q] = 0.f;

    const int a_row = m_off + (lid & 15);
    const int a_kc  = (lid >> 4) << 3;
    const int b_row = n_off + ((lid >> 4) << 3) + (lid & 7);
    const int b_kc  = ((lid >> 3) & 1) << 3;

    const int NT = N_ / 32;
    load_stage(0, 0);
    for (int kt = 0; kt < NT; kt++) {
        if (kt + 1 < NT) {
            load_stage((kt + 1) & 1, (kt + 1) * 32);
            asm volatile("cp.async.wait_group 1;" ::: "memory");
        } else {
            asm volatile("cp.async.wait_group 0;" ::: "memory");
        }
        __syncthreads();

        const uint32_t stg = sbase + (kt & 1) * STAGEB_;
        const uint32_t bAH = stg, bAL = stg + TILEB_, bBH = stg + 2 * TILEB_, bBL = stg + 3 * TILEB_;
#pragma unroll
        for (int k16 = 0; k16 < 2; k16++) {
            const int kb = k16 * 16;
            uint32_t ah[2][4], al[2][4];
#pragma unroll
            for (int mt = 0; mt < 2; mt++) {
                uint32_t ao = (uint32_t)((a_row + mt * 16) * STRD_ + (kb + a_kc) * 2);
                ldsm4_(ah[mt], bAH + ao);
                ldsm4_(al[mt], bAL + ao);
            }
#pragma unroll
            for (int pt = 0; pt < 4; pt++) {
                uint32_t bo = (uint32_t)((b_row + pt * 16) * STRD_ + (kb + b_kc) * 2);
                uint32_t bh[4], bl[4];
                ldsm4_(bh, bBH + bo);
                ldsm4_(bl, bBL + bo);
#pragma unroll
                for (int mt = 0; mt < 2; mt++) {
#pragma unroll
                    for (int sub = 0; sub < 2; sub++) {
                        const int nt = pt * 2 + sub;
                        mma16816_(acc[mt][nt], ah[mt], bh[2 * sub], bh[2 * sub + 1]);
                        mma16816_(acc[mt][nt], ah[mt], bl[2 * sub], bl[2 * sub + 1]);
                        mma16816_(acc[mt][nt], al[mt], bh[2 * sub], bh[2 * sub + 1]);
                    }
                }
            }
        }
        __syncthreads();
    }

#pragma unroll
    for (int mt = 0; mt < 2; mt++) {
        const size_t r0 = (size_t)z * N_ + m0 + m_off + mt * 16 + (lid >> 2);
        float* c0 = C + r0 * D_;
        float* c1 = C + (r0 + 8) * D_;
        __nv_bfloat16* xh0 = Chi + r0 * D_;
        __nv_bfloat16* xl0 = Clo + r0 * D_;
        __nv_bfloat16* xh1 = Chi + (r0 + 8) * D_;
        __nv_bfloat16* xl1 = Clo + (r0 + 8) * D_;
#pragma unroll
        for (int nt = 0; nt < 8; nt++) {
            const int cc = n_off + nt * 8 + (lid & 3) * 2;
            *(float2*)(c0 + cc) = make_float2(acc[mt][nt][0], acc[mt][nt][1]);
            *(float2*)(c1 + cc) = make_float2(acc[mt][nt][2], acc[mt][nt][3]);
            split2_(acc[mt][nt][0], acc[mt][nt][1], xh0 + cc, xl0 + cc);
            split2_(acc[mt][nt][2], acc[mt][nt][3], xh1 + cc, xl1 + cc);
        }
    }
}

// ---------------- HMMA rows GEMM: C[r][j] = act( X[r]·Wt[j] + bias[j] ) ----------
// X [M][K] bf16 split row-major, Wt [N][K] bf16 split. ACT: 0 none,1 softplus,2 tanh.
template <int ACT, bool ACC, bool BIAS>
__global__ void __launch_bounds__(256, 2)
gemm_rows_hmma(const __nv_bfloat16* __restrict__ Xhi, const __nv_bfloat16* __restrict__ Xlo,
               const __nv_bfloat16* __restrict__ Whi, const __nv_bfloat16* __restrict__ Wlo,
               const float* __restrict__ bias, float* __restrict__ C,
               int K, int ldc)
{
    extern __shared__ char smem[];
    const uint32_t sbase = smem_u32_(smem);
    const int j0  = blockIdx.x * 128;
    const int r0  = blockIdx.y * 128;
    const int tid = threadIdx.x;
    const int wid = tid >> 5, lid = tid & 31;
    const int wm = wid & 3, wn = wid >> 2;
    const int m_off = wm * 32, n_off = wn * 64;

    const __nv_bfloat16* gp[4] = {
        Xhi + (size_t)r0 * K, Xlo + (size_t)r0 * K,
        Whi + (size_t)j0 * K, Wlo + (size_t)j0 * K };

    auto load_stage = [&](int buf, int k0) {
        uint32_t base = sbase + buf * STAGEB_;
#pragma unroll
        for (int i = 0; i < 8; i++) {
            int idx = i * 256 + tid;
            int tile = idx >> 9;
            int rem = idx & 511;
            int r = rem >> 2, c = rem & 3;
            uint32_t dst = base + tile * TILEB_ + r * STRD_ + c * 16;
            const void* src = gp[tile] + (size_t)r * K + k0 + c * 8;
            asm volatile("cp.async.cg.shared.global [%0], [%1], 16;" :: "r"(dst), "l"(src));
        }
        asm volatile("cp.async.commit_group;" ::: "memory");
    };

    float acc[2][8][4];
#pragma unroll
    for (int mt = 0; mt < 2; mt++)
#pragma unroll
        for (int nt = 0; nt < 8; nt++)
#pragma unroll
            for (int q = 0; q < 4; q++) acc[mt][nt][q] = 0.f;

    const int a_row = m_off + (lid & 15);
    const int a_kc  = (lid >> 4) << 3;
    const int b_row = n_off + ((lid >> 4) << 3) + (lid & 7);
    const int b_kc  = ((lid >> 3) & 1) << 3;

    const int NT = K >> 5;
    load_stage(0, 0);
    for (int kt = 0; kt < NT; kt++) {
        if (kt + 1 < NT) {
            load_stage((kt + 1) & 1, (kt + 1) * 32);
            asm volatile("cp.async.wait_group 1;" ::: "memory");
        } else {
            asm volatile("cp.async.wait_group 0;" ::: "memory");
        }
        __syncthreads();

        const uint32_t stg = sbase + (kt & 1) * STAGEB_;
        const uint32_t bAH = stg, bAL = stg + TILEB_, bBH = stg + 2 * TILEB_, bBL = stg + 3 * TILEB_;
#pragma unroll
        for (int k16 = 0; k16 < 2; k16++) {
            const int kb = k16 * 16;
            uint32_t ah[2][4], al[2][4];
#pragma unroll
            for (int mt = 0; mt < 2; mt++) {
                uint32_t ao = (uint32_t)((a_row + mt * 16) * STRD_ + (kb + a_kc) * 2);
                ldsm4_(ah[mt], bAH + ao);
                ldsm4_(al[mt], bAL + ao);
            }
#pragma unroll
            for (int pt = 0; pt < 4; pt++) {
                uint32_t bo = (uint32_t)((b_row + pt * 16) * STRD_ + (kb + b_kc) * 2);
                uint32_t bh[4], bl[4];
                ldsm4_(bh, bBH + bo);
                ldsm4_(bl, bBL + bo);
#pragma unroll
                for (int mt = 0; mt < 2; mt++) {
#pragma unroll
                    for (int sub = 0; sub < 2; sub++) {
                        const int nt = pt * 2 + sub;
                        mma16816_(acc[mt][nt], ah[mt], bh[2 * sub], bh[2 * sub + 1]);
                        mma16816_(acc[mt][nt], ah[mt], bl[2 * sub], bl[2 * sub + 1]);
                        mma16816_(acc[mt][nt], al[mt], bh[2 * sub], bh[2 * sub + 1]);
                    }
                }
            }
        }
        __syncthreads();
    }

    auto ep = [&](float v, float b) -> float {
        if (BIAS) v += b;
        if (ACT == 1) v = softplusf_(v);
        else if (ACT == 2) v = tanhf(v);
        return v;
    };
#pragma unroll
    for (int mt = 0; mt < 2; mt++) {
        const int r = r0 + m_off + mt * 16 + (lid >> 2);
        float* c0 = C + (size_t)r * ldc + j0;
        float* c1 = C + (size_t)(r + 8) * ldc + j0;
#pragma unroll
        for (int nt = 0; nt < 8; nt++) {
            const int cc = n_off + nt * 8 + (lid & 3) * 2;
            float b0 = 0.f, b1 = 0.f;
            if (BIAS) { b0 = bias[j0 + cc]; b1 = bias[j0 + cc + 1]; }
            float v0 = ep(acc[mt][nt][0], b0), v1 = ep(acc[mt][nt][1], b1);
            float v2 = ep(acc[mt][nt][2], b0), v3 = ep(acc[mt][nt][3], b1);
            if (ACC) {
                float2 o0 = *(float2*)(c0 + cc);
                float2 o1 = *(float2*)(c1 + cc);
                v0 += o0.x; v1 += o0.y; v2 += o1.x; v3 += o1.y;
            }
            *(float2*)(c0 + cc) = make_float2(v0, v1);
            *(float2*)(c1 + cc) = make_float2(v2, v3);
        }
    }
}

// ---------------- causal depthwise conv (K=4) + SiLU, emits f32 + bf16 split ------
__global__ void conv_silu_kernel(const float* __restrict__ pr, const float* __restrict__ cw,
                                 const float* __restrict__ cb, float* __restrict__ sig,
                                 __nv_bfloat16* __restrict__ hi, __nv_bfloat16* __restrict__ lo)
{
    int idx = blockIdx.x * blockDim.x + threadIdx.x;
    int c = idx & (INNER_ - 1);
    int bn = idx >> 8;
    float w0 = cw[c * 4 + 0], w1 = cw[c * 4 + 1], w2 = cw[c * 4 + 2], w3 = cw[c * 4 + 3];
    float b = cb[c];
    float s[T_];
    size_t base = (size_t)bn * T_ * 512 + c;
#pragma unroll
    for (int t = 0; t < T_; t++) s[t] = pr[base + (size_t)t * 512];
    size_t ob = (size_t)bn * T_ * INNER_ + c;
#pragma unroll
    for (int t = 0; t < T_; t++) {
        float a = b + w3 * s[t];
        if (t >= 1) a += w2 * s[t - 1];
        if (t >= 2) a += w1 * s[t - 2];
        if (t >= 3) a += w0 * s[t - 3];
        float v = a * sigmoidf_(a);
        size_t o = ob + (size_t)t * INNER_;
        sig[o] = v;
        split1_(v, hi + o, lo + o);
    }
}

// ---------------- selective-scan + sigmoid gating, emits y as bf16 split ----------
__global__ void scan_kernel(const float* __restrict__ sig, const float* __restrict__ dl,
                            const float* __restrict__ so, const float* __restrict__ pr,
                            const float* __restrict__ a_log, const float* __restrict__ d_skip,
                            __nv_bfloat16* __restrict__ yhi, __nv_bfloat16* __restrict__ ylo)
{
    int idx = blockIdx.x * blockDim.x + threadIdx.x;
    int c = idx & (INNER_ - 1);
    int bn = idx >> 8;
    float a = -softplusf_(a_log[c]);
    float dsk = d_skip[c];
    float state = 0.f;
    size_t b256 = (size_t)bn * T_ * INNER_ + c;
    size_t b512 = (size_t)bn * T_ * 512 + c;
#pragma unroll
    for (int t = 0; t < T_; t++) {
        float x  = sig[b256 + (size_t)t * INNER_];
        float d  = dl [b256 + (size_t)t * INNER_];
        float iv = pr [b512 + (size_t)t * 512];            // si (cols 0..255)
        float ov = so [b256 + (size_t)t * INNER_];
        float g  = pr [b512 + (size_t)t * 512 + INNER_];   // gate (cols 256..511)
        state = expf(d * a) * state + iv * x;
        float yy = (ov * state + dsk * x) * sigmoidf_(g);
        split1_(yy, yhi + b256 + (size_t)t * INNER_, ylo + b256 + (size_t)t * INNER_);
    }
}

// ---------------- fusion + LayerNorm, emits f32 h_out + bf16 split ----------------
__global__ void fuse_ln_kernel(const float* __restrict__ h_in, const float* __restrict__ sp_pre,
                               const float* __restrict__ gcn_b, const float* __restrict__ tp,
                               const float* __restrict__ ln_g, const float* __restrict__ ln_b,
                               float* __restrict__ h_out,
                               __nv_bfloat16* __restrict__ ohi, __nv_bfloat16* __restrict__ olo)
{
    int token = blockIdx.x;
    int d = threadIdx.x;
    int n  = token % N_;
    int bt = token / N_;
    int t  = bt % T_;
    int b  = bt / T_;
    size_t row    = (size_t)token * D_;
    size_t row_tp = ((size_t)(b * N_ + n) * T_ + t) * D_;

    float hv = h_in[row + d];
    float s = sp_pre[row + d] + gcn_b[d];
    s = geluf_(s);
    float tv = tp[row_tp + d];
    float f = hv + s + tv + s * tv;

    __shared__ float red[8];
    float v = f;
#pragma unroll
    for (int o = 16; o > 0; o >>= 1) v += __shfl_xor_sync(0xffffffffu, v, o);
    if ((d & 31) == 0) red[d >> 5] = v;
    __syncthreads();
    float mu = (red[0] + red[1] + red[2] + red[3]) * (1.f / 128.f);
    float dv = f - mu;
    v = dv * dv;
#pragma unroll
    for (int o = 16; o > 0; o >>= 1) v += __shfl_xor_sync(0xffffffffu, v, o);
    if ((d & 31) == 0) red[4 + (d >> 5)] = v;
    __syncthreads();
    float var = (red[4] + red[5] + red[6] + red[7]) * (1.f / 128.f);
    float out = dv * rsqrtf(var + 1e-5f) * ln_g[d] + ln_b[d];
    h_out[row + d] = out;
    split1_(out, ohi + row + d, olo + row + d);
}

// ---------------- host launcher ----------------
extern "C" void kernel_launch(void* const* d_in, const int* in_sizes, int n_in,
                              void* d_out, int out_size)
{
    (void)in_sizes; (void)n_in; (void)out_size;
    const float* inputs   = (const float*)d_in[0];
    const float* supports = (const float*)d_in[1];
    const float* gcn_w    = (const float*)d_in[2];
    const float* gcn_b    = (const float*)d_in[3];
    const float* in_w     = (const float*)d_in[4];
    const float* in_b     = (const float*)d_in[5];
    const float* conv_w   = (const float*)d_in[6];
    const float* conv_b   = (const float*)d_in[7];
    const float* delta_w  = (const float*)d_in[8];
    const float* delta_b  = (const float*)d_in[9];
    const float* si_w     = (const float*)d_in[10];
    const float* si_b     = (const float*)d_in[11];
    const float* so_w     = (const float*)d_in[12];
    const float* so_b     = (const float*)d_in[13];
    const float* a_log    = (const float*)d_in[14];
    const float* d_skip   = (const float*)d_in[15];
    const float* out_w    = (const float*)d_in[16];
    const float* out_b    = (const float*)d_in[17];
    const float* ln_g     = (const float*)d_in[18];
    const float* ln_b     = (const float*)d_in[19];

    float *hidA, *hidB, *sp, *h2, *tp, *pr, *sig, *dl, *so;
    __nv_bfloat16 *Sthi, *Stlo, *Hthi, *Htlo, *Xhi, *Xlo, *Wthi, *Wtlo;
    cudaGetSymbolAddress((void**)&hidA, g_hidA);
    cudaGetSymbolAddress((void**)&hidB, g_hidB);
    cudaGetSymbolAddress((void**)&sp,   g_sp);
    cudaGetSymbolAddress((void**)&h2,   g_h2);
    cudaGetSymbolAddress((void**)&tp,   g_tp);
    cudaGetSymbolAddress((void**)&pr,   g_pr);
    cudaGetSymbolAddress((void**)&sig,  g_sig);
    cudaGetSymbolAddress((void**)&dl,   g_dl);
    cudaGetSymbolAddress((void**)&so,   g_so);
    cudaGetSymbolAddress((void**)&Sthi, g_Sthi);
    cudaGetSymbolAddress((void**)&Stlo, g_Stlo);
    cudaGetSymbolAddress((void**)&Hthi, g_Hthi);
    cudaGetSymbolAddress((void**)&Htlo, g_Htlo);
    cudaGetSymbolAddress((void**)&Xhi,  g_Xhi);
    cudaGetSymbolAddress((void**)&Xlo,  g_Xlo);
    cudaGetSymbolAddress((void**)&Wthi, g_Wthi);
    cudaGetSymbolAddress((void**)&Wtlo, g_Wtlo);

    cudaFuncSetAttribute(gemm_support_mma, cudaFuncAttributeMaxDynamicSharedMemorySize, SMEM_MMA);
    cudaFuncSetAttribute(gemm_rows_hmma<0,false,false>, cudaFuncAttributeMaxDynamicSharedMemorySize, SMEM_MMA);
    cudaFuncSetAttribute(gemm_rows_hmma<0,true ,false>, cudaFuncAttributeMaxDynamicSharedMemorySize, SMEM_MMA);
    cudaFuncSetAttribute(gemm_rows_hmma<0,false,true >, cudaFuncAttributeMaxDynamicSharedMemorySize, SMEM_MMA);
    cudaFuncSetAttribute(gemm_rows_hmma<1,false,true >, cudaFuncAttributeMaxDynamicSharedMemorySize, SMEM_MMA);
    cudaFuncSetAttribute(gemm_rows_hmma<2,false,true >, cudaFuncAttributeMaxDynamicSharedMemorySize, SMEM_MMA);

    const dim3 blk(256);
    const dim3 gmma(16, BT_);
    const dim3 gcvH(64, 4, BT_);
    const dim3 gr1(1, ROWS_ / 128);
    const dim3 gr2(2, ROWS_ / 128);
    const dim3 gr4(4, ROWS_ / 128);
    const int ew_blocks = (BN_ * INNER_) / 256;

    // supports -> bf16 split (transposed)
    convt_S<<<dim3(64, 64, 2), blk>>>(supports, Sthi, Stlo);
    // all weights -> transposed bf16 split
    for (int l = 0; l < 2; l++) {
        __nv_bfloat16* wh = Wthi + (size_t)l * WSZ_L;
        __nv_bfloat16* wl = Wtlo + (size_t)l * WSZ_L;
        const float* gw = gcn_w + (size_t)l * 640 * 128;
        for (int i = 0; i < 5; i++)
            convt_W<<<dim3(4, 4), blk>>>(gw + (size_t)i * 128 * 128, 128, 128,
                                         wh + WOFF_GCN(i), wl + WOFF_GCN(i));
        convt_W<<<dim3(4, 16), blk>>>(in_w   + (size_t)l * 128 * 512, 128, 512, wh + WOFF_IN,  wl + WOFF_IN);
        convt_W<<<dim3(8, 8),  blk>>>(delta_w + (size_t)l * 256 * 256, 256, 256, wh + WOFF_DL,  wl + WOFF_DL);
        convt_W<<<dim3(8, 8),  blk>>>(si_w    + (size_t)l * 256 * 256, 256, 256, wh + WOFF_SI,  wl + WOFF_SI);
        convt_W<<<dim3(8, 8),  blk>>>(so_w    + (size_t)l * 256 * 256, 256, 256, wh + WOFF_SO,  wl + WOFF_SO);
        convt_W<<<dim3(8, 4),  blk>>>(out_w   + (size_t)l * 256 * 128, 256, 128, wh + WOFF_OUT, wl + WOFF_OUT);
    }
    // layer-0 input -> X bf16 split
    conv_plain<<<(int)(SZ_H / 512), blk>>>(inputs, Xhi, Xlo);

    for (int l = 0; l < 2; l++) {
        const float* h_in  = (l == 0) ? inputs : h2;
        float*       h_out = (l == 0) ? h2 : (float*)d_out;
        const __nv_bfloat16* wh = Wthi + (size_t)l * WSZ_L;
        const __nv_bfloat16* wl = Wtlo + (size_t)l * WSZ_L;
        const float* gb  = gcn_b  + l * 128;
        const float* ib  = in_b   + l * 512;
        const float* cw  = conv_w + (size_t)l * INNER_ * KC_;
        const float* cb  = conv_b + l * INNER_;
        const float* db  = delta_b + l * INNER_;
        const float* sib = si_b + l * INNER_;
        const float* sob = so_b + l * INNER_;
        const float* al  = a_log  + l * INNER_;
        const float* dsk = d_skip + l * INNER_;
        const float* ob  = out_b + l * 128;
        const float* lg  = ln_g + l * 128;
        const float* lb  = ln_b + l * 128;

        // --- spatial (GCN) branch --- (X currently holds h_in bf16 split)
        gemm_rows_hmma<0,false,false><<<gr1, blk, SMEM_MMA>>>(Xhi, Xlo, wh + WOFF_GCN(0), wl + WOFF_GCN(0), nullptr, sp, 128, 128);
        convt_H<<<gcvH, blk>>>(h_in, Hthi, Htlo);
        gemm_support_mma<<<gmma, blk, SMEM_MMA>>>(Sthi, Stlo, Hthi, Htlo, hidA, Xhi, Xlo);          // S0 h
        gemm_rows_hmma<0,true,false><<<gr1, blk, SMEM_MMA>>>(Xhi, Xlo, wh + WOFF_GCN(1), wl + WOFF_GCN(1), nullptr, sp, 128, 128);
        convt_H<<<gcvH, blk>>>(hidA, Hthi, Htlo);
        gemm_support_mma<<<gmma, blk, SMEM_MMA>>>(Sthi, Stlo, Hthi, Htlo, hidB, Xhi, Xlo);          // S0^2 h
        gemm_rows_hmma<0,true,false><<<gr1, blk, SMEM_MMA>>>(Xhi, Xlo, wh + WOFF_GCN(2), wl + WOFF_GCN(2), nullptr, sp, 128, 128);
        convt_H<<<gcvH, blk>>>(h_in, Hthi, Htlo);
        gemm_support_mma<<<gmma, blk, SMEM_MMA>>>(Sthi + NN_, Stlo + NN_, Hthi, Htlo, hidA, Xhi, Xlo); // S1 h
        gemm_rows_hmma<0,true,false><<<gr1, blk, SMEM_MMA>>>(Xhi, Xlo, wh + WOFF_GCN(3), wl + WOFF_GCN(3), nullptr, sp, 128, 128);
        convt_H<<<gcvH, blk>>>(hidA, Hthi, Htlo);
        gemm_support_mma<<<gmma, blk, SMEM_MMA>>>(Sthi + NN_, Stlo + NN_, Hthi, Htlo, hidB, Xhi, Xlo); // S1^2 h
        gemm_rows_hmma<0,true,false><<<gr1, blk, SMEM_MMA>>>(Xhi, Xlo, wh + WOFF_GCN(4), wl + WOFF_GCN(4), nullptr, sp, 128, 128);

        // --- temporal branch ---
        transpose_convert_bt<<<(ROWS_ * 32) / 256, 256>>>(h_in, Xhi, Xlo);
        gemm_rows_hmma<0,false,true><<<gr4, blk, SMEM_MMA>>>(Xhi, Xlo, wh + WOFF_IN, wl + WOFF_IN, ib, pr, 128, 512);
        conv_silu_kernel<<<ew_blocks, 256>>>(pr, cw, cb, sig, Xhi, Xlo);
        gemm_rows_hmma<1,false,true><<<gr2, blk, SMEM_MMA>>>(Xhi, Xlo, wh + WOFF_DL, wl + WOFF_DL, db,  dl, 256, 256);
        gemm_rows_hmma<2,false,true><<<gr2, blk, SMEM_MMA>>>(Xhi, Xlo, wh + WOFF_SO, wl + WOFF_SO, sob, so, 256, 256);
        gemm_rows_hmma<2,false,true><<<gr2, blk, SMEM_MMA>>>(Xhi, Xlo, wh + WOFF_SI, wl + WOFF_SI, sib, pr, 256, 512);
        scan_kernel<<<ew_blocks, 256>>>(sig, dl, so, pr, al, dsk, Xhi, Xlo);
        gemm_rows_hmma<0,false,true><<<gr1, blk, SMEM_MMA>>>(Xhi, Xlo, wh + WOFF_OUT, wl + WOFF_OUT, ob, tp, 256, 128);

        // --- fusion + layernorm (also emits next layer's X) ---
        fuse_ln_kernel<<<ROWS_, 128>>>(h_in, sp, gb, tp, lg, lb, h_out, Xhi, Xlo);
    }
}

// round 6
// speedup vs baseline: 2.0350x; 1.0112x over previous
#include <cuda_runtime.h>
#include <cuda_bf16.h>
#include <math.h>
#include <stdint.h>

// ---------------- problem constants ----------------
#define B_    16
#define T_    12
#define N_    2048
#define D_    128
#define INNER_ 256
#define BT_   (B_*T_)          // 192
#define ROWS_ (B_*T_*N_)       // 393216
#define BN_   (B_*N_)          // 32768
#define NN_   ((size_t)N_*N_)
#define XLD_  640              // Xcat row stride (5*128 feature concat)

// ---------------- scratch (device globals; ~3.78 GiB) ----------------
#define SZ_H  ((size_t)ROWS_*D_)
#define SZ_PR ((size_t)ROWS_*512)
#define SZ_I  ((size_t)ROWS_*INNER_)
#define SZ_X  ((size_t)ROWS_*XLD_)
#define SZ_HT ((size_t)BT_*D_*N_)

__device__ __align__(16) float g_sp  [SZ_H];
__device__ __align__(16) float g_h2  [SZ_H];
__device__ __align__(16) float g_tp  [SZ_H];
__device__ __align__(16) float g_pr  [SZ_PR];   // cols 0..255: signal, then delta; 256..511: gate
__device__ __align__(16) float g_sig [SZ_I];
__device__ __align__(16) float g_si  [SZ_I];
__device__ __align__(16) float g_so  [SZ_I];

__device__ __align__(16) __nv_bfloat16 g_Xhi[SZ_X];   // concat activations [M][640]
__device__ __align__(16) __nv_bfloat16 g_Xlo[SZ_X];
__device__ __align__(16) __nv_bfloat16 g_Sthi[2*NN_]; // S^T [i][m][k]
__device__ __align__(16) __nv_bfloat16 g_Stlo[2*NN_];
__device__ __align__(16) __nv_bfloat16 g_Ht0hi[SZ_HT];  // Ht(h)
__device__ __align__(16) __nv_bfloat16 g_Ht0lo[SZ_HT];
__device__ __align__(16) __nv_bfloat16 g_Ht1hi[SZ_HT];  // Ht scratch
__device__ __align__(16) __nv_bfloat16 g_Ht1lo[SZ_HT];

// transposed weights per layer: gcn(640x128)=81920, in=65536, dl/si/so=65536, out=32768
#define WOFF_GCN 0
#define WOFF_IN  81920
#define WOFF_DL  147456
#define WOFF_SI  212992
#define WOFF_SO  278528
#define WOFF_OUT 344064
#define WSZ_L    376832
__device__ __align__(16) __nv_bfloat16 g_Wthi[2*WSZ_L];
__device__ __align__(16) __nv_bfloat16 g_Wtlo[2*WSZ_L];

// ---------------- helpers ----------------
__device__ __forceinline__ float sigmoidf_(float x) { return 1.f / (1.f + expf(-x)); }
__device__ __forceinline__ float softplusf_(float x) {
    return fmaxf(x, 0.f) + log1pf(expf(-fabsf(x)));
}
__device__ __forceinline__ float geluf_(float x) {
    return 0.5f * x * (1.f + erff(x * 0.7071067811865475f));
}
__device__ __forceinline__ uint32_t smem_u32_(const void* p) {
    uint32_t a;
    asm("{ .reg .u64 t; cvta.to.shared.u64 t, %1; cvt.u32.u64 %0, t; }" : "=r"(a) : "l"(p));
    return a;
}
__device__ __forceinline__ void ldsm4_(uint32_t* r, uint32_t a) {
    asm volatile("ldmatrix.sync.aligned.m8n8.x4.shared.b16 {%0,%1,%2,%3}, [%4];"
        : "=r"(r[0]), "=r"(r[1]), "=r"(r[2]), "=r"(r[3]) : "r"(a));
}
__device__ __forceinline__ void mma16816_(float* d, const uint32_t* a, uint32_t b0, uint32_t b1) {
    asm volatile(
        "mma.sync.aligned.m16n8k16.row.col.f32.bf16.bf16.f32 "
        "{%0,%1,%2,%3}, {%4,%5,%6,%7}, {%8,%9}, {%0,%1,%2,%3};"
        : "+f"(d[0]), "+f"(d[1]), "+f"(d[2]), "+f"(d[3])
        : "r"(a[0]), "r"(a[1]), "r"(a[2]), "r"(a[3]), "r"(b0), "r"(b1));
}
__device__ __forceinline__ void split1_(float v, __nv_bfloat16* hi, __nv_bfloat16* lo) {
    __nv_bfloat16 h = __float2bfloat16(v);
    *hi = h;
    *lo = __float2bfloat16(v - __bfloat162float(h));
}
__device__ __forceinline__ void split2_(float v0, float v1,
                                        __nv_bfloat16* hi, __nv_bfloat16* lo) {
    __nv_bfloat16 h0 = __float2bfloat16(v0), h1 = __float2bfloat16(v1);
    __nv_bfloat162 hh; hh.x = h0; hh.y = h1;
    __nv_bfloat162 ll;
    ll.x = __float2bfloat16(v0 - __bfloat162float(h0));
    ll.y = __float2bfloat16(v1 - __bfloat162float(h1));
    *(__nv_bfloat162*)hi = hh;
    *(__nv_bfloat162*)lo = ll;
}

// ---------------- conversions ----------------
__global__ void convt_S(const float* __restrict__ S,
                        __nv_bfloat16* __restrict__ hi, __nv_bfloat16* __restrict__ lo)
{
    __shared__ float t[32][33];
    const int k0 = blockIdx.x * 32, m0 = blockIdx.y * 32, i = blockIdx.z;
    const int tx = threadIdx.x & 31, ty = threadIdx.x >> 5;
    const float* Si = S + (size_t)i * NN_;
    for (int r = ty; r < 32; r += 8)
        t[r][tx] = Si[(size_t)(k0 + r) * N_ + m0 + tx];
    __syncthreads();
    for (int r = ty; r < 32; r += 8) {
        float v = t[tx][r];
        size_t o = (size_t)i * NN_ + (size_t)(m0 + r) * N_ + k0 + tx;
        split1_(v, hi + o, lo + o);
    }
}
// Ht[z][d][n] = H[z][n][d]  (only for the per-layer h input)
__global__ void convt_H(const float* __restrict__ H,
                        __nv_bfloat16* __restrict__ hi, __nv_bfloat16* __restrict__ lo)
{
    __shared__ float t[32][33];
    const int n0 = blockIdx.x * 32, d0 = blockIdx.y * 32, z = blockIdx.z;
    const int tx = threadIdx.x & 31, ty = threadIdx.x >> 5;
    const float* Hz = H + (size_t)z * N_ * D_;
    for (int r = ty; r < 32; r += 8)
        t[r][tx] = Hz[(size_t)(n0 + r) * D_ + d0 + tx];
    __syncthreads();
    for (int r = ty; r < 32; r += 8) {
        float v = t[tx][r];
        size_t o = ((size_t)z * D_ + d0 + r) * N_ + n0 + tx;
        split1_(v, hi + o, lo + o);
    }
}
// Wt[n][k] = W[k][n]
__global__ void convt_W(const float* __restrict__ W, int K, int N,
                        __nv_bfloat16* __restrict__ hi, __nv_bfloat16* __restrict__ lo)
{
    __shared__ float t[32][33];
    const int k0 = blockIdx.x * 32, n0 = blockIdx.y * 32;
    const int tx = threadIdx.x & 31, ty = threadIdx.x >> 5;
    for (int r = ty; r < 32; r += 8)
        t[r][tx] = W[(size_t)(k0 + r) * N + n0 + tx];
    __syncthreads();
    for (int r = ty; r < 32; r += 8) {
        float v = t[tx][r];
        size_t o = (size_t)(n0 + r) * K + k0 + tx;
        split1_(v, hi + o, lo + o);
    }
}
// inputs f32 [M][128] -> Xcat cols 0..127 (ld 640)
__global__ void conv_plain(const float* __restrict__ src,
                           __nv_bfloat16* __restrict__ hi, __nv_bfloat16* __restrict__ lo)
{
    size_t e = ((size_t)blockIdx.x * blockDim.x + threadIdx.x) * 2;
    size_t row = e >> 7;
    int col = (int)(e & 127);
    float2 v = *(const float2*)(src + e);
    size_t o = row * XLD_ + col;
    split2_(v.x, v.y, hi + o, lo + o);
}
// h(b,t,n,d) -> Xcat rows bn*T+t, cols 0..127 (ld 640)
__global__ void transpose_convert_bt(const float* __restrict__ h,
                                     __nv_bfloat16* __restrict__ hi, __nv_bfloat16* __restrict__ lo)
{
    size_t gid = (size_t)blockIdx.x * blockDim.x + threadIdx.x;
    int q = (int)(gid & 31);
    int r = (int)(gid >> 5);
    int t = r % T_;
    int bn = r / T_;
    int n = bn % N_;
    int b = bn / N_;
    size_t src = ((size_t)((b * T_ + t) * N_) + n) * D_ + q * 4;
    float4 v = *(const float4*)(h + src);
    size_t o = (size_t)r * XLD_ + q * 4;
    split2_(v.x, v.y, hi + o, lo + o);
    split2_(v.z, v.w, hi + o + 2, lo + o + 2);
}

// ---------------- HMMA support einsum ----------------
// out[m][d] = sum_k St[m][k]*Ht[z][d][k]; emits Xcat slice; optionally transposed Ht pair.
#define STRD_ 80
#define TILEB_ (128 * STRD_)
#define STAGEB_ (4 * TILEB_)          // 40960
#define SMEM_MMA (2 * STAGEB_)        // 81920

template <bool EMIT_HT>
__global__ void __launch_bounds__(256, 2)
gemm_support_mma(const __nv_bfloat16* __restrict__ Ah, const __nv_bfloat16* __restrict__ Al,
                 const __nv_bfloat16* __restrict__ Bh, const __nv_bfloat16* __restrict__ Bl,
                 __nv_bfloat16* __restrict__ Xhi, __nv_bfloat16* __restrict__ Xlo,  // pre-offset by slot
                 __nv_bfloat16* Hohi, __nv_bfloat16* Holo)
{
    extern __shared__ char smem[];
    const uint32_t sbase = smem_u32_(smem);
    const int m0  = blockIdx.x * 128;
    const int z   = blockIdx.y;
    const int tid = threadIdx.x;
    const int wid = tid >> 5, lid = tid & 31;
    const int wm = wid & 3, wn = wid >> 2;
    const int m_off = wm * 32, n_off = wn * 64;

    const __nv_bfloat16* gp[4] = {
        Ah + (size_t)m0 * N_, Al + (size_t)m0 * N_,
        Bh + (size_t)z * D_ * N_, Bl + (size_t)z * D_ * N_ };

    auto load_stage = [&](int buf, int k0) {
        uint32_t base = sbase + buf * STAGEB_;
#pragma unroll
        for (int i = 0; i < 8; i++) {
            int idx = i * 256 + tid;
            int tile = idx >> 9;
            int rem = idx & 511;
            int r = rem >> 2, c = rem & 3;
            uint32_t dst = base + tile * TILEB_ + r * STRD_ + c * 16;
            const void* src = gp[tile] + (size_t)r * N_ + k0 + c * 8;
            asm volatile("cp.async.cg.shared.global [%0], [%1], 16;" :: "r"(dst), "l"(src));
        }
        asm volatile("cp.async.commit_group;" ::: "memory");
    };

    float acc[2][8][4];
#pragma unroll
    for (int mt = 0; mt < 2; mt++)
#pragma unroll
        for (int nt = 0; nt < 8; nt++)
#pragma unroll
            for (int q = 0; q < 4; q++) acc[mt][nt][q] = 0.f;

    const int a_row = m_off + (lid & 15);
    const int a_kc  = (lid >> 4) << 3;
    const int b_row = n_off + ((lid >> 4) << 3) + (lid & 7);
    const int b_kc  = ((lid >> 3) & 1) << 3;

    const int NT = N_ / 32;
    load_stage(0, 0);
    for (int kt = 0; kt < NT; kt++) {
        if (kt + 1 < NT) {
            load_stage((kt + 1) & 1, (kt + 1) * 32);
            asm volatile("cp.async.wait_group 1;" ::: "memory");
        } else {
            asm volatile("cp.async.wait_group 0;" ::: "memory");
        }
        __syncthreads();

        const uint32_t stg = sbase + (kt & 1) * STAGEB_;
        const uint32_t bAH = stg, bAL = stg + TILEB_, bBH = stg + 2 * TILEB_, bBL = stg + 3 * TILEB_;
#pragma unroll
        for (int k16 = 0; k16 < 2; k16++) {
            const int kb = k16 * 16;
            uint32_t ah[2][4], al[2][4];
#pragma unroll
            for (int mt = 0; mt < 2; mt++) {
                uint32_t ao = (uint32_t)((a_row + mt * 16) * STRD_ + (kb + a_kc) * 2);
                ldsm4_(ah[mt], bAH + ao);
                ldsm4_(al[mt], bAL + ao);
            }
#pragma unroll
            for (int pt = 0; pt < 4; pt++) {
                uint32_t bo = (uint32_t)((b_row + pt * 16) * STRD_ + (kb + b_kc) * 2);
                uint32_t bh[4], bl[4];
                ldsm4_(bh, bBH + bo);
                ldsm4_(bl, bBL + bo);
#pragma unroll
                for (int mt = 0; mt < 2; mt++) {
#pragma unroll
                    for (int sub = 0; sub < 2; sub++) {
                        const int nt = pt * 2 + sub;
                        mma16816_(acc[mt][nt], ah[mt], bh[2 * sub], bh[2 * sub + 1]);
                        mma16816_(acc[mt][nt], ah[mt], bl[2 * sub], bl[2 * sub + 1]);
                        mma16816_(acc[mt][nt], al[mt], bh[2 * sub], bh[2 * sub + 1]);
                    }
                }
            }
        }
        __syncthreads();
    }

    // epilogue 1: Xcat slice (rows z*N+m, ld XLD_)
#pragma unroll
    for (int mt = 0; mt < 2; mt++) {
        const size_t r0 = (size_t)z * N_ + m0 + m_off + mt * 16 + (lid >> 2);
        __nv_bfloat16* xh0 = Xhi + r0 * XLD_;
        __nv_bfloat16* xl0 = Xlo + r0 * XLD_;
        __nv_bfloat16* xh1 = Xhi + (r0 + 8) * XLD_;
        __nv_bfloat16* xl1 = Xlo + (r0 + 8) * XLD_;
#pragma unroll
        for (int nt = 0; nt < 8; nt++) {
            const int cc = n_off + nt * 8 + (lid & 3) * 2;
            split2_(acc[mt][nt][0], acc[mt][nt][1], xh0 + cc, xl0 + cc);
            split2_(acc[mt][nt][2], acc[mt][nt][3], xh1 + cc, xl1 + cc);
        }
    }

    // epilogue 2: transposed Ht emission via smem
    if (EMIT_HT) {
        float* ts = (float*)smem;    // [128][132]
#pragma unroll
        for (int mt = 0; mt < 2; mt++) {
            const int mr = m_off + mt * 16 + (lid >> 2);
#pragma unroll
            for (int nt = 0; nt < 8; nt++) {
                const int cc = n_off + nt * 8 + (lid & 3) * 2;
                ts[mr * 132 + cc]           = acc[mt][nt][0];
                ts[mr * 132 + cc + 1]       = acc[mt][nt][1];
                ts[(mr + 8) * 132 + cc]     = acc[mt][nt][2];
                ts[(mr + 8) * 132 + cc + 1] = acc[mt][nt][3];
            }
        }
        __syncthreads();
        const int d = tid >> 1;
        const int mh = (tid & 1) * 64;
        const size_t hb = (size_t)z * D_ * N_ + (size_t)d * N_ + m0 + mh;
#pragma unroll
        for (int mi = 0; mi < 32; mi++) {
            float v0 = ts[(mh + mi * 2) * 132 + d];
            float v1 = ts[(mh + mi * 2 + 1) * 132 + d];
            split2_(v0, v1, Hohi + hb + mi * 2, Holo + hb + mi * 2);
        }
    }
}

// ---------------- HMMA rows GEMM: C = act( X·Wt + bias ) ----------
// X [M][K] (row stride lda), Wt [N][K] (row stride ldb). ACT: 0 none,1 softplus,2 tanh.
template <int ACT, bool BIAS>
__global__ void __launch_bounds__(256, 2)
gemm_rows_hmma(const __nv_bfloat16* __restrict__ Xhi, const __nv_bfloat16* __restrict__ Xlo,
               const __nv_bfloat16* __restrict__ Whi, const __nv_bfloat16* __restrict__ Wlo,
               const float* __restrict__ bias, float* __restrict__ C,
               int K, int lda, int ldb, int ldc)
{
    extern __shared__ char smem[];
    const uint32_t sbase = smem_u32_(smem);
    const int j0  = blockIdx.x * 128;
    const int r0  = blockIdx.y * 128;
    const int tid = threadIdx.x;
    const int wid = tid >> 5, lid = tid & 31;
    const int wm = wid & 3, wn = wid >> 2;
    const int m_off = wm * 32, n_off = wn * 64;

    const __nv_bfloat16* gp[4] = {
        Xhi + (size_t)r0 * lda, Xlo + (size_t)r0 * lda,
        Whi + (size_t)j0 * ldb, Wlo + (size_t)j0 * ldb };

    auto load_stage = [&](int buf, int k0) {
        uint32_t base = sbase + buf * STAGEB_;
#pragma unroll
        for (int i = 0; i < 8; i++) {
            int idx = i * 256 + tid;
            int tile = idx >> 9;
            int rem = idx & 511;
            int r = rem >> 2, c = rem & 3;
            int ld = (tile < 2) ? lda : ldb;
            uint32_t dst = base + tile * TILEB_ + r * STRD_ + c * 16;
            const void* src = gp[tile] + (size_t)r * ld + k0 + c * 8;
            asm volatile("cp.async.cg.shared.global [%0], [%1], 16;" :: "r"(dst), "l"(src));
        }
        asm volatile("cp.async.commit_group;" ::: "memory");
    };

    float acc[2][8][4];
#pragma unroll
    for (int mt = 0; mt < 2; mt++)
#pragma unroll
        for (int nt = 0; nt < 8; nt++)
#pragma unroll
            for (int q = 0; q < 4; q++) acc[mt][nt][q] = 0.f;

    const int a_row = m_off + (lid & 15);
    const int a_kc  = (lid >> 4) << 3;
    const int b_row = n_off + ((lid >> 4) << 3) + (lid & 7);
    const int b_kc  = ((lid >> 3) & 1) << 3;

    const int NT = K >> 5;
    load_stage(0, 0);
    for (int kt = 0; kt < NT; kt++) {
        if (kt + 1 < NT) {
            load_stage((kt + 1) & 1, (kt + 1) * 32);
            asm volatile("cp.async.wait_group 1;" ::: "memory");
        } else {
            asm volatile("cp.async.wait_group 0;" ::: "memory");
        }
        __syncthreads();

        const uint32_t stg = sbase + (kt & 1) * STAGEB_;
        const uint32_t bAH = stg, bAL = stg + TILEB_, bBH = stg + 2 * TILEB_, bBL = stg + 3 * TILEB_;
#pragma unroll
        for (int k16 = 0; k16 < 2; k16++) {
            const int kb = k16 * 16;
            uint32_t ah[2][4], al[2][4];
#pragma unroll
            for (int mt = 0; mt < 2; mt++) {
                uint32_t ao = (uint32_t)((a_row + mt * 16) * STRD_ + (kb + a_kc) * 2);
                ldsm4_(ah[mt], bAH + ao);
                ldsm4_(al[mt], bAL + ao);
            }
#pragma unroll
            for (int pt = 0; pt < 4; pt++) {
                uint32_t bo = (uint32_t)((b_row + pt * 16) * STRD_ + (kb + b_kc) * 2);
                uint32_t bh[4], bl[4];
                ldsm4_(bh, bBH + bo);
                ldsm4_(bl, bBL + bo);
#pragma unroll
                for (int mt = 0; mt < 2; mt++) {
#pragma unroll
                    for (int sub = 0; sub < 2; sub++) {
                        const int nt = pt * 2 + sub;
                        mma16816_(acc[mt][nt], ah[mt], bh[2 * sub], bh[2 * sub + 1]);
                        mma16816_(acc[mt][nt], ah[mt], bl[2 * sub], bl[2 * sub + 1]);
                        mma16816_(acc[mt][nt], al[mt], bh[2 * sub], bh[2 * sub + 1]);
                    }
                }
            }
        }
        __syncthreads();
    }

    auto ep = [&](float v, float b) -> float {
        if (BIAS) v += b;
        if (ACT == 1) v = softplusf_(v);
        else if (ACT == 2) v = tanhf(v);
        return v;
    };
#pragma unroll
    for (int mt = 0; mt < 2; mt++) {
        const int r = r0 + m_off + mt * 16 + (lid >> 2);
        float* c0 = C + (size_t)r * ldc + j0;
        float* c1 = C + (size_t)(r + 8) * ldc + j0;
#pragma unroll
        for (int nt = 0; nt < 8; nt++) {
            const int cc = n_off + nt * 8 + (lid & 3) * 2;
            float b0 = 0.f, b1 = 0.f;
            if (BIAS) { b0 = bias[j0 + cc]; b1 = bias[j0 + cc + 1]; }
            *(float2*)(c0 + cc) = make_float2(ep(acc[mt][nt][0], b0), ep(acc[mt][nt][1], b1));
            *(float2*)(c1 + cc) = make_float2(ep(acc[mt][nt][2], b0), ep(acc[mt][nt][3], b1));
        }
    }
}

// ---------------- causal depthwise conv (K=4) + SiLU ------
__global__ void conv_silu_kernel(const float* __restrict__ pr, const float* __restrict__ cw,
                                 const float* __restrict__ cb, float* __restrict__ sig,
                                 __nv_bfloat16* __restrict__ hi, __nv_bfloat16* __restrict__ lo)
{
    int idx = blockIdx.x * blockDim.x + threadIdx.x;
    int c = idx & (INNER_ - 1);
    int bn = idx >> 8;
    float w0 = cw[c * 4 + 0], w1 = cw[c * 4 + 1], w2 = cw[c * 4 + 2], w3 = cw[c * 4 + 3];
    float b = cb[c];
    float s[T_];
    size_t base = (size_t)bn * T_ * 512 + c;
#pragma unroll
    for (int t = 0; t < T_; t++) s[t] = pr[base + (size_t)t * 512];
    size_t ob = (size_t)bn * T_ * INNER_ + c;
    size_t ox = (size_t)bn * T_ * XLD_ + c;
#pragma unroll
    for (int t = 0; t < T_; t++) {
        float a = b + w3 * s[t];
        if (t >= 1) a += w2 * s[t - 1];
        if (t >= 2) a += w1 * s[t - 2];
        if (t >= 3) a += w0 * s[t - 3];
        float v = a * sigmoidf_(a);
        sig[ob + (size_t)t * INNER_] = v;
        split1_(v, hi + ox + (size_t)t * XLD_, lo + ox + (size_t)t * XLD_);
    }
}

// ---------------- selective-scan + gating; y -> Xcat cols 0..255 ----------
__global__ void scan_kernel(const float* __restrict__ sig, const float* __restrict__ si,
                            const float* __restrict__ so, const float* __restrict__ pr,
                            const float* __restrict__ a_log, const float* __restrict__ d_skip,
                            __nv_bfloat16* __restrict__ yhi, __nv_bfloat16* __restrict__ ylo)
{
    int idx = blockIdx.x * blockDim.x + threadIdx.x;
    int c = idx & (INNER_ - 1);
    int bn = idx >> 8;
    float a = -softplusf_(a_log[c]);
    float dsk = d_skip[c];
    float state = 0.f;
    size_t b256 = (size_t)bn * T_ * INNER_ + c;
    size_t b512 = (size_t)bn * T_ * 512 + c;
    size_t bx   = (size_t)bn * T_ * XLD_ + c;
#pragma unroll
    for (int t = 0; t < T_; t++) {
        float x  = sig[b256 + (size_t)t * INNER_];
        float d  = pr [b512 + (size_t)t * 512];            // delta (cols 0..255)
        float iv = si [b256 + (size_t)t * INNER_];
        float ov = so [b256 + (size_t)t * INNER_];
        float g  = pr [b512 + (size_t)t * 512 + INNER_];   // gate (cols 256..511)
        state = expf(d * a) * state + iv * x;
        float yy = (ov * state + dsk * x) * sigmoidf_(g);
        split1_(yy, yhi + bx + (size_t)t * XLD_, ylo + bx + (size_t)t * XLD_);
    }
}

// ---------------- fusion + LayerNorm; also emits Xcat h slice -----------------
__global__ void fuse_ln_kernel(const float* __restrict__ h_in, const float* __restrict__ sp_pre,
                               const float* __restrict__ gcn_b, const float* __restrict__ tp,
                               const float* __restrict__ ln_g, const float* __restrict__ ln_b,
                               float* __restrict__ h_out,
                               __nv_bfloat16* __restrict__ ohi, __nv_bfloat16* __restrict__ olo)
{
    int token = blockIdx.x;
    int d = threadIdx.x;
    int n  = token % N_;
    int bt = token / N_;
    int t  = bt % T_;
    int b  = bt / T_;
    size_t row    = (size_t)token * D_;
    size_t row_tp = ((size_t)(b * N_ + n) * T_ + t) * D_;

    float hv = h_in[row + d];
    float s = sp_pre[row + d] + gcn_b[d];
    s = geluf_(s);
    float tv = tp[row_tp + d];
    float f = hv + s + tv + s * tv;

    __shared__ float red[8];
    float v = f;
#pragma unroll
    for (int o = 16; o > 0; o >>= 1) v += __shfl_xor_sync(0xffffffffu, v, o);
    if ((d & 31) == 0) red[d >> 5] = v;
    __syncthreads();
    float mu = (red[0] + red[1] + red[2] + red[3]) * (1.f / 128.f);
    float dv = f - mu;
    v = dv * dv;
#pragma unroll
    for (int o = 16; o > 0; o >>= 1) v += __shfl_xor_sync(0xffffffffu, v, o);
    if ((d & 31) == 0) red[4 + (d >> 5)] = v;
    __syncthreads();
    float var = (red[4] + red[5] + red[6] + red[7]) * (1.f / 128.f);
    float out = dv * rsqrtf(var + 1e-5f) * ln_g[d] + ln_b[d];
    h_out[row + d] = out;
    split1_(out, ohi + (size_t)token * XLD_ + d, olo + (size_t)token * XLD_ + d);
}

// ---------------- host launcher ----------------
extern "C" void kernel_launch(void* const* d_in, const int* in_sizes, int n_in,
                              void* d_out, int out_size)
{
    (void)in_sizes; (void)n_in; (void)out_size;
    const float* inputs   = (const float*)d_in[0];
    const float* supports = (const float*)d_in[1];
    const float* gcn_w    = (const float*)d_in[2];
    const float* gcn_b    = (const float*)d_in[3];
    const float* in_w     = (const float*)d_in[4];
    const float* in_b     = (const float*)d_in[5];
    const float* conv_w   = (const float*)d_in[6];
    const float* conv_b   = (const float*)d_in[7];
    const float* delta_w  = (const float*)d_in[8];
    const float* delta_b  = (const float*)d_in[9];
    const float* si_w     = (const float*)d_in[10];
    const float* si_b     = (const float*)d_in[11];
    const float* so_w     = (const float*)d_in[12];
    const float* so_b     = (const float*)d_in[13];
    const float* a_log    = (const float*)d_in[14];
    const float* d_skip   = (const float*)d_in[15];
    const float* out_w    = (const float*)d_in[16];
    const float* out_b    = (const float*)d_in[17];
    const float* ln_g     = (const float*)d_in[18];
    const float* ln_b     = (const float*)d_in[19];

    float *sp, *h2, *tp, *pr, *sig, *si, *so;
    __nv_bfloat16 *Sthi, *Stlo, *Xhi, *Xlo, *Wthi, *Wtlo;
    __nv_bfloat16 *Ht0hi, *Ht0lo, *Ht1hi, *Ht1lo;
    cudaGetSymbolAddress((void**)&sp,   g_sp);
    cudaGetSymbolAddress((void**)&h2,   g_h2);
    cudaGetSymbolAddress((void**)&tp,   g_tp);
    cudaGetSymbolAddress((void**)&pr,   g_pr);
    cudaGetSymbolAddress((void**)&sig,  g_sig);
    cudaGetSymbolAddress((void**)&si,   g_si);
    cudaGetSymbolAddress((void**)&so,   g_so);
    cudaGetSymbolAddress((void**)&Sthi, g_Sthi);
    cudaGetSymbolAddress((void**)&Stlo, g_Stlo);
    cudaGetSymbolAddress((void**)&Xhi,  g_Xhi);
    cudaGetSymbolAddress((void**)&Xlo,  g_Xlo);
    cudaGetSymbolAddress((void**)&Wthi, g_Wthi);
    cudaGetSymbolAddress((void**)&Wtlo, g_Wtlo);
    cudaGetSymbolAddress((void**)&Ht0hi, g_Ht0hi);
    cudaGetSymbolAddress((void**)&Ht0lo, g_Ht0lo);
    cudaGetSymbolAddress((void**)&Ht1hi, g_Ht1hi);
    cudaGetSymbolAddress((void**)&Ht1lo, g_Ht1lo);

    cudaFuncSetAttribute(gemm_support_mma<true >, cudaFuncAttributeMaxDynamicSharedMemorySize, SMEM_MMA);
    cudaFuncSetAttribute(gemm_support_mma<false>, cudaFuncAttributeMaxDynamicSharedMemorySize, SMEM_MMA);
    cudaFuncSetAttribute(gemm_rows_hmma<0,false>, cudaFuncAttributeMaxDynamicSharedMemorySize, SMEM_MMA);
    cudaFuncSetAttribute(gemm_rows_hmma<0,true >, cudaFuncAttributeMaxDynamicSharedMemorySize, SMEM_MMA);
    cudaFuncSetAttribute(gemm_rows_hmma<1,true >, cudaFuncAttributeMaxDynamicSharedMemorySize, SMEM_MMA);
    cudaFuncSetAttribute(gemm_rows_hmma<2,true >, cudaFuncAttributeMaxDynamicSharedMemorySize, SMEM_MMA);

    const dim3 blk(256);
    const dim3 gmma(16, BT_);
    const dim3 gcvH(64, 4, BT_);
    const dim3 gr1(1, ROWS_ / 128);
    const dim3 gr2(2, ROWS_ / 128);
    const dim3 gr4(4, ROWS_ / 128);
    const int ew_blocks = (BN_ * INNER_) / 256;

    convt_S<<<dim3(64, 64, 2), blk>>>(supports, Sthi, Stlo);
    for (int l = 0; l < 2; l++) {
        __nv_bfloat16* wh = Wthi + (size_t)l * WSZ_L;
        __nv_bfloat16* wl = Wtlo + (size_t)l * WSZ_L;
        convt_W<<<dim3(20, 4), blk>>>(gcn_w  + (size_t)l * 640 * 128, 640, 128, wh + WOFF_GCN, wl + WOFF_GCN);
        convt_W<<<dim3(4, 16), blk>>>(in_w   + (size_t)l * 128 * 512, 128, 512, wh + WOFF_IN,  wl + WOFF_IN);
        convt_W<<<dim3(8, 8),  blk>>>(delta_w + (size_t)l * 256 * 256, 256, 256, wh + WOFF_DL,  wl + WOFF_DL);
        convt_W<<<dim3(8, 8),  blk>>>(si_w    + (size_t)l * 256 * 256, 256, 256, wh + WOFF_SI,  wl + WOFF_SI);
        convt_W<<<dim3(8, 8),  blk>>>(so_w    + (size_t)l * 256 * 256, 256, 256, wh + WOFF_SO,  wl + WOFF_SO);
        convt_W<<<dim3(8, 4),  blk>>>(out_w   + (size_t)l * 256 * 128, 256, 128, wh + WOFF_OUT, wl + WOFF_OUT);
    }
    conv_plain<<<(int)(SZ_H / 512), blk>>>(inputs, Xhi, Xlo);   // h slice for layer 0

    for (int l = 0; l < 2; l++) {
        const float* h_in  = (l == 0) ? inputs : h2;
        float*       h_out = (l == 0) ? h2 : (float*)d_out;
        const __nv_bfloat16* wh = Wthi + (size_t)l * WSZ_L;
        const __nv_bfloat16* wl = Wtlo + (size_t)l * WSZ_L;
        const float* gb  = gcn_b  + l * 128;
        const float* ib  = in_b   + l * 512;
        const float* cw  = conv_w + (size_t)l * INNER_ * 4;
        const float* cb  = conv_b + l * INNER_;
        const float* db  = delta_b + l * INNER_;
        const float* sib = si_b + l * INNER_;
        const float* sob = so_b + l * INNER_;
        const float* al  = a_log  + l * INNER_;
        const float* dsk = d_skip + l * INNER_;
        const float* ob  = out_b + l * 128;
        const float* lg  = ln_g + l * 128;
        const float* lb  = ln_b + l * 128;

        // --- spatial branch: 4 einsums fill Xcat slices, then one K=640 GEMM ---
        convt_H<<<gcvH, blk>>>(h_in, Ht0hi, Ht0lo);
        gemm_support_mma<true ><<<gmma, blk, SMEM_MMA>>>(Sthi,       Stlo,       Ht0hi, Ht0lo, Xhi + 128, Xlo + 128, Ht1hi, Ht1lo); // S0 h
        gemm_support_mma<false><<<gmma, blk, SMEM_MMA>>>(Sthi,       Stlo,       Ht1hi, Ht1lo, Xhi + 256, Xlo + 256, nullptr, nullptr); // S0^2 h
        gemm_support_mma<true ><<<gmma, blk, SMEM_MMA>>>(Sthi + NN_, Stlo + NN_, Ht0hi, Ht0lo, Xhi + 384, Xlo + 384, Ht1hi, Ht1lo); // S1 h
        gemm_support_mma<false><<<gmma, blk, SMEM_MMA>>>(Sthi + NN_, Stlo + NN_, Ht1hi, Ht1lo, Xhi + 512, Xlo + 512, nullptr, nullptr); // S1^2 h
        gemm_rows_hmma<0,false><<<gr1, blk, SMEM_MMA>>>(Xhi, Xlo, wh + WOFF_GCN, wl + WOFF_GCN, nullptr, sp, 640, XLD_, 640, 128);

        // --- temporal branch ---
        transpose_convert_bt<<<(ROWS_ * 32) / 256, 256>>>(h_in, Xhi, Xlo);
        gemm_rows_hmma<0,true><<<gr4, blk, SMEM_MMA>>>(Xhi, Xlo, wh + WOFF_IN, wl + WOFF_IN, ib, pr, 128, XLD_, 128, 512);
        conv_silu_kernel<<<ew_blocks, 256>>>(pr, cw, cb, sig, Xhi, Xlo);
        gemm_rows_hmma<1,true><<<gr2, blk, SMEM_MMA>>>(Xhi, Xlo, wh + WOFF_DL, wl + WOFF_DL, db,  pr, 256, XLD_, 256, 512); // delta -> pr cols 0..255
        gemm_rows_hmma<2,true><<<gr2, blk, SMEM_MMA>>>(Xhi, Xlo, wh + WOFF_SI, wl + WOFF_SI, sib, si, 256, XLD_, 256, 256);
        gemm_rows_hmma<2,true><<<gr2, blk, SMEM_MMA>>>(Xhi, Xlo, wh + WOFF_SO, wl + WOFF_SO, sob, so, 256, XLD_, 256, 256);
        scan_kernel<<<ew_blocks, 256>>>(sig, si, so, pr, al, dsk, Xhi, Xlo);
        gemm_rows_hmma<0,true><<<gr1, blk, SMEM_MMA>>>(Xhi, Xlo, wh + WOFF_OUT, wl + WOFF_OUT, ob, tp, 256, XLD_, 256, 128);

        // --- fusion + layernorm (also emits next layer's h slice into Xcat) ---
        fuse_ln_kernel<<<ROWS_, 128>>>(h_in, sp, gb, tp, lg, lb, h_out, Xhi, Xlo);
    }
}

// round 7
// speedup vs baseline: 2.7646x; 1.3585x over previous
#include <cuda_runtime.h>
#include <cuda_fp16.h>
#include <math.h>
#include <stdint.h>

// ---------------- problem constants ----------------
#define B_    16
#define T_    12
#define N_    2048
#define D_    128
#define INNER_ 256
#define BT_   (B_*T_)          // 192
#define ROWS_ (B_*T_*N_)       // 393216
#define BN_   (B_*N_)          // 32768
#define NN_   ((size_t)N_*N_)
#define XLD_  640              // Xcat row stride (5*128 feature concat)

// ---------------- scratch (device globals; ~3.1 GiB) ----------------
#define SZ_H  ((size_t)ROWS_*D_)
#define SZ_PR ((size_t)ROWS_*512)
#define SZ_I  ((size_t)ROWS_*INNER_)
#define SZ_X  ((size_t)ROWS_*XLD_)
#define SZ_HT ((size_t)BT_*D_*N_)

__device__ __align__(16) float g_sp  [SZ_H];
__device__ __align__(16) float g_h2  [SZ_H];
__device__ __align__(16) float g_tp  [SZ_H];
__device__ __align__(16) float g_pr  [SZ_PR];   // cols 0..255: signal, then delta; 256..511: gate
__device__ __align__(16) float g_sig [SZ_I];
__device__ __align__(16) float g_si  [SZ_I];
__device__ __align__(16) float g_so  [SZ_I];

__device__ __align__(16) __half g_X   [SZ_X];    // concat activations, single fp16 [M][640]
__device__ __align__(16) __half g_St  [2*NN_];   // S^T single fp16 [i][m][k]
__device__ __align__(16) __half g_Ht0hi[SZ_HT];  // Ht(h) split [z][d][k]
__device__ __align__(16) __half g_Ht0lo[SZ_HT];
__device__ __align__(16) __half g_Ht1hi[SZ_HT];  // Ht scratch
__device__ __align__(16) __half g_Ht1lo[SZ_HT];

// transposed weights per layer (split fp16)
#define WOFF_GCN 0
#define WOFF_IN  81920
#define WOFF_DL  147456
#define WOFF_SI  212992
#define WOFF_SO  278528
#define WOFF_OUT 344064
#define WSZ_L    376832
__device__ __align__(16) __half g_Wthi[2*WSZ_L];
__device__ __align__(16) __half g_Wtlo[2*WSZ_L];

// ---------------- helpers ----------------
__device__ __forceinline__ float sigmoidf_(float x) { return 1.f / (1.f + expf(-x)); }
__device__ __forceinline__ float softplusf_(float x) {
    return fmaxf(x, 0.f) + log1pf(expf(-fabsf(x)));
}
__device__ __forceinline__ float geluf_(float x) {
    return 0.5f * x * (1.f + erff(x * 0.7071067811865475f));
}
__device__ __forceinline__ uint32_t smem_u32_(const void* p) {
    uint32_t a;
    asm("{ .reg .u64 t; cvta.to.shared.u64 t, %1; cvt.u32.u64 %0, t; }" : "=r"(a) : "l"(p));
    return a;
}
__device__ __forceinline__ void ldsm4_(uint32_t* r, uint32_t a) {
    asm volatile("ldmatrix.sync.aligned.m8n8.x4.shared.b16 {%0,%1,%2,%3}, [%4];"
        : "=r"(r[0]), "=r"(r[1]), "=r"(r[2]), "=r"(r[3]) : "r"(a));
}
__device__ __forceinline__ void mma16816_(float* d, const uint32_t* a, uint32_t b0, uint32_t b1) {
    asm volatile(
        "mma.sync.aligned.m16n8k16.row.col.f32.f16.f16.f32 "
        "{%0,%1,%2,%3}, {%4,%5,%6,%7}, {%8,%9}, {%0,%1,%2,%3};"
        : "+f"(d[0]), "+f"(d[1]), "+f"(d[2]), "+f"(d[3])
        : "r"(a[0]), "r"(a[1]), "r"(a[2]), "r"(a[3]), "r"(b0), "r"(b1));
}
__device__ __forceinline__ void splith_(float v, __half* hi, __half* lo) {
    __half h = __float2half_rn(v);
    *hi = h;
    *lo = __float2half_rn(v - __half2float(h));
}
__device__ __forceinline__ void splith2_(float v0, float v1, __half* hi, __half* lo) {
    __half h0 = __float2half_rn(v0), h1 = __float2half_rn(v1);
    __half2 hh; hh.x = h0; hh.y = h1;
    __half2 ll;
    ll.x = __float2half_rn(v0 - __half2float(h0));
    ll.y = __float2half_rn(v1 - __half2float(h1));
    *(__half2*)hi = hh;
    *(__half2*)lo = ll;
}

// ---------------- conversions ----------------
// St[i][m][k] = S[i][k][m], single fp16
__global__ void convt_S(const float* __restrict__ S, __half* __restrict__ out)
{
    __shared__ float t[32][33];
    const int k0 = blockIdx.x * 32, m0 = blockIdx.y * 32, i = blockIdx.z;
    const int tx = threadIdx.x & 31, ty = threadIdx.x >> 5;
    const float* Si = S + (size_t)i * NN_;
    for (int r = ty; r < 32; r += 8)
        t[r][tx] = Si[(size_t)(k0 + r) * N_ + m0 + tx];
    __syncthreads();
    for (int r = ty; r < 32; r += 8) {
        size_t o = (size_t)i * NN_ + (size_t)(m0 + r) * N_ + k0 + tx;
        out[o] = __float2half_rn(t[tx][r]);
    }
}
// Ht[z][d][n] = H[z][n][d], split fp16
__global__ void convt_H(const float* __restrict__ H,
                        __half* __restrict__ hi, __half* __restrict__ lo)
{
    __shared__ float t[32][33];
    const int n0 = blockIdx.x * 32, d0 = blockIdx.y * 32, z = blockIdx.z;
    const int tx = threadIdx.x & 31, ty = threadIdx.x >> 5;
    const float* Hz = H + (size_t)z * N_ * D_;
    for (int r = ty; r < 32; r += 8)
        t[r][tx] = Hz[(size_t)(n0 + r) * D_ + d0 + tx];
    __syncthreads();
    for (int r = ty; r < 32; r += 8) {
        size_t o = ((size_t)z * D_ + d0 + r) * N_ + n0 + tx;
        splith_(t[tx][r], hi + o, lo + o);
    }
}
// Wt[n][k] = W[k][n], split fp16
__global__ void convt_W(const float* __restrict__ W, int K, int N,
                        __half* __restrict__ hi, __half* __restrict__ lo)
{
    __shared__ float t[32][33];
    const int k0 = blockIdx.x * 32, n0 = blockIdx.y * 32;
    const int tx = threadIdx.x & 31, ty = threadIdx.x >> 5;
    for (int r = ty; r < 32; r += 8)
        t[r][tx] = W[(size_t)(k0 + r) * N + n0 + tx];
    __syncthreads();
    for (int r = ty; r < 32; r += 8) {
        size_t o = (size_t)(n0 + r) * K + k0 + tx;
        splith_(t[tx][r], hi + o, lo + o);
    }
}
// inputs f32 [M][128] -> Xcat cols 0..127 (ld 640)
__global__ void conv_plain(const float* __restrict__ src, __half* __restrict__ x)
{
    size_t e = ((size_t)blockIdx.x * blockDim.x + threadIdx.x) * 2;
    size_t row = e >> 7;
    int col = (int)(e & 127);
    float2 v = *(const float2*)(src + e);
    *(__half2*)(x + row * XLD_ + col) = __floats2half2_rn(v.x, v.y);
}
// h(b,t,n,d) -> Xcat rows bn*T+t, cols 0..127 (ld 640)
__global__ void transpose_convert_bt(const float* __restrict__ h, __half* __restrict__ x)
{
    size_t gid = (size_t)blockIdx.x * blockDim.x + threadIdx.x;
    int q = (int)(gid & 31);
    int r = (int)(gid >> 5);
    int t = r % T_;
    int bn = r / T_;
    int n = bn % N_;
    int b = bn / N_;
    size_t src = ((size_t)((b * T_ + t) * N_) + n) * D_ + q * 4;
    float4 v = *(const float4*)(h + src);
    size_t o = (size_t)r * XLD_ + q * 4;
    *(__half2*)(x + o)     = __floats2half2_rn(v.x, v.y);
    *(__half2*)(x + o + 2) = __floats2half2_rn(v.z, v.w);
}

// ---------------- HMMA GEMM infrastructure ----------------
// stage: 3 tiles (A single, Bhi, Blo), each 128 rows x 32 k of fp16, row stride 80B
#define STRD_ 80
#define TILEB_ (128 * STRD_)          // 10240
#define STAGEB_ (3 * TILEB_)          // 30720
#define NSTG_ 3
#define SMEM_MMA (NSTG_ * STAGEB_)    // 92160

// ---------------- support einsum: C[m][d] = sum_k St[m][k] * Ht[z][d][k] -------
// 2-product: St * (Hhi + Hlo). Emits Xcat slice (fp16); optionally transposed Ht split.
template <bool EMIT_HT>
__global__ void __launch_bounds__(256, 2)
gemm_support_mma(const __half* __restrict__ A,
                 const __half* __restrict__ Bh, const __half* __restrict__ Bl,
                 __half* __restrict__ X,          // pre-offset by slot
                 __half* Hohi, __half* Holo)
{
    extern __shared__ char smem[];
    const uint32_t sbase = smem_u32_(smem);
    const int m0  = blockIdx.x * 128;
    const int z   = blockIdx.y;
    const int tid = threadIdx.x;
    const int wid = tid >> 5, lid = tid & 31;
    const int wm = wid & 3, wn = wid >> 2;
    const int m_off = wm * 32, n_off = wn * 64;

    const __half* gp[3] = {
        A + (size_t)m0 * N_,
        Bh + (size_t)z * D_ * N_, Bl + (size_t)z * D_ * N_ };

    auto load_stage = [&](int buf, int k0) {
        uint32_t base = sbase + buf * STAGEB_;
#pragma unroll
        for (int i = 0; i < 6; i++) {
            int idx = i * 256 + tid;          // 0..1535
            int tile = idx >> 9;
            int rem = idx & 511;
            int r = rem >> 2, c = rem & 3;
            uint32_t dst = base + tile * TILEB_ + r * STRD_ + c * 16;
            const void* src = gp[tile] + (size_t)r * N_ + k0 + c * 8;
            asm volatile("cp.async.cg.shared.global [%0], [%1], 16;" :: "r"(dst), "l"(src));
        }
        asm volatile("cp.async.commit_group;" ::: "memory");
    };

    float acc[2][8][4];
#pragma unroll
    for (int mt = 0; mt < 2; mt++)
#pragma unroll
        for (int nt = 0; nt < 8; nt++)
#pragma unroll
            for (int q = 0; q < 4; q++) acc[mt][nt][q] = 0.f;

    const int a_row = m_off + (lid & 15);
    const int a_kc  = (lid >> 4) << 3;
    const int b_row = n_off + ((lid >> 4) << 3) + (lid & 7);
    const int b_kc  = ((lid >> 3) & 1) << 3;

    const int NT = N_ / 32;   // 64
    load_stage(0, 0);
    load_stage(1, 32);
    for (int kt = 0; kt < NT; kt++) {
        if (kt + 1 < NT) asm volatile("cp.async.wait_group 1;" ::: "memory");
        else             asm volatile("cp.async.wait_group 0;" ::: "memory");
        __syncthreads();
        if (kt + 2 < NT) load_stage((kt + 2) % NSTG_, (kt + 2) * 32);

        const uint32_t stg = sbase + (kt % NSTG_) * STAGEB_;
        const uint32_t bA = stg, bBH = stg + TILEB_, bBL = stg + 2 * TILEB_;
#pragma unroll
        for (int k16 = 0; k16 < 2; k16++) {
            const int kb = k16 * 16;
            uint32_t ah[2][4];
#pragma unroll
            for (int mt = 0; mt < 2; mt++)
                ldsm4_(ah[mt], bA + (uint32_t)((a_row + mt * 16) * STRD_ + (kb + a_kc) * 2));
#pragma unroll
            for (int pt = 0; pt < 4; pt++) {
                uint32_t bo = (uint32_t)((b_row + pt * 16) * STRD_ + (kb + b_kc) * 2);
                uint32_t bh[4], bl[4];
                ldsm4_(bh, bBH + bo);
                ldsm4_(bl, bBL + bo);
#pragma unroll
                for (int mt = 0; mt < 2; mt++) {
#pragma unroll
                    for (int sub = 0; sub < 2; sub++) {
                        const int nt = pt * 2 + sub;
                        mma16816_(acc[mt][nt], ah[mt], bh[2 * sub], bh[2 * sub + 1]);
                        mma16816_(acc[mt][nt], ah[mt], bl[2 * sub], bl[2 * sub + 1]);
                    }
                }
            }
        }
    }
    __syncthreads();

    // epilogue 1: Xcat slice (rows z*N+m, ld XLD_), single fp16
#pragma unroll
    for (int mt = 0; mt < 2; mt++) {
        const size_t r0 = (size_t)z * N_ + m0 + m_off + mt * 16 + (lid >> 2);
        __half* x0 = X + r0 * XLD_;
        __half* x1 = X + (r0 + 8) * XLD_;
#pragma unroll
        for (int nt = 0; nt < 8; nt++) {
            const int cc = n_off + nt * 8 + (lid & 3) * 2;
            *(__half2*)(x0 + cc) = __floats2half2_rn(acc[mt][nt][0], acc[mt][nt][1]);
            *(__half2*)(x1 + cc) = __floats2half2_rn(acc[mt][nt][2], acc[mt][nt][3]);
        }
    }

    // epilogue 2: transposed Ht split emission via smem
    if (EMIT_HT) {
        float* ts = (float*)smem;    // [128][132]
#pragma unroll
        for (int mt = 0; mt < 2; mt++) {
            const int mr = m_off + mt * 16 + (lid >> 2);
#pragma unroll
            for (int nt = 0; nt < 8; nt++) {
                const int cc = n_off + nt * 8 + (lid & 3) * 2;
                ts[mr * 132 + cc]           = acc[mt][nt][0];
                ts[mr * 132 + cc + 1]       = acc[mt][nt][1];
                ts[(mr + 8) * 132 + cc]     = acc[mt][nt][2];
                ts[(mr + 8) * 132 + cc + 1] = acc[mt][nt][3];
            }
        }
        __syncthreads();
        const int d = tid >> 1;
        const int mh = (tid & 1) * 64;
        const size_t hb = (size_t)z * D_ * N_ + (size_t)d * N_ + m0 + mh;
#pragma unroll
        for (int mi = 0; mi < 32; mi++) {
            float v0 = ts[(mh + mi * 2) * 132 + d];
            float v1 = ts[(mh + mi * 2 + 1) * 132 + d];
            splith2_(v0, v1, Hohi + hb + mi * 2, Holo + hb + mi * 2);
        }
    }
}

// ---------------- rows GEMM: C = act( X·Wt + bias ) ----------
// X [M][K] single fp16 (row stride lda), Wt [N][K] split fp16. ACT: 0 none,1 softplus,2 tanh.
template <int ACT, bool BIAS>
__global__ void __launch_bounds__(256, 2)
gemm_rows_hmma(const __half* __restrict__ X,
               const __half* __restrict__ Whi, const __half* __restrict__ Wlo,
               const float* __restrict__ bias, float* __restrict__ C,
               int K, int lda, int ldb, int ldc)
{
    extern __shared__ char smem[];
    const uint32_t sbase = smem_u32_(smem);
    const int j0  = blockIdx.x * 128;
    const int r0  = blockIdx.y * 128;
    const int tid = threadIdx.x;
    const int wid = tid >> 5, lid = tid & 31;
    const int wm = wid & 3, wn = wid >> 2;
    const int m_off = wm * 32, n_off = wn * 64;

    const __half* gp[3] = {
        X + (size_t)r0 * lda,
        Whi + (size_t)j0 * ldb, Wlo + (size_t)j0 * ldb };

    auto load_stage = [&](int buf, int k0) {
        uint32_t base = sbase + buf * STAGEB_;
#pragma unroll
        for (int i = 0; i < 6; i++) {
            int idx = i * 256 + tid;
            int tile = idx >> 9;
            int rem = idx & 511;
            int r = rem >> 2, c = rem & 3;
            int ld = (tile == 0) ? lda : ldb;
            uint32_t dst = base + tile * TILEB_ + r * STRD_ + c * 16;
            const void* src = gp[tile] + (size_t)r * ld + k0 + c * 8;
            asm volatile("cp.async.cg.shared.global [%0], [%1], 16;" :: "r"(dst), "l"(src));
        }
        asm volatile("cp.async.commit_group;" ::: "memory");
    };

    float acc[2][8][4];
#pragma unroll
    for (int mt = 0; mt < 2; mt++)
#pragma unroll
        for (int nt = 0; nt < 8; nt++)
#pragma unroll
            for (int q = 0; q < 4; q++) acc[mt][nt][q] = 0.f;

    const int a_row = m_off + (lid & 15);
    const int a_kc  = (lid >> 4) << 3;
    const int b_row = n_off + ((lid >> 4) << 3) + (lid & 7);
    const int b_kc  = ((lid >> 3) & 1) << 3;

    const int NT = K >> 5;
    load_stage(0, 0);
    load_stage(1, 32);
    for (int kt = 0; kt < NT; kt++) {
        if (kt + 1 < NT) asm volatile("cp.async.wait_group 1;" ::: "memory");
        else             asm volatile("cp.async.wait_group 0;" ::: "memory");
        __syncthreads();
        if (kt + 2 < NT) load_stage((kt + 2) % NSTG_, (kt + 2) * 32);

        const uint32_t stg = sbase + (kt % NSTG_) * STAGEB_;
        const uint32_t bA = stg, bBH = stg + TILEB_, bBL = stg + 2 * TILEB_;
#pragma unroll
        for (int k16 = 0; k16 < 2; k16++) {
            const int kb = k16 * 16;
            uint32_t ah[2][4];
#pragma unroll
            for (int mt = 0; mt < 2; mt++)
                ldsm4_(ah[mt], bA + (uint32_t)((a_row + mt * 16) * STRD_ + (kb + a_kc) * 2));
#pragma unroll
            for (int pt = 0; pt < 4; pt++) {
                uint32_t bo = (uint32_t)((b_row + pt * 16) * STRD_ + (kb + b_kc) * 2);
                uint32_t bh[4], bl[4];
                ldsm4_(bh, bBH + bo);
                ldsm4_(bl, bBL + bo);
#pragma unroll
                for (int mt = 0; mt < 2; mt++) {
#pragma unroll
                    for (int sub = 0; sub < 2; sub++) {
                        const int nt = pt * 2 + sub;
                        mma16816_(acc[mt][nt], ah[mt], bh[2 * sub], bh[2 * sub + 1]);
                        mma16816_(acc[mt][nt], ah[mt], bl[2 * sub], bl[2 * sub + 1]);
                    }
                }
            }
        }
    }

    auto ep = [&](float v, float b) -> float {
        if (BIAS) v += b;
        if (ACT == 1) v = softplusf_(v);
        else if (ACT == 2) v = tanhf(v);
        return v;
    };
#pragma unroll
    for (int mt = 0; mt < 2; mt++) {
        const int r = r0 + m_off + mt * 16 + (lid >> 2);
        float* c0 = C + (size_t)r * ldc + j0;
        float* c1 = C + (size_t)(r + 8) * ldc + j0;
#pragma unroll
        for (int nt = 0; nt < 8; nt++) {
            const int cc = n_off + nt * 8 + (lid & 3) * 2;
            float b0 = 0.f, b1 = 0.f;
            if (BIAS) { b0 = bias[j0 + cc]; b1 = bias[j0 + cc + 1]; }
            *(float2*)(c0 + cc) = make_float2(ep(acc[mt][nt][0], b0), ep(acc[mt][nt][1], b1));
            *(float2*)(c1 + cc) = make_float2(ep(acc[mt][nt][2], b0), ep(acc[mt][nt][3], b1));
        }
    }
}

// ---------------- causal depthwise conv (K=4) + SiLU ------
__global__ void conv_silu_kernel(const float* __restrict__ pr, const float* __restrict__ cw,
                                 const float* __restrict__ cb, float* __restrict__ sig,
                                 __half* __restrict__ x)
{
    int idx = blockIdx.x * blockDim.x + threadIdx.x;
    int c = idx & (INNER_ - 1);
    int bn = idx >> 8;
    float w0 = cw[c * 4 + 0], w1 = cw[c * 4 + 1], w2 = cw[c * 4 + 2], w3 = cw[c * 4 + 3];
    float b = cb[c];
    float s[T_];
    size_t base = (size_t)bn * T_ * 512 + c;
#pragma unroll
    for (int t = 0; t < T_; t++) s[t] = pr[base + (size_t)t * 512];
    size_t ob = (size_t)bn * T_ * INNER_ + c;
    size_t ox = (size_t)bn * T_ * XLD_ + c;
#pragma unroll
    for (int t = 0; t < T_; t++) {
        float a = b + w3 * s[t];
        if (t >= 1) a += w2 * s[t - 1];
        if (t >= 2) a += w1 * s[t - 2];
        if (t >= 3) a += w0 * s[t - 3];
        float v = a * sigmoidf_(a);
        sig[ob + (size_t)t * INNER_] = v;
        x[ox + (size_t)t * XLD_] = __float2half_rn(v);
    }
}

// ---------------- selective-scan + gating; y -> Xcat cols 0..255 ----------
__global__ void scan_kernel(const float* __restrict__ sig, const float* __restrict__ si,
                            const float* __restrict__ so, const float* __restrict__ pr,
                            const float* __restrict__ a_log, const float* __restrict__ d_skip,
                            __half* __restrict__ y)
{
    int idx = blockIdx.x * blockDim.x + threadIdx.x;
    int c = idx & (INNER_ - 1);
    int bn = idx >> 8;
    float a = -softplusf_(a_log[c]);
    float dsk = d_skip[c];
    float state = 0.f;
    size_t b256 = (size_t)bn * T_ * INNER_ + c;
    size_t b512 = (size_t)bn * T_ * 512 + c;
    size_t bx   = (size_t)bn * T_ * XLD_ + c;
#pragma unroll
    for (int t = 0; t < T_; t++) {
        float x  = sig[b256 + (size_t)t * INNER_];
        float d  = pr [b512 + (size_t)t * 512];            // delta (cols 0..255)
        float iv = si [b256 + (size_t)t * INNER_];
        float ov = so [b256 + (size_t)t * INNER_];
        float g  = pr [b512 + (size_t)t * 512 + INNER_];   // gate (cols 256..511)
        state = expf(d * a) * state + iv * x;
        float yy = (ov * state + dsk * x) * sigmoidf_(g);
        y[bx + (size_t)t * XLD_] = __float2half_rn(yy);
    }
}

// ---------------- fusion + LayerNorm; also emits Xcat h slice -----------------
__global__ void fuse_ln_kernel(const float* __restrict__ h_in, const float* __restrict__ sp_pre,
                               const float* __restrict__ gcn_b, const float* __restrict__ tp,
                               const float* __restrict__ ln_g, const float* __restrict__ ln_b,
                               float* __restrict__ h_out, __half* __restrict__ xo)
{
    int token = blockIdx.x;
    int d = threadIdx.x;
    int n  = token % N_;
    int bt = token / N_;
    int t  = bt % T_;
    int b  = bt / T_;
    size_t row    = (size_t)token * D_;
    size_t row_tp = ((size_t)(b * N_ + n) * T_ + t) * D_;

    float hv = h_in[row + d];
    float s = sp_pre[row + d] + gcn_b[d];
    s = geluf_(s);
    float tv = tp[row_tp + d];
    float f = hv + s + tv + s * tv;

    __shared__ float red[8];
    float v = f;
#pragma unroll
    for (int o = 16; o > 0; o >>= 1) v += __shfl_xor_sync(0xffffffffu, v, o);
    if ((d & 31) == 0) red[d >> 5] = v;
    __syncthreads();
    float mu = (red[0] + red[1] + red[2] + red[3]) * (1.f / 128.f);
    float dv = f - mu;
    v = dv * dv;
#pragma unroll
    for (int o = 16; o > 0; o >>= 1) v += __shfl_xor_sync(0xffffffffu, v, o);
    if ((d & 31) == 0) red[4 + (d >> 5)] = v;
    __syncthreads();
    float var = (red[4] + red[5] + red[6] + red[7]) * (1.f / 128.f);
    float out = dv * rsqrtf(var + 1e-5f) * ln_g[d] + ln_b[d];
    h_out[row + d] = out;
    xo[(size_t)token * XLD_ + d] = __float2half_rn(out);
}

// ---------------- host launcher ----------------
extern "C" void kernel_launch(void* const* d_in, const int* in_sizes, int n_in,
                              void* d_out, int out_size)
{
    (void)in_sizes; (void)n_in; (void)out_size;
    const float* inputs   = (const float*)d_in[0];
    const float* supports = (const float*)d_in[1];
    const float* gcn_w    = (const float*)d_in[2];
    const float* gcn_b    = (const float*)d_in[3];
    const float* in_w     = (const float*)d_in[4];
    const float* in_b     = (const float*)d_in[5];
    const float* conv_w   = (const float*)d_in[6];
    const float* conv_b   = (const float*)d_in[7];
    const float* delta_w  = (const float*)d_in[8];
    const float* delta_b  = (const float*)d_in[9];
    const float* si_w     = (const float*)d_in[10];
    const float* si_b     = (const float*)d_in[11];
    const float* so_w     = (const float*)d_in[12];
    const float* so_b     = (const float*)d_in[13];
    const float* a_log    = (const float*)d_in[14];
    const float* d_skip   = (const float*)d_in[15];
    const float* out_w    = (const float*)d_in[16];
    const float* out_b    = (const float*)d_in[17];
    const float* ln_g     = (const float*)d_in[18];
    const float* ln_b     = (const float*)d_in[19];

    float *sp, *h2, *tp, *pr, *sig, *si, *so;
    __half *St, *X, *Wthi, *Wtlo, *Ht0hi, *Ht0lo, *Ht1hi, *Ht1lo;
    cudaGetSymbolAddress((void**)&sp,   g_sp);
    cudaGetSymbolAddress((void**)&h2,   g_h2);
    cudaGetSymbolAddress((void**)&tp,   g_tp);
    cudaGetSymbolAddress((void**)&pr,   g_pr);
    cudaGetSymbolAddress((void**)&sig,  g_sig);
    cudaGetSymbolAddress((void**)&si,   g_si);
    cudaGetSymbolAddress((void**)&so,   g_so);
    cudaGetSymbolAddress((void**)&St,   g_St);
    cudaGetSymbolAddress((void**)&X,    g_X);
    cudaGetSymbolAddress((void**)&Wthi, g_Wthi);
    cudaGetSymbolAddress((void**)&Wtlo, g_Wtlo);
    cudaGetSymbolAddress((void**)&Ht0hi, g_Ht0hi);
    cudaGetSymbolAddress((void**)&Ht0lo, g_Ht0lo);
    cudaGetSymbolAddress((void**)&Ht1hi, g_Ht1hi);
    cudaGetSymbolAddress((void**)&Ht1lo, g_Ht1lo);

    cudaFuncSetAttribute(gemm_support_mma<true >, cudaFuncAttributeMaxDynamicSharedMemorySize, SMEM_MMA);
    cudaFuncSetAttribute(gemm_support_mma<false>, cudaFuncAttributeMaxDynamicSharedMemorySize, SMEM_MMA);
    cudaFuncSetAttribute(gemm_rows_hmma<0,false>, cudaFuncAttributeMaxDynamicSharedMemorySize, SMEM_MMA);
    cudaFuncSetAttribute(gemm_rows_hmma<0,true >, cudaFuncAttributeMaxDynamicSharedMemorySize, SMEM_MMA);
    cudaFuncSetAttribute(gemm_rows_hmma<1,true >, cudaFuncAttributeMaxDynamicSharedMemorySize, SMEM_MMA);
    cudaFuncSetAttribute(gemm_rows_hmma<2,true >, cudaFuncAttributeMaxDynamicSharedMemorySize, SMEM_MMA);

    const dim3 blk(256);
    const dim3 gmma(16, BT_);
    const dim3 gcvH(64, 4, BT_);
    const dim3 gr1(1, ROWS_ / 128);
    const dim3 gr2(2, ROWS_ / 128);
    const dim3 gr4(4, ROWS_ / 128);
    const int ew_blocks = (BN_ * INNER_) / 256;

    convt_S<<<dim3(64, 64, 2), blk>>>(supports, St);
    for (int l = 0; l < 2; l++) {
        __half* wh = Wthi + (size_t)l * WSZ_L;
        __half* wl = Wtlo + (size_t)l * WSZ_L;
        convt_W<<<dim3(20, 4), blk>>>(gcn_w  + (size_t)l * 640 * 128, 640, 128, wh + WOFF_GCN, wl + WOFF_GCN);
        convt_W<<<dim3(4, 16), blk>>>(in_w   + (size_t)l * 128 * 512, 128, 512, wh + WOFF_IN,  wl + WOFF_IN);
        convt_W<<<dim3(8, 8),  blk>>>(delta_w + (size_t)l * 256 * 256, 256, 256, wh + WOFF_DL,  wl + WOFF_DL);
        convt_W<<<dim3(8, 8),  blk>>>(si_w    + (size_t)l * 256 * 256, 256, 256, wh + WOFF_SI,  wl + WOFF_SI);
        convt_W<<<dim3(8, 8),  blk>>>(so_w    + (size_t)l * 256 * 256, 256, 256, wh + WOFF_SO,  wl + WOFF_SO);
        convt_W<<<dim3(8, 4),  blk>>>(out_w   + (size_t)l * 256 * 128, 256, 128, wh + WOFF_OUT, wl + WOFF_OUT);
    }
    conv_plain<<<(int)(SZ_H / 512), blk>>>(inputs, X);   // h slice for layer 0

    for (int l = 0; l < 2; l++) {
        const float* h_in  = (l == 0) ? inputs : h2;
        float*       h_out = (l == 0) ? h2 : (float*)d_out;
        const __half* wh = Wthi + (size_t)l * WSZ_L;
        const __half* wl = Wtlo + (size_t)l * WSZ_L;
        const float* gb  = gcn_b  + l * 128;
        const float* ib  = in_b   + l * 512;
        const float* cw  = conv_w + (size_t)l * INNER_ * 4;
        const float* cb  = conv_b + l * INNER_;
        const float* db  = delta_b + l * INNER_;
        const float* sib = si_b + l * INNER_;
        const float* sob = so_b + l * INNER_;
        const float* al  = a_log  + l * INNER_;
        const float* dsk = d_skip + l * INNER_;
        const float* ob  = out_b + l * 128;
        const float* lg  = ln_g + l * 128;
        const float* lb  = ln_b + l * 128;

        // --- spatial branch: 4 einsums fill Xcat slices, then one K=640 GEMM ---
        convt_H<<<gcvH, blk>>>(h_in, Ht0hi, Ht0lo);
        gemm_support_mma<true ><<<gmma, blk, SMEM_MMA>>>(St,       Ht0hi, Ht0lo, X + 128, Ht1hi, Ht1lo); // S0 h
        gemm_support_mma<false><<<gmma, blk, SMEM_MMA>>>(St,       Ht1hi, Ht1lo, X + 256, nullptr, nullptr); // S0^2 h
        gemm_support_mma<true ><<<gmma, blk, SMEM_MMA>>>(St + NN_, Ht0hi, Ht0lo, X + 384, Ht1hi, Ht1lo); // S1 h
        gemm_support_mma<false><<<gmma, blk, SMEM_MMA>>>(St + NN_, Ht1hi, Ht1lo, X + 512, nullptr, nullptr); // S1^2 h
        gemm_rows_hmma<0,false><<<gr1, blk, SMEM_MMA>>>(X, wh + WOFF_GCN, wl + WOFF_GCN, nullptr, sp, 640, XLD_, 640, 128);

        // --- temporal branch ---
        transpose_convert_bt<<<(ROWS_ * 32) / 256, 256>>>(h_in, X);
        gemm_rows_hmma<0,true><<<gr4, blk, SMEM_MMA>>>(X, wh + WOFF_IN, wl + WOFF_IN, ib, pr, 128, XLD_, 128, 512);
        conv_silu_kernel<<<ew_blocks, 256>>>(pr, cw, cb, sig, X);
        gemm_rows_hmma<1,true><<<gr2, blk, SMEM_MMA>>>(X, wh + WOFF_DL, wl + WOFF_DL, db,  pr, 256, XLD_, 256, 512); // delta -> pr cols 0..255
        gemm_rows_hmma<2,true><<<gr2, blk, SMEM_MMA>>>(X, wh + WOFF_SI, wl + WOFF_SI, sib, si, 256, XLD_, 256, 256);
        gemm_rows_hmma<2,true><<<gr2, blk, SMEM_MMA>>>(X, wh + WOFF_SO, wl + WOFF_SO, sob, so, 256, XLD_, 256, 256);
        scan_kernel<<<ew_blocks, 256>>>(sig, si, so, pr, al, dsk, X);
        gemm_rows_hmma<0,true><<<gr1, blk, SMEM_MMA>>>(X, wh + WOFF_OUT, wl + WOFF_OUT, ob, tp, 256, XLD_, 256, 128);

        // --- fusion + layernorm (also emits next layer's h slice into Xcat) ---
        fuse_ln_kernel<<<ROWS_, 128>>>(h_in, sp, gb, tp, lg, lb, h_out, X);
    }
}

// round 8
// speedup vs baseline: 4.3408x; 1.5701x over previous
#include <cuda_runtime.h>
#include <cuda_fp16.h>
#include <math.h>
#include <stdint.h>

// ---------------- problem constants ----------------
#define B_    16
#define T_    12
#define N_    2048
#define D_    128
#define INNER_ 256
#define BT_   (B_*T_)          // 192
#define ROWS_ (B_*T_*N_)       // 393216
#define BN_   (B_*N_)          // 32768
#define NN_   ((size_t)N_*N_)
#define XLD_  640              // Xcat row stride (5*128 feature concat)

// ---------------- scratch (device globals) ----------------
#define SZ_H  ((size_t)ROWS_*D_)
#define SZ_PR ((size_t)ROWS_*512)
#define SZ_I  ((size_t)ROWS_*INNER_)
#define SZ_X  ((size_t)ROWS_*XLD_)
#define SZ_HT ((size_t)BT_*D_*N_)

__device__ __align__(16) float g_sp  [SZ_H];
__device__ __align__(16) float g_h2  [SZ_H];
__device__ __align__(16) float g_tp  [SZ_H];
__device__ __align__(16) float g_pr  [SZ_PR];   // cols 0..255: signal, then delta; 256..511: gate
__device__ __align__(16) float g_sig [SZ_I];
__device__ __align__(16) float g_si  [SZ_I];
__device__ __align__(16) float g_so  [SZ_I];

__device__ __align__(16) __half g_X  [SZ_X];    // concat activations fp16 [M][640]
__device__ __align__(16) __half g_St [2*NN_];   // S^T fp16 [i][m][k]
__device__ __align__(16) __half g_Ht0[SZ_HT];   // Ht(h) fp16 [z][d][k]
__device__ __align__(16) __half g_Ht1[SZ_HT];   // Ht scratch

// transposed weights per layer (fp16)
#define WOFF_GCN 0
#define WOFF_IN  81920
#define WOFF_DL  147456
#define WOFF_SI  212992
#define WOFF_SO  278528
#define WOFF_OUT 344064
#define WSZ_L    376832
__device__ __align__(16) __half g_Wt[2*WSZ_L];

// ---------------- helpers ----------------
__device__ __forceinline__ float sigmoidf_(float x) { return 1.f / (1.f + expf(-x)); }
__device__ __forceinline__ float softplusf_(float x) {
    return fmaxf(x, 0.f) + log1pf(expf(-fabsf(x)));
}
__device__ __forceinline__ float geluf_(float x) {
    return 0.5f * x * (1.f + erff(x * 0.7071067811865475f));
}
__device__ __forceinline__ uint32_t smem_u32_(const void* p) {
    uint32_t a;
    asm("{ .reg .u64 t; cvta.to.shared.u64 t, %1; cvt.u32.u64 %0, t; }" : "=r"(a) : "l"(p));
    return a;
}
__device__ __forceinline__ void ldsm4_(uint32_t* r, uint32_t a) {
    asm volatile("ldmatrix.sync.aligned.m8n8.x4.shared.b16 {%0,%1,%2,%3}, [%4];"
        : "=r"(r[0]), "=r"(r[1]), "=r"(r[2]), "=r"(r[3]) : "r"(a));
}
__device__ __forceinline__ void mma16816_(float* d, const uint32_t* a, uint32_t b0, uint32_t b1) {
    asm volatile(
        "mma.sync.aligned.m16n8k16.row.col.f32.f16.f16.f32 "
        "{%0,%1,%2,%3}, {%4,%5,%6,%7}, {%8,%9}, {%0,%1,%2,%3};"
        : "+f"(d[0]), "+f"(d[1]), "+f"(d[2]), "+f"(d[3])
        : "r"(a[0]), "r"(a[1]), "r"(a[2]), "r"(a[3]), "r"(b0), "r"(b1));
}

// ---------------- conversions ----------------
// St[i][m][k] = S[i][k][m]
__global__ void convt_S(const float* __restrict__ S, __half* __restrict__ out)
{
    __shared__ float t[32][33];
    const int k0 = blockIdx.x * 32, m0 = blockIdx.y * 32, i = blockIdx.z;
    const int tx = threadIdx.x & 31, ty = threadIdx.x >> 5;
    const float* Si = S + (size_t)i * NN_;
    for (int r = ty; r < 32; r += 8)
        t[r][tx] = Si[(size_t)(k0 + r) * N_ + m0 + tx];
    __syncthreads();
    for (int r = ty; r < 32; r += 8) {
        size_t o = (size_t)i * NN_ + (size_t)(m0 + r) * N_ + k0 + tx;
        out[o] = __float2half_rn(t[tx][r]);
    }
}
// Ht[z][d][n] = H[z][n][d]
__global__ void convt_H(const float* __restrict__ H, __half* __restrict__ out)
{
    __shared__ float t[32][33];
    const int n0 = blockIdx.x * 32, d0 = blockIdx.y * 32, z = blockIdx.z;
    const int tx = threadIdx.x & 31, ty = threadIdx.x >> 5;
    const float* Hz = H + (size_t)z * N_ * D_;
    for (int r = ty; r < 32; r += 8)
        t[r][tx] = Hz[(size_t)(n0 + r) * D_ + d0 + tx];
    __syncthreads();
    for (int r = ty; r < 32; r += 8) {
        size_t o = ((size_t)z * D_ + d0 + r) * N_ + n0 + tx;
        out[o] = __float2half_rn(t[tx][r]);
    }
}
// Wt[n][k] = W[k][n]
__global__ void convt_W(const float* __restrict__ W, int K, int N, __half* __restrict__ out)
{
    __shared__ float t[32][33];
    const int k0 = blockIdx.x * 32, n0 = blockIdx.y * 32;
    const int tx = threadIdx.x & 31, ty = threadIdx.x >> 5;
    for (int r = ty; r < 32; r += 8)
        t[r][tx] = W[(size_t)(k0 + r) * N + n0 + tx];
    __syncthreads();
    for (int r = ty; r < 32; r += 8) {
        size_t o = (size_t)(n0 + r) * K + k0 + tx;
        out[o] = __float2half_rn(t[tx][r]);
    }
}
// inputs f32 [M][128] -> Xcat cols 0..127 (ld 640)
__global__ void conv_plain(const float* __restrict__ src, __half* __restrict__ x)
{
    size_t e = ((size_t)blockIdx.x * blockDim.x + threadIdx.x) * 2;
    size_t row = e >> 7;
    int col = (int)(e & 127);
    float2 v = *(const float2*)(src + e);
    *(__half2*)(x + row * XLD_ + col) = __floats2half2_rn(v.x, v.y);
}
// h(b,t,n,d) -> Xcat rows bn*T+t, cols 0..127 (ld 640)
__global__ void transpose_convert_bt(const float* __restrict__ h, __half* __restrict__ x)
{
    size_t gid = (size_t)blockIdx.x * blockDim.x + threadIdx.x;
    int q = (int)(gid & 31);
    int r = (int)(gid >> 5);
    int t = r % T_;
    int bn = r / T_;
    int n = bn % N_;
    int b = bn / N_;
    size_t src = ((size_t)((b * T_ + t) * N_) + n) * D_ + q * 4;
    float4 v = *(const float4*)(h + src);
    size_t o = (size_t)r * XLD_ + q * 4;
    *(__half2*)(x + o)     = __floats2half2_rn(v.x, v.y);
    *(__half2*)(x + o + 2) = __floats2half2_rn(v.z, v.w);
}

// ---------------- HMMA GEMM infrastructure ----------------
// stage: 2 tiles (A, B), each 128 rows x 32 k fp16, row stride 80B
#define STRD_ 80
#define TILEB_ (128 * STRD_)          // 10240
#define STAGEB_ (2 * TILEB_)          // 20480
#define NSTG_ 3
#define SMEM_MMA 67584                // max(3*STAGEB_=61440, transpose 128*132*4)

// ---------------- support einsum: C[m][d] = sum_k St[m][k] * Ht[z][d][k] -------
// Emits Xcat slice (fp16); optionally transposed Ht (fp16).
template <bool EMIT_HT>
__global__ void __launch_bounds__(256, 2)
gemm_support_mma(const __half* __restrict__ A, const __half* __restrict__ Bm,
                 __half* __restrict__ X,          // pre-offset by slot
                 __half* Ho)
{
    extern __shared__ char smem[];
    const uint32_t sbase = smem_u32_(smem);
    const int m0  = blockIdx.x * 128;
    const int z   = blockIdx.y;
    const int tid = threadIdx.x;
    const int wid = tid >> 5, lid = tid & 31;
    const int wm = wid & 3, wn = wid >> 2;
    const int m_off = wm * 32, n_off = wn * 64;

    const __half* gp[2] = { A + (size_t)m0 * N_, Bm + (size_t)z * D_ * N_ };

    auto load_stage = [&](int buf, int k0) {
        uint32_t base = sbase + buf * STAGEB_;
#pragma unroll
        for (int i = 0; i < 4; i++) {
            int idx = i * 256 + tid;          // 0..1023
            int tile = idx >> 9;
            int rem = idx & 511;
            int r = rem >> 2, c = rem & 3;
            uint32_t dst = base + tile * TILEB_ + r * STRD_ + c * 16;
            const void* src = gp[tile] + (size_t)r * N_ + k0 + c * 8;
            asm volatile("cp.async.cg.shared.global [%0], [%1], 16;" :: "r"(dst), "l"(src));
        }
        asm volatile("cp.async.commit_group;" ::: "memory");
    };

    float acc[2][8][4];
#pragma unroll
    for (int mt = 0; mt < 2; mt++)
#pragma unroll
        for (int nt = 0; nt < 8; nt++)
#pragma unroll
            for (int q = 0; q < 4; q++) acc[mt][nt][q] = 0.f;

    const int a_row = m_off + (lid & 15);
    const int a_kc  = (lid >> 4) << 3;
    const int b_row = n_off + ((lid >> 4) << 3) + (lid & 7);
    const int b_kc  = ((lid >> 3) & 1) << 3;

    const int NT = N_ / 32;   // 64
    load_stage(0, 0);
    load_stage(1, 32);
    for (int kt = 0; kt < NT; kt++) {
        if (kt + 1 < NT) asm volatile("cp.async.wait_group 1;" ::: "memory");
        else             asm volatile("cp.async.wait_group 0;" ::: "memory");
        __syncthreads();
        if (kt + 2 < NT) load_stage((kt + 2) % NSTG_, (kt + 2) * 32);

        const uint32_t stg = sbase + (kt % NSTG_) * STAGEB_;
        const uint32_t bA = stg, bB = stg + TILEB_;
#pragma unroll
        for (int k16 = 0; k16 < 2; k16++) {
            const int kb = k16 * 16;
            uint32_t ah[2][4];
#pragma unroll
            for (int mt = 0; mt < 2; mt++)
                ldsm4_(ah[mt], bA + (uint32_t)((a_row + mt * 16) * STRD_ + (kb + a_kc) * 2));
#pragma unroll
            for (int pt = 0; pt < 4; pt++) {
                uint32_t bo = (uint32_t)((b_row + pt * 16) * STRD_ + (kb + b_kc) * 2);
                uint32_t bh[4];
                ldsm4_(bh, bB + bo);
#pragma unroll
                for (int mt = 0; mt < 2; mt++) {
#pragma unroll
                    for (int sub = 0; sub < 2; sub++)
                        mma16816_(acc[mt][pt * 2 + sub], ah[mt], bh[2 * sub], bh[2 * sub + 1]);
                }
            }
        }
    }
    __syncthreads();

    // epilogue 1: Xcat slice (rows z*N+m, ld XLD_)
#pragma unroll
    for (int mt = 0; mt < 2; mt++) {
        const size_t r0 = (size_t)z * N_ + m0 + m_off + mt * 16 + (lid >> 2);
        __half* x0 = X + r0 * XLD_;
        __half* x1 = X + (r0 + 8) * XLD_;
#pragma unroll
        for (int nt = 0; nt < 8; nt++) {
            const int cc = n_off + nt * 8 + (lid & 3) * 2;
            *(__half2*)(x0 + cc) = __floats2half2_rn(acc[mt][nt][0], acc[mt][nt][1]);
            *(__half2*)(x1 + cc) = __floats2half2_rn(acc[mt][nt][2], acc[mt][nt][3]);
        }
    }

    // epilogue 2: transposed Ht emission via smem
    if (EMIT_HT) {
        float* ts = (float*)smem;    // [128][132]
#pragma unroll
        for (int mt = 0; mt < 2; mt++) {
            const int mr = m_off + mt * 16 + (lid >> 2);
#pragma unroll
            for (int nt = 0; nt < 8; nt++) {
                const int cc = n_off + nt * 8 + (lid & 3) * 2;
                ts[mr * 132 + cc]           = acc[mt][nt][0];
                ts[mr * 132 + cc + 1]       = acc[mt][nt][1];
                ts[(mr + 8) * 132 + cc]     = acc[mt][nt][2];
                ts[(mr + 8) * 132 + cc + 1] = acc[mt][nt][3];
            }
        }
        __syncthreads();
        const int d = tid >> 1;
        const int mh = (tid & 1) * 64;
        const size_t hb = (size_t)z * D_ * N_ + (size_t)d * N_ + m0 + mh;
#pragma unroll
        for (int mi = 0; mi < 32; mi++) {
            float v0 = ts[(mh + mi * 2) * 132 + d];
            float v1 = ts[(mh + mi * 2 + 1) * 132 + d];
            *(__half2*)(Ho + hb + mi * 2) = __floats2half2_rn(v0, v1);
        }
    }
}

// ---------------- rows GEMM: C = act( X·Wt + bias ) ----------
// X [M][K] fp16 (row stride lda), Wt [N][K] fp16. ACT: 0 none,1 softplus,2 tanh.
template <int ACT, bool BIAS>
__global__ void __launch_bounds__(256, 2)
gemm_rows_hmma(const __half* __restrict__ X, const __half* __restrict__ W,
               const float* __restrict__ bias, float* __restrict__ C,
               int K, int lda, int ldb, int ldc)
{
    extern __shared__ char smem[];
    const uint32_t sbase = smem_u32_(smem);
    const int j0  = blockIdx.x * 128;
    const int r0  = blockIdx.y * 128;
    const int tid = threadIdx.x;
    const int wid = tid >> 5, lid = tid & 31;
    const int wm = wid & 3, wn = wid >> 2;
    const int m_off = wm * 32, n_off = wn * 64;

    const __half* gp[2] = { X + (size_t)r0 * lda, W + (size_t)j0 * ldb };

    auto load_stage = [&](int buf, int k0) {
        uint32_t base = sbase + buf * STAGEB_;
#pragma unroll
        for (int i = 0; i < 4; i++) {
            int idx = i * 256 + tid;
            int tile = idx >> 9;
            int rem = idx & 511;
            int r = rem >> 2, c = rem & 3;
            int ld = (tile == 0) ? lda : ldb;
            uint32_t dst = base + tile * TILEB_ + r * STRD_ + c * 16;
            const void* src = gp[tile] + (size_t)r * ld + k0 + c * 8;
            asm volatile("cp.async.cg.shared.global [%0], [%1], 16;" :: "r"(dst), "l"(src));
        }
        asm volatile("cp.async.commit_group;" ::: "memory");
    };

    float acc[2][8][4];
#pragma unroll
    for (int mt = 0; mt < 2; mt++)
#pragma unroll
        for (int nt = 0; nt < 8; nt++)
#pragma unroll
            for (int q = 0; q < 4; q++) acc[mt][nt][q] = 0.f;

    const int a_row = m_off + (lid & 15);
    const int a_kc  = (lid >> 4) << 3;
    const int b_row = n_off + ((lid >> 4) << 3) + (lid & 7);
    const int b_kc  = ((lid >> 3) & 1) << 3;

    const int NT = K >> 5;
    load_stage(0, 0);
    load_stage(1, 32);
    for (int kt = 0; kt < NT; kt++) {
        if (kt + 1 < NT) asm volatile("cp.async.wait_group 1;" ::: "memory");
        else             asm volatile("cp.async.wait_group 0;" ::: "memory");
        __syncthreads();
        if (kt + 2 < NT) load_stage((kt + 2) % NSTG_, (kt + 2) * 32);

        const uint32_t stg = sbase + (kt % NSTG_) * STAGEB_;
        const uint32_t bA = stg, bB = stg + TILEB_;
#pragma unroll
        for (int k16 = 0; k16 < 2; k16++) {
            const int kb = k16 * 16;
            uint32_t ah[2][4];
#pragma unroll
            for (int mt = 0; mt < 2; mt++)
                ldsm4_(ah[mt], bA + (uint32_t)((a_row + mt * 16) * STRD_ + (kb + a_kc) * 2));
#pragma unroll
            for (int pt = 0; pt < 4; pt++) {
                uint32_t bo = (uint32_t)((b_row + pt * 16) * STRD_ + (kb + b_kc) * 2);
                uint32_t bh[4];
                ldsm4_(bh, bB + bo);
#pragma unroll
                for (int mt = 0; mt < 2; mt++) {
#pragma unroll
                    for (int sub = 0; sub < 2; sub++)
                        mma16816_(acc[mt][pt * 2 + sub], ah[mt], bh[2 * sub], bh[2 * sub + 1]);
                }
            }
        }
    }

    auto ep = [&](float v, float b) -> float {
        if (BIAS) v += b;
        if (ACT == 1) v = softplusf_(v);
        else if (ACT == 2) v = tanhf(v);
        return v;
    };
#pragma unroll
    for (int mt = 0; mt < 2; mt++) {
        const int r = r0 + m_off + mt * 16 + (lid >> 2);
        float* c0 = C + (size_t)r * ldc + j0;
        float* c1 = C + (size_t)(r + 8) * ldc + j0;
#pragma unroll
        for (int nt = 0; nt < 8; nt++) {
            const int cc = n_off + nt * 8 + (lid & 3) * 2;
            float b0 = 0.f, b1 = 0.f;
            if (BIAS) { b0 = bias[j0 + cc]; b1 = bias[j0 + cc + 1]; }
            *(float2*)(c0 + cc) = make_float2(ep(acc[mt][nt][0], b0), ep(acc[mt][nt][1], b1));
            *(float2*)(c1 + cc) = make_float2(ep(acc[mt][nt][2], b0), ep(acc[mt][nt][3], b1));
        }
    }
}

// ---------------- causal depthwise conv (K=4) + SiLU ------
__global__ void conv_silu_kernel(const float* __restrict__ pr, const float* __restrict__ cw,
                                 const float* __restrict__ cb, float* __restrict__ sig,
                                 __half* __restrict__ x)
{
    int idx = blockIdx.x * blockDim.x + threadIdx.x;
    int c = idx & (INNER_ - 1);
    int bn = idx >> 8;
    float w0 = cw[c * 4 + 0], w1 = cw[c * 4 + 1], w2 = cw[c * 4 + 2], w3 = cw[c * 4 + 3];
    float b = cb[c];
    float s[T_];
    size_t base = (size_t)bn * T_ * 512 + c;
#pragma unroll
    for (int t = 0; t < T_; t++) s[t] = pr[base + (size_t)t * 512];
    size_t ob = (size_t)bn * T_ * INNER_ + c;
    size_t ox = (size_t)bn * T_ * XLD_ + c;
#pragma unroll
    for (int t = 0; t < T_; t++) {
        float a = b + w3 * s[t];
        if (t >= 1) a += w2 * s[t - 1];
        if (t >= 2) a += w1 * s[t - 2];
        if (t >= 3) a += w0 * s[t - 3];
        float v = a * sigmoidf_(a);
        sig[ob + (size_t)t * INNER_] = v;
        x[ox + (size_t)t * XLD_] = __float2half_rn(v);
    }
}

// ---------------- selective-scan + gating; y -> Xcat cols 0..255 ----------
__global__ void scan_kernel(const float* __restrict__ sig, const float* __restrict__ si,
                            const float* __restrict__ so, const float* __restrict__ pr,
                            const float* __restrict__ a_log, const float* __restrict__ d_skip,
                            __half* __restrict__ y)
{
    int idx = blockIdx.x * blockDim.x + threadIdx.x;
    int c = idx & (INNER_ - 1);
    int bn = idx >> 8;
    float a = -softplusf_(a_log[c]);
    float dsk = d_skip[c];
    float state = 0.f;
    size_t b256 = (size_t)bn * T_ * INNER_ + c;
    size_t b512 = (size_t)bn * T_ * 512 + c;
    size_t bx   = (size_t)bn * T_ * XLD_ + c;
#pragma unroll
    for (int t = 0; t < T_; t++) {
        float x  = sig[b256 + (size_t)t * INNER_];
        float d  = pr [b512 + (size_t)t * 512];            // delta (cols 0..255)
        float iv = si [b256 + (size_t)t * INNER_];
        float ov = so [b256 + (size_t)t * INNER_];
        float g  = pr [b512 + (size_t)t * 512 + INNER_];   // gate (cols 256..511)
        state = expf(d * a) * state + iv * x;
        float yy = (ov * state + dsk * x) * sigmoidf_(g);
        y[bx + (size_t)t * XLD_] = __float2half_rn(yy);
    }
}

// ---------------- fusion + LayerNorm; also emits Xcat h slice -----------------
__global__ void fuse_ln_kernel(const float* __restrict__ h_in, const float* __restrict__ sp_pre,
                               const float* __restrict__ gcn_b, const float* __restrict__ tp,
                               const float* __restrict__ ln_g, const float* __restrict__ ln_b,
                               float* __restrict__ h_out, __half* __restrict__ xo)
{
    int token = blockIdx.x;
    int d = threadIdx.x;
    int n  = token % N_;
    int bt = token / N_;
    int t  = bt % T_;
    int b  = bt / T_;
    size_t row    = (size_t)token * D_;
    size_t row_tp = ((size_t)(b * N_ + n) * T_ + t) * D_;

    float hv = h_in[row + d];
    float s = sp_pre[row + d] + gcn_b[d];
    s = geluf_(s);
    float tv = tp[row_tp + d];
    float f = hv + s + tv + s * tv;

    __shared__ float red[8];
    float v = f;
#pragma unroll
    for (int o = 16; o > 0; o >>= 1) v += __shfl_xor_sync(0xffffffffu, v, o);
    if ((d & 31) == 0) red[d >> 5] = v;
    __syncthreads();
    float mu = (red[0] + red[1] + red[2] + red[3]) * (1.f / 128.f);
    float dv = f - mu;
    v = dv * dv;
#pragma unroll
    for (int o = 16; o > 0; o >>= 1) v += __shfl_xor_sync(0xffffffffu, v, o);
    if ((d & 31) == 0) red[4 + (d >> 5)] = v;
    __syncthreads();
    float var = (red[4] + red[5] + red[6] + red[7]) * (1.f / 128.f);
    float out = dv * rsqrtf(var + 1e-5f) * ln_g[d] + ln_b[d];
    h_out[row + d] = out;
    xo[(size_t)token * XLD_ + d] = __float2half_rn(out);
}

// ---------------- host launcher ----------------
extern "C" void kernel_launch(void* const* d_in, const int* in_sizes, int n_in,
                              void* d_out, int out_size)
{
    (void)in_sizes; (void)n_in; (void)out_size;
    const float* inputs   = (const float*)d_in[0];
    const float* supports = (const float*)d_in[1];
    const float* gcn_w    = (const float*)d_in[2];
    const float* gcn_b    = (const float*)d_in[3];
    const float* in_w     = (const float*)d_in[4];
    const float* in_b     = (const float*)d_in[5];
    const float* conv_w   = (const float*)d_in[6];
    const float* conv_b   = (const float*)d_in[7];
    const float* delta_w  = (const float*)d_in[8];
    const float* delta_b  = (const float*)d_in[9];
    const float* si_w     = (const float*)d_in[10];
    const float* si_b     = (const float*)d_in[11];
    const float* so_w     = (const float*)d_in[12];
    const float* so_b     = (const float*)d_in[13];
    const float* a_log    = (const float*)d_in[14];
    const float* d_skip   = (const float*)d_in[15];
    const float* out_w    = (const float*)d_in[16];
    const float* out_b    = (const float*)d_in[17];
    const float* ln_g     = (const float*)d_in[18];
    const float* ln_b     = (const float*)d_in[19];

    float *sp, *h2, *tp, *pr, *sig, *si, *so;
    __half *St, *X, *Wt, *Ht0, *Ht1;
    cudaGetSymbolAddress((void**)&sp,   g_sp);
    cudaGetSymbolAddress((void**)&h2,   g_h2);
    cudaGetSymbolAddress((void**)&tp,   g_tp);
    cudaGetSymbolAddress((void**)&pr,   g_pr);
    cudaGetSymbolAddress((void**)&sig,  g_sig);
    cudaGetSymbolAddress((void**)&si,   g_si);
    cudaGetSymbolAddress((void**)&so,   g_so);
    cudaGetSymbolAddress((void**)&St,   g_St);
    cudaGetSymbolAddress((void**)&X,    g_X);
    cudaGetSymbolAddress((void**)&Wt,   g_Wt);
    cudaGetSymbolAddress((void**)&Ht0,  g_Ht0);
    cudaGetSymbolAddress((void**)&Ht1,  g_Ht1);

    cudaFuncSetAttribute(gemm_support_mma<true >, cudaFuncAttributeMaxDynamicSharedMemorySize, SMEM_MMA);
    cudaFuncSetAttribute(gemm_support_mma<false>, cudaFuncAttributeMaxDynamicSharedMemorySize, SMEM_MMA);
    cudaFuncSetAttribute(gemm_rows_hmma<0,false>, cudaFuncAttributeMaxDynamicSharedMemorySize, SMEM_MMA);
    cudaFuncSetAttribute(gemm_rows_hmma<0,true >, cudaFuncAttributeMaxDynamicSharedMemorySize, SMEM_MMA);
    cudaFuncSetAttribute(gemm_rows_hmma<1,true >, cudaFuncAttributeMaxDynamicSharedMemorySize, SMEM_MMA);
    cudaFuncSetAttribute(gemm_rows_hmma<2,true >, cudaFuncAttributeMaxDynamicSharedMemorySize, SMEM_MMA);

    const dim3 blk(256);
    const dim3 gmma(16, BT_);
    const dim3 gcvH(64, 4, BT_);
    const dim3 gr1(1, ROWS_ / 128);
    const dim3 gr2(2, ROWS_ / 128);
    const dim3 gr4(4, ROWS_ / 128);
    const int ew_blocks = (BN_ * INNER_) / 256;

    convt_S<<<dim3(64, 64, 2), blk>>>(supports, St);
    for (int l = 0; l < 2; l++) {
        __half* w = Wt + (size_t)l * WSZ_L;
        convt_W<<<dim3(20, 4), blk>>>(gcn_w  + (size_t)l * 640 * 128, 640, 128, w + WOFF_GCN);
        convt_W<<<dim3(4, 16), blk>>>(in_w   + (size_t)l * 128 * 512, 128, 512, w + WOFF_IN);
        convt_W<<<dim3(8, 8),  blk>>>(delta_w + (size_t)l * 256 * 256, 256, 256, w + WOFF_DL);
        convt_W<<<dim3(8, 8),  blk>>>(si_w    + (size_t)l * 256 * 256, 256, 256, w + WOFF_SI);
        convt_W<<<dim3(8, 8),  blk>>>(so_w    + (size_t)l * 256 * 256, 256, 256, w + WOFF_SO);
        convt_W<<<dim3(8, 4),  blk>>>(out_w   + (size_t)l * 256 * 128, 256, 128, w + WOFF_OUT);
    }
    conv_plain<<<(int)(SZ_H / 512), blk>>>(inputs, X);   // h slice for layer 0

    for (int l = 0; l < 2; l++) {
        const float* h_in  = (l == 0) ? inputs : h2;
        float*       h_out = (l == 0) ? h2 : (float*)d_out;
        const __half* w = Wt + (size_t)l * WSZ_L;
        const float* gb  = gcn_b  + l * 128;
        const float* ib  = in_b   + l * 512;
        const float* cw  = conv_w + (size_t)l * INNER_ * 4;
        const float* cb  = conv_b + l * INNER_;
        const float* db  = delta_b + l * INNER_;
        const float* sib = si_b + l * INNER_;
        const float* sob = so_b + l * INNER_;
        const float* al  = a_log  + l * INNER_;
        const float* dsk = d_skip + l * INNER_;
        const float* ob  = out_b + l * 128;
        const float* lg  = ln_g + l * 128;
        const float* lb  = ln_b + l * 128;

        // --- spatial branch: 4 einsums fill Xcat slices, then one K=640 GEMM ---
        convt_H<<<gcvH, blk>>>(h_in, Ht0);
        gemm_support_mma<true ><<<gmma, blk, SMEM_MMA>>>(St,       Ht0, X + 128, Ht1); // S0 h
        gemm_support_mma<false><<<gmma, blk, SMEM_MMA>>>(St,       Ht1, X + 256, nullptr); // S0^2 h
        gemm_support_mma<true ><<<gmma, blk, SMEM_MMA>>>(St + NN_, Ht0, X + 384, Ht1); // S1 h
        gemm_support_mma<false><<<gmma, blk, SMEM_MMA>>>(St + NN_, Ht1, X + 512, nullptr); // S1^2 h
        gemm_rows_hmma<0,false><<<gr1, blk, SMEM_MMA>>>(X, w + WOFF_GCN, nullptr, sp, 640, XLD_, 640, 128);

        // --- temporal branch ---
        transpose_convert_bt<<<(ROWS_ * 32) / 256, 256>>>(h_in, X);
        gemm_rows_hmma<0,true><<<gr4, blk, SMEM_MMA>>>(X, w + WOFF_IN, ib, pr, 128, XLD_, 128, 512);
        conv_silu_kernel<<<ew_blocks, 256>>>(pr, cw, cb, sig, X);
        gemm_rows_hmma<1,true><<<gr2, blk, SMEM_MMA>>>(X, w + WOFF_DL, db,  pr, 256, XLD_, 256, 512); // delta -> pr cols 0..255
        gemm_rows_hmma<2,true><<<gr2, blk, SMEM_MMA>>>(X, w + WOFF_SI, sib, si, 256, XLD_, 256, 256);
        gemm_rows_hmma<2,true><<<gr2, blk, SMEM_MMA>>>(X, w + WOFF_SO, sob, so, 256, XLD_, 256, 256);
        scan_kernel<<<ew_blocks, 256>>>(sig, si, so, pr, al, dsk, X);
        gemm_rows_hmma<0,true><<<gr1, blk, SMEM_MMA>>>(X, w + WOFF_OUT, ob, tp, 256, XLD_, 256, 128);

        // --- fusion + layernorm (also emits next layer's h slice into Xcat) ---
        fuse_ln_kernel<<<ROWS_, 128>>>(h_in, sp, gb, tp, lg, lb, h_out, X);
    }
}

// round 9
// speedup vs baseline: 4.3590x; 1.0042x over previous
#include <cuda_runtime.h>
#include <cuda_fp16.h>
#include <math.h>
#include <stdint.h>

// ---------------- problem constants ----------------
#define B_    16
#define T_    12
#define N_    2048
#define D_    128
#define INNER_ 256
#define BT_   (B_*T_)          // 192
#define ROWS_ (B_*T_*N_)       // 393216
#define BN_   (B_*N_)          // 32768
#define NN_   ((size_t)N_*N_)
#define XLD_  640              // Xcat row stride (5*128 feature concat)

// ---------------- scratch (device globals; ~2.3 GiB) ----------------
#define SZ_H  ((size_t)ROWS_*D_)
#define SZ_PR ((size_t)ROWS_*512)
#define SZ_DSO ((size_t)ROWS_*768)
#define SZ_X  ((size_t)ROWS_*XLD_)
#define SZ_HT ((size_t)BT_*D_*N_)

__device__ __align__(16) float g_sp  [SZ_H];
__device__ __align__(16) float g_h2  [SZ_H];
__device__ __align__(16) float g_tp  [SZ_H];
__device__ __align__(16) float g_bcat[2*768];

__device__ __align__(16) __half g_pr [SZ_PR];   // fp16: cols 0..255 signal, 256..511 gate
__device__ __align__(16) __half g_dso[SZ_DSO];  // fp16: delta | si | so
__device__ __align__(16) __half g_X  [SZ_X];    // concat activations fp16 [M][640]
__device__ __align__(16) __half g_St [2*NN_];   // S^T fp16 [i][m][k]
__device__ __align__(16) __half g_Ht0[SZ_HT];   // Ht(h) fp16 [z][d][k]
__device__ __align__(16) __half g_Ht1[SZ_HT];   // Ht scratch

// transposed weights per layer (fp16); dl/si/so contiguous => fused N=768 GEMM
#define WOFF_GCN 0
#define WOFF_IN  81920
#define WOFF_DL  147456
#define WOFF_OUT 344064
#define WSZ_L    376832
__device__ __align__(16) __half g_Wt[2*WSZ_L];

// ---------------- helpers ----------------
__device__ __forceinline__ float sigmoidf_(float x) { return 1.f / (1.f + expf(-x)); }
__device__ __forceinline__ float softplusf_(float x) {
    return fmaxf(x, 0.f) + log1pf(expf(-fabsf(x)));
}
__device__ __forceinline__ float geluf_(float x) {
    return 0.5f * x * (1.f + erff(x * 0.7071067811865475f));
}
__device__ __forceinline__ uint32_t smem_u32_(const void* p) {
    uint32_t a;
    asm("{ .reg .u64 t; cvta.to.shared.u64 t, %1; cvt.u32.u64 %0, t; }" : "=r"(a) : "l"(p));
    return a;
}
__device__ __forceinline__ void ldsm4_(uint32_t* r, uint32_t a) {
    asm volatile("ldmatrix.sync.aligned.m8n8.x4.shared.b16 {%0,%1,%2,%3}, [%4];"
        : "=r"(r[0]), "=r"(r[1]), "=r"(r[2]), "=r"(r[3]) : "r"(a));
}
__device__ __forceinline__ void mma16816_(float* d, const uint32_t* a, uint32_t b0, uint32_t b1) {
    asm volatile(
        "mma.sync.aligned.m16n8k16.row.col.f32.f16.f16.f32 "
        "{%0,%1,%2,%3}, {%4,%5,%6,%7}, {%8,%9}, {%0,%1,%2,%3};"
        : "+f"(d[0]), "+f"(d[1]), "+f"(d[2]), "+f"(d[3])
        : "r"(a[0]), "r"(a[1]), "r"(a[2]), "r"(a[3]), "r"(b0), "r"(b1));
}

// ---------------- conversions ----------------
__global__ void convt_S(const float* __restrict__ S, __half* __restrict__ out)
{
    __shared__ float t[32][33];
    const int k0 = blockIdx.x * 32, m0 = blockIdx.y * 32, i = blockIdx.z;
    const int tx = threadIdx.x & 31, ty = threadIdx.x >> 5;
    const float* Si = S + (size_t)i * NN_;
    for (int r = ty; r < 32; r += 8)
        t[r][tx] = Si[(size_t)(k0 + r) * N_ + m0 + tx];
    __syncthreads();
    for (int r = ty; r < 32; r += 8) {
        size_t o = (size_t)i * NN_ + (size_t)(m0 + r) * N_ + k0 + tx;
        out[o] = __float2half_rn(t[tx][r]);
    }
}
__global__ void convt_H(const float* __restrict__ H, __half* __restrict__ out)
{
    __shared__ float t[32][33];
    const int n0 = blockIdx.x * 32, d0 = blockIdx.y * 32, z = blockIdx.z;
    const int tx = threadIdx.x & 31, ty = threadIdx.x >> 5;
    const float* Hz = H + (size_t)z * N_ * D_;
    for (int r = ty; r < 32; r += 8)
        t[r][tx] = Hz[(size_t)(n0 + r) * D_ + d0 + tx];
    __syncthreads();
    for (int r = ty; r < 32; r += 8) {
        size_t o = ((size_t)z * D_ + d0 + r) * N_ + n0 + tx;
        out[o] = __float2half_rn(t[tx][r]);
    }
}
__global__ void convt_W(const float* __restrict__ W, int K, int N, __half* __restrict__ out)
{
    __shared__ float t[32][33];
    const int k0 = blockIdx.x * 32, n0 = blockIdx.y * 32;
    const int tx = threadIdx.x & 31, ty = threadIdx.x >> 5;
    for (int r = ty; r < 32; r += 8)
        t[r][tx] = W[(size_t)(k0 + r) * N + n0 + tx];
    __syncthreads();
    for (int r = ty; r < 32; r += 8) {
        size_t o = (size_t)(n0 + r) * K + k0 + tx;
        out[o] = __float2half_rn(t[tx][r]);
    }
}
__global__ void bias_cat(const float* __restrict__ d, const float* __restrict__ s,
                         const float* __restrict__ o, float* __restrict__ out)
{
    int l = blockIdx.x, t = threadIdx.x;        // 768 threads
    const float* src = (t < 256) ? d : ((t < 512) ? s : o);
    out[l * 768 + t] = src[l * 256 + (t & 255)];
}
__global__ void conv_plain(const float* __restrict__ src, __half* __restrict__ x)
{
    size_t e = ((size_t)blockIdx.x * blockDim.x + threadIdx.x) * 2;
    size_t row = e >> 7;
    int col = (int)(e & 127);
    float2 v = *(const float2*)(src + e);
    *(__half2*)(x + row * XLD_ + col) = __floats2half2_rn(v.x, v.y);
}
__global__ void transpose_convert_bt(const float* __restrict__ h, __half* __restrict__ x)
{
    size_t gid = (size_t)blockIdx.x * blockDim.x + threadIdx.x;
    int q = (int)(gid & 31);
    int r = (int)(gid >> 5);
    int t = r % T_;
    int bn = r / T_;
    int n = bn % N_;
    int b = bn / N_;
    size_t src = ((size_t)((b * T_ + t) * N_) + n) * D_ + q * 4;
    float4 v = *(const float4*)(h + src);
    size_t o = (size_t)r * XLD_ + q * 4;
    *(__half2*)(x + o)     = __floats2half2_rn(v.x, v.y);
    *(__half2*)(x + o + 2) = __floats2half2_rn(v.z, v.w);
}

// ---------------- HMMA GEMM infrastructure ----------------
#define STRD_ 80
#define TILEB_ (128 * STRD_)          // 10240
#define STAGEB_ (2 * TILEB_)          // 20480
#define NSTG_ 3
#define SMEM_MMA 67584                // max(3*STAGEB_, transpose 128*132*4)

// ---------------- support einsum: C[m][d] = sum_k St[m][k] * Ht[z][d][k] -------
template <bool EMIT_HT>
__global__ void __launch_bounds__(256, 2)
gemm_support_mma(const __half* __restrict__ A, const __half* __restrict__ Bm,
                 __half* __restrict__ X, __half* Ho)
{
    extern __shared__ char smem[];
    const uint32_t sbase = smem_u32_(smem);
    const int m0  = blockIdx.x * 128;
    const int z   = blockIdx.y;
    const int tid = threadIdx.x;
    const int wid = tid >> 5, lid = tid & 31;
    const int wm = wid & 3, wn = wid >> 2;
    const int m_off = wm * 32, n_off = wn * 64;

    const __half* gp[2] = { A + (size_t)m0 * N_, Bm + (size_t)z * D_ * N_ };

    auto load_stage = [&](int buf, int k0) {
        uint32_t base = sbase + buf * STAGEB_;
#pragma unroll
        for (int i = 0; i < 4; i++) {
            int idx = i * 256 + tid;
            int tile = idx >> 9;
            int rem = idx & 511;
            int r = rem >> 2, c = rem & 3;
            uint32_t dst = base + tile * TILEB_ + r * STRD_ + c * 16;
            const void* src = gp[tile] + (size_t)r * N_ + k0 + c * 8;
            asm volatile("cp.async.cg.shared.global [%0], [%1], 16;" :: "r"(dst), "l"(src));
        }
        asm volatile("cp.async.commit_group;" ::: "memory");
    };

    float acc[2][8][4];
#pragma unroll
    for (int mt = 0; mt < 2; mt++)
#pragma unroll
        for (int nt = 0; nt < 8; nt++)
#pragma unroll
            for (int q = 0; q < 4; q++) acc[mt][nt][q] = 0.f;

    const int a_row = m_off + (lid & 15);
    const int a_kc  = (lid >> 4) << 3;
    const int b_row = n_off + ((lid >> 4) << 3) + (lid & 7);
    const int b_kc  = ((lid >> 3) & 1) << 3;

    const int NT = N_ / 32;
    load_stage(0, 0);
    load_stage(1, 32);
    for (int kt = 0; kt < NT; kt++) {
        if (kt + 1 < NT) asm volatile("cp.async.wait_group 1;" ::: "memory");
        else             asm volatile("cp.async.wait_group 0;" ::: "memory");
        __syncthreads();
        if (kt + 2 < NT) load_stage((kt + 2) % NSTG_, (kt + 2) * 32);

        const uint32_t stg = sbase + (kt % NSTG_) * STAGEB_;
        const uint32_t bA = stg, bB = stg + TILEB_;
#pragma unroll
        for (int k16 = 0; k16 < 2; k16++) {
            const int kb = k16 * 16;
            uint32_t ah[2][4];
#pragma unroll
            for (int mt = 0; mt < 2; mt++)
                ldsm4_(ah[mt], bA + (uint32_t)((a_row + mt * 16) * STRD_ + (kb + a_kc) * 2));
#pragma unroll
            for (int pt = 0; pt < 4; pt++) {
                uint32_t bo = (uint32_t)((b_row + pt * 16) * STRD_ + (kb + b_kc) * 2);
                uint32_t bh[4];
                ldsm4_(bh, bB + bo);
#pragma unroll
                for (int mt = 0; mt < 2; mt++) {
#pragma unroll
                    for (int sub = 0; sub < 2; sub++)
                        mma16816_(acc[mt][pt * 2 + sub], ah[mt], bh[2 * sub], bh[2 * sub + 1]);
                }
            }
        }
    }
    __syncthreads();

    // epilogue 1: Xcat slice
#pragma unroll
    for (int mt = 0; mt < 2; mt++) {
        const size_t r0 = (size_t)z * N_ + m0 + m_off + mt * 16 + (lid >> 2);
        __half* x0 = X + r0 * XLD_;
        __half* x1 = X + (r0 + 8) * XLD_;
#pragma unroll
        for (int nt = 0; nt < 8; nt++) {
            const int cc = n_off + nt * 8 + (lid & 3) * 2;
            *(__half2*)(x0 + cc) = __floats2half2_rn(acc[mt][nt][0], acc[mt][nt][1]);
            *(__half2*)(x1 + cc) = __floats2half2_rn(acc[mt][nt][2], acc[mt][nt][3]);
        }
    }

    // epilogue 2: transposed Ht emission via smem
    if (EMIT_HT) {
        float* ts = (float*)smem;    // [128][132]
#pragma unroll
        for (int mt = 0; mt < 2; mt++) {
            const int mr = m_off + mt * 16 + (lid >> 2);
#pragma unroll
            for (int nt = 0; nt < 8; nt++) {
                const int cc = n_off + nt * 8 + (lid & 3) * 2;
                ts[mr * 132 + cc]           = acc[mt][nt][0];
                ts[mr * 132 + cc + 1]       = acc[mt][nt][1];
                ts[(mr + 8) * 132 + cc]     = acc[mt][nt][2];
                ts[(mr + 8) * 132 + cc + 1] = acc[mt][nt][3];
            }
        }
        __syncthreads();
        const int d = tid >> 1;
        const int mh = (tid & 1) * 64;
        const size_t hb = (size_t)z * D_ * N_ + (size_t)d * N_ + m0 + mh;
#pragma unroll
        for (int mi = 0; mi < 32; mi++) {
            float v0 = ts[(mh + mi * 2) * 132 + d];
            float v1 = ts[(mh + mi * 2 + 1) * 132 + d];
            *(__half2*)(Ho + hb + mi * 2) = __floats2half2_rn(v0, v1);
        }
    }
}

// ---------------- rows GEMM: C = act( X·Wt + bias ) ----------
// ACT: 0 none, 1 softplus, 2 tanh, 3 mixed (softplus for j0<256 else tanh).
// HOUT: write fp16 instead of f32.
template <int ACT, bool BIAS, bool HOUT>
__global__ void __launch_bounds__(256, 2)
gemm_rows_hmma(const __half* __restrict__ X, const __half* __restrict__ W,
               const float* __restrict__ bias, void* __restrict__ Cv,
               int K, int lda, int ldb, int ldc)
{
    extern __shared__ char smem[];
    const uint32_t sbase = smem_u32_(smem);
    const int j0  = blockIdx.x * 128;
    const int r0  = blockIdx.y * 128;
    const int tid = threadIdx.x;
    const int wid = tid >> 5, lid = tid & 31;
    const int wm = wid & 3, wn = wid >> 2;
    const int m_off = wm * 32, n_off = wn * 64;

    const __half* gp[2] = { X + (size_t)r0 * lda, W + (size_t)j0 * ldb };

    auto load_stage = [&](int buf, int k0) {
        uint32_t base = sbase + buf * STAGEB_;
#pragma unroll
        for (int i = 0; i < 4; i++) {
            int idx = i * 256 + tid;
            int tile = idx >> 9;
            int rem = idx & 511;
            int r = rem >> 2, c = rem & 3;
            int ld = (tile == 0) ? lda : ldb;
            uint32_t dst = base + tile * TILEB_ + r * STRD_ + c * 16;
            const void* src = gp[tile] + (size_t)r * ld + k0 + c * 8;
            asm volatile("cp.async.cg.shared.global [%0], [%1], 16;" :: "r"(dst), "l"(src));
        }
        asm volatile("cp.async.commit_group;" ::: "memory");
    };

    float acc[2][8][4];
#pragma unroll
    for (int mt = 0; mt < 2; mt++)
#pragma unroll
        for (int nt = 0; nt < 8; nt++)
#pragma unroll
            for (int q = 0; q < 4; q++) acc[mt][nt][q] = 0.f;

    const int a_row = m_off + (lid & 15);
    const int a_kc  = (lid >> 4) << 3;
    const int b_row = n_off + ((lid >> 4) << 3) + (lid & 7);
    const int b_kc  = ((lid >> 3) & 1) << 3;

    const int NT = K >> 5;
    load_stage(0, 0);
    load_stage(1, 32);
    for (int kt = 0; kt < NT; kt++) {
        if (kt + 1 < NT) asm volatile("cp.async.wait_group 1;" ::: "memory");
        else             asm volatile("cp.async.wait_group 0;" ::: "memory");
        __syncthreads();
        if (kt + 2 < NT) load_stage((kt + 2) % NSTG_, (kt + 2) * 32);

        const uint32_t stg = sbase + (kt % NSTG_) * STAGEB_;
        const uint32_t bA = stg, bB = stg + TILEB_;
#pragma unroll
        for (int k16 = 0; k16 < 2; k16++) {
            const int kb = k16 * 16;
            uint32_t ah[2][4];
#pragma unroll
            for (int mt = 0; mt < 2; mt++)
                ldsm4_(ah[mt], bA + (uint32_t)((a_row + mt * 16) * STRD_ + (kb + a_kc) * 2));
#pragma unroll
            for (int pt = 0; pt < 4; pt++) {
                uint32_t bo = (uint32_t)((b_row + pt * 16) * STRD_ + (kb + b_kc) * 2);
                uint32_t bh[4];
                ldsm4_(bh, bB + bo);
#pragma unroll
                for (int mt = 0; mt < 2; mt++) {
#pragma unroll
                    for (int sub = 0; sub < 2; sub++)
                        mma16816_(acc[mt][pt * 2 + sub], ah[mt], bh[2 * sub], bh[2 * sub + 1]);
                }
            }
        }
    }

    auto ep = [&](float v, float b) -> float {
        if (BIAS) v += b;
        if (ACT == 1) v = softplusf_(v);
        else if (ACT == 2) v = tanhf(v);
        else if (ACT == 3) v = (j0 < 256) ? softplusf_(v) : tanhf(v);
        return v;
    };
#pragma unroll
    for (int mt = 0; mt < 2; mt++) {
        const int r = r0 + m_off + mt * 16 + (lid >> 2);
#pragma unroll
        for (int nt = 0; nt < 8; nt++) {
            const int cc = n_off + nt * 8 + (lid & 3) * 2;
            float b0 = 0.f, b1 = 0.f;
            if (BIAS) { b0 = bias[j0 + cc]; b1 = bias[j0 + cc + 1]; }
            float v0 = ep(acc[mt][nt][0], b0), v1 = ep(acc[mt][nt][1], b1);
            float v2 = ep(acc[mt][nt][2], b0), v3 = ep(acc[mt][nt][3], b1);
            if (HOUT) {
                __half* c0 = (__half*)Cv + (size_t)r * ldc + j0 + cc;
                __half* c1 = (__half*)Cv + (size_t)(r + 8) * ldc + j0 + cc;
                *(__half2*)c0 = __floats2half2_rn(v0, v1);
                *(__half2*)c1 = __floats2half2_rn(v2, v3);
            } else {
                float* c0 = (float*)Cv + (size_t)r * ldc + j0 + cc;
                float* c1 = (float*)Cv + (size_t)(r + 8) * ldc + j0 + cc;
                *(float2*)c0 = make_float2(v0, v1);
                *(float2*)c1 = make_float2(v2, v3);
            }
        }
    }
}

// ---------------- causal depthwise conv (K=4) + SiLU; sig -> X cols 0..255 -----
__global__ void conv_silu_kernel(const __half* __restrict__ pr, const float* __restrict__ cw,
                                 const float* __restrict__ cb, __half* __restrict__ x)
{
    int idx = blockIdx.x * blockDim.x + threadIdx.x;
    int c = idx & (INNER_ - 1);
    int bn = idx >> 8;
    float w0 = cw[c * 4 + 0], w1 = cw[c * 4 + 1], w2 = cw[c * 4 + 2], w3 = cw[c * 4 + 3];
    float b = cb[c];
    float s[T_];
    size_t base = (size_t)bn * T_ * 512 + c;
#pragma unroll
    for (int t = 0; t < T_; t++) s[t] = __half2float(pr[base + (size_t)t * 512]);
    size_t ox = (size_t)bn * T_ * XLD_ + c;
#pragma unroll
    for (int t = 0; t < T_; t++) {
        float a = b + w3 * s[t];
        if (t >= 1) a += w2 * s[t - 1];
        if (t >= 2) a += w1 * s[t - 2];
        if (t >= 3) a += w0 * s[t - 3];
        float v = a * sigmoidf_(a);
        x[ox + (size_t)t * XLD_] = __float2half_rn(v);
    }
}

// ---------------- selective-scan + gating; reads X sig, overwrites with y ------
__global__ void scan_kernel(const __half* __restrict__ dso, const __half* __restrict__ pr,
                            const float* __restrict__ a_log, const float* __restrict__ d_skip,
                            __half* x)
{
    int idx = blockIdx.x * blockDim.x + threadIdx.x;
    int c = idx & (INNER_ - 1);
    int bn = idx >> 8;
    float a = -softplusf_(a_log[c]);
    float dsk = d_skip[c];
    float state = 0.f;
    size_t b768 = (size_t)bn * T_ * 768 + c;
    size_t b512 = (size_t)bn * T_ * 512 + c;
    size_t bx   = (size_t)bn * T_ * XLD_ + c;
#pragma unroll
    for (int t = 0; t < T_; t++) {
        float xs = __half2float(x  [bx   + (size_t)t * XLD_]);          // sig
        float d  = __half2float(dso[b768 + (size_t)t * 768]);           // delta
        float iv = __half2float(dso[b768 + (size_t)t * 768 + 256]);     // si
        float ov = __half2float(dso[b768 + (size_t)t * 768 + 512]);     // so
        float g  = __half2float(pr [b512 + (size_t)t * 512 + INNER_]);  // gate
        state = expf(d * a) * state + iv * xs;
        float yy = (ov * state + dsk * xs) * sigmoidf_(g);
        x[bx + (size_t)t * XLD_] = __float2half_rn(yy);
    }
}

// ---------------- fusion + LayerNorm; also emits Xcat h slice -----------------
__global__ void fuse_ln_kernel(const float* __restrict__ h_in, const float* __restrict__ sp_pre,
                               const float* __restrict__ gcn_b, const float* __restrict__ tp,
                               const float* __restrict__ ln_g, const float* __restrict__ ln_b,
                               float* __restrict__ h_out, __half* __restrict__ xo)
{
    int token = blockIdx.x;
    int d = threadIdx.x;
    int n  = token % N_;
    int bt = token / N_;
    int t  = bt % T_;
    int b  = bt / T_;
    size_t row    = (size_t)token * D_;
    size_t row_tp = ((size_t)(b * N_ + n) * T_ + t) * D_;

    float hv = h_in[row + d];
    float s = sp_pre[row + d] + gcn_b[d];
    s = geluf_(s);
    float tv = tp[row_tp + d];
    float f = hv + s + tv + s * tv;

    __shared__ float red[8];
    float v = f;
#pragma unroll
    for (int o = 16; o > 0; o >>= 1) v += __shfl_xor_sync(0xffffffffu, v, o);
    if ((d & 31) == 0) red[d >> 5] = v;
    __syncthreads();
    float mu = (red[0] + red[1] + red[2] + red[3]) * (1.f / 128.f);
    float dv = f - mu;
    v = dv * dv;
#pragma unroll
    for (int o = 16; o > 0; o >>= 1) v += __shfl_xor_sync(0xffffffffu, v, o);
    if ((d & 31) == 0) red[4 + (d >> 5)] = v;
    __syncthreads();
    float var = (red[4] + red[5] + red[6] + red[7]) * (1.f / 128.f);
    float out = dv * rsqrtf(var + 1e-5f) * ln_g[d] + ln_b[d];
    h_out[row + d] = out;
    xo[(size_t)token * XLD_ + d] = __float2half_rn(out);
}

// ---------------- host launcher ----------------
extern "C" void kernel_launch(void* const* d_in, const int* in_sizes, int n_in,
                              void* d_out, int out_size)
{
    (void)in_sizes; (void)n_in; (void)out_size;
    const float* inputs   = (const float*)d_in[0];
    const float* supports = (const float*)d_in[1];
    const float* gcn_w    = (const float*)d_in[2];
    const float* gcn_b    = (const float*)d_in[3];
    const float* in_w     = (const float*)d_in[4];
    const float* in_b     = (const float*)d_in[5];
    const float* conv_w   = (const float*)d_in[6];
    const float* conv_b   = (const float*)d_in[7];
    const float* delta_w  = (const float*)d_in[8];
    const float* delta_b  = (const float*)d_in[9];
    const float* si_w     = (const float*)d_in[10];
    const float* si_b     = (const float*)d_in[11];
    const float* so_w     = (const float*)d_in[12];
    const float* so_b     = (const float*)d_in[13];
    const float* a_log    = (const float*)d_in[14];
    const float* d_skip   = (const float*)d_in[15];
    const float* out_w    = (const float*)d_in[16];
    const float* out_b    = (const float*)d_in[17];
    const float* ln_g     = (const float*)d_in[18];
    const float* ln_b     = (const float*)d_in[19];

    float *sp, *h2, *tp, *bcat;
    __half *St, *X, *Wt, *Ht0, *Ht1, *pr, *dso;
    cudaGetSymbolAddress((void**)&sp,   g_sp);
    cudaGetSymbolAddress((void**)&h2,   g_h2);
    cudaGetSymbolAddress((void**)&tp,   g_tp);
    cudaGetSymbolAddress((void**)&bcat, g_bcat);
    cudaGetSymbolAddress((void**)&St,   g_St);
    cudaGetSymbolAddress((void**)&X,    g_X);
    cudaGetSymbolAddress((void**)&Wt,   g_Wt);
    cudaGetSymbolAddress((void**)&Ht0,  g_Ht0);
    cudaGetSymbolAddress((void**)&Ht1,  g_Ht1);
    cudaGetSymbolAddress((void**)&pr,   g_pr);
    cudaGetSymbolAddress((void**)&dso,  g_dso);

    cudaFuncSetAttribute(gemm_support_mma<true >, cudaFuncAttributeMaxDynamicSharedMemorySize, SMEM_MMA);
    cudaFuncSetAttribute(gemm_support_mma<false>, cudaFuncAttributeMaxDynamicSharedMemorySize, SMEM_MMA);
    cudaFuncSetAttribute(gemm_rows_hmma<0,false,false>, cudaFuncAttributeMaxDynamicSharedMemorySize, SMEM_MMA);
    cudaFuncSetAttribute(gemm_rows_hmma<0,true ,false>, cudaFuncAttributeMaxDynamicSharedMemorySize, SMEM_MMA);
    cudaFuncSetAttribute(gemm_rows_hmma<0,true ,true >, cudaFuncAttributeMaxDynamicSharedMemorySize, SMEM_MMA);
    cudaFuncSetAttribute(gemm_rows_hmma<3,true ,true >, cudaFuncAttributeMaxDynamicSharedMemorySize, SMEM_MMA);

    const dim3 blk(256);
    const dim3 gmma(16, BT_);
    const dim3 gcvH(64, 4, BT_);
    const dim3 gr1(1, ROWS_ / 128);
    const dim3 gr4(4, ROWS_ / 128);
    const dim3 gr6(6, ROWS_ / 128);
    const int ew_blocks = (BN_ * INNER_) / 256;

    convt_S<<<dim3(64, 64, 2), blk>>>(supports, St);
    for (int l = 0; l < 2; l++) {
        __half* w = Wt + (size_t)l * WSZ_L;
        convt_W<<<dim3(20, 4), blk>>>(gcn_w  + (size_t)l * 640 * 128, 640, 128, w + WOFF_GCN);
        convt_W<<<dim3(4, 16), blk>>>(in_w   + (size_t)l * 128 * 512, 128, 512, w + WOFF_IN);
        convt_W<<<dim3(8, 8),  blk>>>(delta_w + (size_t)l * 256 * 256, 256, 256, w + WOFF_DL);
        convt_W<<<dim3(8, 8),  blk>>>(si_w    + (size_t)l * 256 * 256, 256, 256, w + WOFF_DL + 65536);
        convt_W<<<dim3(8, 8),  blk>>>(so_w    + (size_t)l * 256 * 256, 256, 256, w + WOFF_DL + 131072);
        convt_W<<<dim3(8, 4),  blk>>>(out_w   + (size_t)l * 256 * 128, 256, 128, w + WOFF_OUT);
    }
    bias_cat<<<2, 768>>>(delta_b, si_b, so_b, bcat);
    conv_plain<<<(int)(SZ_H / 512), blk>>>(inputs, X);   // h slice for layer 0

    for (int l = 0; l < 2; l++) {
        const float* h_in  = (l == 0) ? inputs : h2;
        float*       h_out = (l == 0) ? h2 : (float*)d_out;
        const __half* w = Wt + (size_t)l * WSZ_L;
        const float* gb  = gcn_b  + l * 128;
        const float* ib  = in_b   + l * 512;
        const float* cw  = conv_w + (size_t)l * INNER_ * 4;
        const float* cb  = conv_b + l * INNER_;
        const float* al  = a_log  + l * INNER_;
        const float* dsk = d_skip + l * INNER_;
        const float* ob  = out_b + l * 128;
        const float* lg  = ln_g + l * 128;
        const float* lb  = ln_b + l * 128;

        // --- spatial branch: 4 einsums fill Xcat slices, then one K=640 GEMM ---
        convt_H<<<gcvH, blk>>>(h_in, Ht0);
        gemm_support_mma<true ><<<gmma, blk, SMEM_MMA>>>(St,       Ht0, X + 128, Ht1); // S0 h
        gemm_support_mma<false><<<gmma, blk, SMEM_MMA>>>(St,       Ht1, X + 256, nullptr); // S0^2 h
        gemm_support_mma<true ><<<gmma, blk, SMEM_MMA>>>(St + NN_, Ht0, X + 384, Ht1); // S1 h
        gemm_support_mma<false><<<gmma, blk, SMEM_MMA>>>(St + NN_, Ht1, X + 512, nullptr); // S1^2 h
        gemm_rows_hmma<0,false,false><<<gr1, blk, SMEM_MMA>>>(X, w + WOFF_GCN, nullptr, sp, 640, XLD_, 640, 128);

        // --- temporal branch ---
        transpose_convert_bt<<<(ROWS_ * 32) / 256, 256>>>(h_in, X);
        gemm_rows_hmma<0,true,true ><<<gr4, blk, SMEM_MMA>>>(X, w + WOFF_IN, ib, pr, 128, XLD_, 128, 512);
        conv_silu_kernel<<<ew_blocks, 256>>>(pr, cw, cb, X);
        gemm_rows_hmma<3,true,true ><<<gr6, blk, SMEM_MMA>>>(X, w + WOFF_DL, bcat + l * 768, dso, 256, XLD_, 256, 768);
        scan_kernel<<<ew_blocks, 256>>>(dso, pr, al, dsk, X);
        gemm_rows_hmma<0,true,false><<<gr1, blk, SMEM_MMA>>>(X, w + WOFF_OUT, ob, tp, 256, XLD_, 256, 128);

        // --- fusion + layernorm (also emits next layer's h slice into Xcat) ---
        fuse_ln_kernel<<<ROWS_, 128>>>(h_in, sp, gb, tp, lg, lb, h_out, X);
    }
}

// round 10
// speedup vs baseline: 4.6006x; 1.0554x over previous
#include <cuda_runtime.h>
#include <cuda_fp16.h>
#include <math.h>
#include <stdint.h>

// ---------------- problem constants ----------------
#define B_    16
#define T_    12
#define N_    2048
#define D_    128
#define INNER_ 256
#define BT_   (B_*T_)          // 192
#define ROWS_ (B_*T_*N_)       // 393216
#define BN_   (B_*N_)          // 32768
#define NN_   ((size_t)N_*N_)
#define XLD_  640              // Xcat row stride (spatial concat)
#define XTLD_ 256              // Xt row stride (temporal)

// ---------------- scratch (device globals; ~2.6 GiB) ----------------
#define SZ_H  ((size_t)ROWS_*D_)
#define SZ_PR ((size_t)ROWS_*512)
#define SZ_DSO ((size_t)ROWS_*768)
#define SZ_X  ((size_t)ROWS_*XLD_)
#define SZ_XT ((size_t)ROWS_*XTLD_)
#define SZ_HT ((size_t)BT_*D_*N_)

__device__ __align__(16) float g_sp  [SZ_H];
__device__ __align__(16) float g_h2  [SZ_H];
__device__ __align__(16) float g_tp  [SZ_H];
__device__ __align__(16) float g_bcat[2*768];

__device__ __align__(16) __half g_pr [SZ_PR];   // fp16: cols 0..255 signal, 256..511 gate
__device__ __align__(16) __half g_dso[SZ_DSO];  // fp16: delta | si | so
__device__ __align__(16) __half g_X  [SZ_X];    // spatial concat activations [M][640]
__device__ __align__(16) __half g_Xt [SZ_XT];   // temporal activations [bn*T+t][256]
__device__ __align__(16) __half g_St [2*NN_];   // S^T fp16 [i][m][k]
__device__ __align__(16) __half g_Ht0[SZ_HT];   // Ht(h)
__device__ __align__(16) __half g_Ht1[SZ_HT];   // Ht(S0 h)
__device__ __align__(16) __half g_Ht2[SZ_HT];   // Ht(S1 h)

// transposed weights per layer (fp16); dl/si/so contiguous => fused N=768 GEMM
#define WOFF_GCN 0
#define WOFF_IN  81920
#define WOFF_DL  147456
#define WOFF_OUT 344064
#define WSZ_L    376832
__device__ __align__(16) __half g_Wt[2*WSZ_L];

// ---------------- helpers ----------------
__device__ __forceinline__ float sigmoidf_(float x) { return 1.f / (1.f + expf(-x)); }
__device__ __forceinline__ float softplusf_(float x) {
    return fmaxf(x, 0.f) + log1pf(expf(-fabsf(x)));
}
__device__ __forceinline__ float geluf_(float x) {
    return 0.5f * x * (1.f + erff(x * 0.7071067811865475f));
}
__device__ __forceinline__ uint32_t smem_u32_(const void* p) {
    uint32_t a;
    asm("{ .reg .u64 t; cvta.to.shared.u64 t, %1; cvt.u32.u64 %0, t; }" : "=r"(a) : "l"(p));
    return a;
}
__device__ __forceinline__ void ldsm4_(uint32_t* r, uint32_t a) {
    asm volatile("ldmatrix.sync.aligned.m8n8.x4.shared.b16 {%0,%1,%2,%3}, [%4];"
        : "=r"(r[0]), "=r"(r[1]), "=r"(r[2]), "=r"(r[3]) : "r"(a));
}
__device__ __forceinline__ void mma16816_(float* d, const uint32_t* a, uint32_t b0, uint32_t b1) {
    asm volatile(
        "mma.sync.aligned.m16n8k16.row.col.f32.f16.f16.f32 "
        "{%0,%1,%2,%3}, {%4,%5,%6,%7}, {%8,%9}, {%0,%1,%2,%3};"
        : "+f"(d[0]), "+f"(d[1]), "+f"(d[2]), "+f"(d[3])
        : "r"(a[0]), "r"(a[1]), "r"(a[2]), "r"(a[3]), "r"(b0), "r"(b1));
}

// ---------------- conversions ----------------
__global__ void convt_S(const float* __restrict__ S, __half* __restrict__ out)
{
    __shared__ float t[32][33];
    const int k0 = blockIdx.x * 32, m0 = blockIdx.y * 32, i = blockIdx.z;
    const int tx = threadIdx.x & 31, ty = threadIdx.x >> 5;
    const float* Si = S + (size_t)i * NN_;
    for (int r = ty; r < 32; r += 8)
        t[r][tx] = Si[(size_t)(k0 + r) * N_ + m0 + tx];
    __syncthreads();
    for (int r = ty; r < 32; r += 8) {
        size_t o = (size_t)i * NN_ + (size_t)(m0 + r) * N_ + k0 + tx;
        out[o] = __float2half_rn(t[tx][r]);
    }
}
__global__ void convt_H(const float* __restrict__ H, __half* __restrict__ out)
{
    __shared__ float t[32][33];
    const int n0 = blockIdx.x * 32, d0 = blockIdx.y * 32, z = blockIdx.z;
    const int tx = threadIdx.x & 31, ty = threadIdx.x >> 5;
    const float* Hz = H + (size_t)z * N_ * D_;
    for (int r = ty; r < 32; r += 8)
        t[r][tx] = Hz[(size_t)(n0 + r) * D_ + d0 + tx];
    __syncthreads();
    for (int r = ty; r < 32; r += 8) {
        size_t o = ((size_t)z * D_ + d0 + r) * N_ + n0 + tx;
        out[o] = __float2half_rn(t[tx][r]);
    }
}
__global__ void convt_W(const float* __restrict__ W, int K, int N, __half* __restrict__ out)
{
    __shared__ float t[32][33];
    const int k0 = blockIdx.x * 32, n0 = blockIdx.y * 32;
    const int tx = threadIdx.x & 31, ty = threadIdx.x >> 5;
    for (int r = ty; r < 32; r += 8)
        t[r][tx] = W[(size_t)(k0 + r) * N + n0 + tx];
    __syncthreads();
    for (int r = ty; r < 32; r += 8) {
        size_t o = (size_t)(n0 + r) * K + k0 + tx;
        out[o] = __float2half_rn(t[tx][r]);
    }
}
__global__ void bias_cat(const float* __restrict__ d, const float* __restrict__ s,
                         const float* __restrict__ o, float* __restrict__ out)
{
    int l = blockIdx.x, t = threadIdx.x;
    const float* src = (t < 256) ? d : ((t < 512) ? s : o);
    out[l * 768 + t] = src[l * 256 + (t & 255)];
}
__global__ void conv_plain(const float* __restrict__ src, __half* __restrict__ x)
{
    size_t e = ((size_t)blockIdx.x * blockDim.x + threadIdx.x) * 2;
    size_t row = e >> 7;
    int col = (int)(e & 127);
    float2 v = *(const float2*)(src + e);
    *(__half2*)(x + row * XLD_ + col) = __floats2half2_rn(v.x, v.y);
}
// h(b,t,n,d) -> Xt rows bn*T+t, cols 0..127 (ld 256)
__global__ void transpose_convert_bt(const float* __restrict__ h, __half* __restrict__ x)
{
    size_t gid = (size_t)blockIdx.x * blockDim.x + threadIdx.x;
    int q = (int)(gid & 31);
    int r = (int)(gid >> 5);
    int t = r % T_;
    int bn = r / T_;
    int n = bn % N_;
    int b = bn / N_;
    size_t src = ((size_t)((b * T_ + t) * N_) + n) * D_ + q * 4;
    float4 v = *(const float4*)(h + src);
    size_t o = (size_t)r * XTLD_ + q * 4;
    *(__half2*)(x + o)     = __floats2half2_rn(v.x, v.y);
    *(__half2*)(x + o + 2) = __floats2half2_rn(v.z, v.w);
}

// ---------------- HMMA GEMM infrastructure ----------------
#define STRD_ 80
#define TILEB_ (128 * STRD_)          // 10240
#define STAGEB_ (2 * TILEB_)          // 20480
#define NSTG_ 3
#define SMEM_MMA 67584                // max(3*STAGEB_, transpose 128*132*4)

// ---------------- merged support einsum (both supports in one launch) ----------
// blockIdx.x: [0,16) -> support 0, [16,32) -> support 1.
// C[m][d] = sum_k St[h][m][k] * B{h}[z][d][k]; writes X slice slot{h}; opt. transposed Ht.
template <bool EMIT_HT>
__global__ void __launch_bounds__(256, 2)
gemm_support2(const __half* __restrict__ St,
              const __half* __restrict__ B0, const __half* __restrict__ B1,
              __half* __restrict__ Xb, int slot0, int slot1,
              __half* Ho0, __half* Ho1)
{
    extern __shared__ char smem[];
    const uint32_t sbase = smem_u32_(smem);
    const int half = blockIdx.x >> 4;
    const int m0  = (blockIdx.x & 15) * 128;
    const int z   = blockIdx.y;
    const int tid = threadIdx.x;
    const int wid = tid >> 5, lid = tid & 31;
    const int wm = wid & 3, wn = wid >> 2;
    const int m_off = wm * 32, n_off = wn * 64;

    const __half* A  = St + (size_t)half * NN_ + (size_t)m0 * N_;
    const __half* Bz = (half ? B1 : B0) + (size_t)z * D_ * N_;
    __half* Xs = Xb + (half ? slot1 : slot0);
    __half* Ho = half ? Ho1 : Ho0;
    const __half* gp[2] = { A, Bz };

    auto load_stage = [&](int buf, int k0) {
        uint32_t base = sbase + buf * STAGEB_;
#pragma unroll
        for (int i = 0; i < 4; i++) {
            int idx = i * 256 + tid;
            int tile = idx >> 9;
            int rem = idx & 511;
            int r = rem >> 2, c = rem & 3;
            uint32_t dst = base + tile * TILEB_ + r * STRD_ + c * 16;
            const void* src = gp[tile] + (size_t)r * N_ + k0 + c * 8;
            asm volatile("cp.async.cg.shared.global [%0], [%1], 16;" :: "r"(dst), "l"(src));
        }
        asm volatile("cp.async.commit_group;" ::: "memory");
    };

    float acc[2][8][4];
#pragma unroll
    for (int mt = 0; mt < 2; mt++)
#pragma unroll
        for (int nt = 0; nt < 8; nt++)
#pragma unroll
            for (int q = 0; q < 4; q++) acc[mt][nt][q] = 0.f;

    const int a_row = m_off + (lid & 15);
    const int a_kc  = (lid >> 4) << 3;
    const int b_row = n_off + ((lid >> 4) << 3) + (lid & 7);
    const int b_kc  = ((lid >> 3) & 1) << 3;

    const int NT = N_ / 32;
    load_stage(0, 0);
    load_stage(1, 32);
    for (int kt = 0; kt < NT; kt++) {
        if (kt + 1 < NT) asm volatile("cp.async.wait_group 1;" ::: "memory");
        else             asm volatile("cp.async.wait_group 0;" ::: "memory");
        __syncthreads();
        if (kt + 2 < NT) load_stage((kt + 2) % NSTG_, (kt + 2) * 32);

        const uint32_t stg = sbase + (kt % NSTG_) * STAGEB_;
        const uint32_t bA = stg, bB = stg + TILEB_;
#pragma unroll
        for (int k16 = 0; k16 < 2; k16++) {
            const int kb = k16 * 16;
            uint32_t ah[2][4];
#pragma unroll
            for (int mt = 0; mt < 2; mt++)
                ldsm4_(ah[mt], bA + (uint32_t)((a_row + mt * 16) * STRD_ + (kb + a_kc) * 2));
#pragma unroll
            for (int pt = 0; pt < 4; pt++) {
                uint32_t bo = (uint32_t)((b_row + pt * 16) * STRD_ + (kb + b_kc) * 2);
                uint32_t bh[4];
                ldsm4_(bh, bB + bo);
#pragma unroll
                for (int mt = 0; mt < 2; mt++) {
#pragma unroll
                    for (int sub = 0; sub < 2; sub++)
                        mma16816_(acc[mt][pt * 2 + sub], ah[mt], bh[2 * sub], bh[2 * sub + 1]);
                }
            }
        }
    }
    __syncthreads();

    // epilogue 1: Xcat slice
#pragma unroll
    for (int mt = 0; mt < 2; mt++) {
        const size_t r0 = (size_t)z * N_ + m0 + m_off + mt * 16 + (lid >> 2);
        __half* x0 = Xs + r0 * XLD_;
        __half* x1 = Xs + (r0 + 8) * XLD_;
#pragma unroll
        for (int nt = 0; nt < 8; nt++) {
            const int cc = n_off + nt * 8 + (lid & 3) * 2;
            *(__half2*)(x0 + cc) = __floats2half2_rn(acc[mt][nt][0], acc[mt][nt][1]);
            *(__half2*)(x1 + cc) = __floats2half2_rn(acc[mt][nt][2], acc[mt][nt][3]);
        }
    }

    // epilogue 2: transposed Ht emission via smem
    if (EMIT_HT) {
        float* ts = (float*)smem;    // [128][132]
#pragma unroll
        for (int mt = 0; mt < 2; mt++) {
            const int mr = m_off + mt * 16 + (lid >> 2);
#pragma unroll
            for (int nt = 0; nt < 8; nt++) {
                const int cc = n_off + nt * 8 + (lid & 3) * 2;
                ts[mr * 132 + cc]           = acc[mt][nt][0];
                ts[mr * 132 + cc + 1]       = acc[mt][nt][1];
                ts[(mr + 8) * 132 + cc]     = acc[mt][nt][2];
                ts[(mr + 8) * 132 + cc + 1] = acc[mt][nt][3];
            }
        }
        __syncthreads();
        const int d = tid >> 1;
        const int mh = (tid & 1) * 64;
        const size_t hb = (size_t)z * D_ * N_ + (size_t)d * N_ + m0 + mh;
#pragma unroll
        for (int mi = 0; mi < 32; mi++) {
            float v0 = ts[(mh + mi * 2) * 132 + d];
            float v1 = ts[(mh + mi * 2 + 1) * 132 + d];
            *(__half2*)(Ho + hb + mi * 2) = __floats2half2_rn(v0, v1);
        }
    }
}

// ---------------- rows GEMM: C = act( X·Wt + bias ) ----------
template <int ACT, bool BIAS, bool HOUT>
__global__ void __launch_bounds__(256, 2)
gemm_rows_hmma(const __half* __restrict__ X, const __half* __restrict__ W,
               const float* __restrict__ bias, void* __restrict__ Cv,
               int K, int lda, int ldb, int ldc)
{
    extern __shared__ char smem[];
    const uint32_t sbase = smem_u32_(smem);
    const int j0  = blockIdx.x * 128;
    const int r0  = blockIdx.y * 128;
    const int tid = threadIdx.x;
    const int wid = tid >> 5, lid = tid & 31;
    const int wm = wid & 3, wn = wid >> 2;
    const int m_off = wm * 32, n_off = wn * 64;

    const __half* gp[2] = { X + (size_t)r0 * lda, W + (size_t)j0 * ldb };

    auto load_stage = [&](int buf, int k0) {
        uint32_t base = sbase + buf * STAGEB_;
#pragma unroll
        for (int i = 0; i < 4; i++) {
            int idx = i * 256 + tid;
            int tile = idx >> 9;
            int rem = idx & 511;
            int r = rem >> 2, c = rem & 3;
            int ld = (tile == 0) ? lda : ldb;
            uint32_t dst = base + tile * TILEB_ + r * STRD_ + c * 16;
            const void* src = gp[tile] + (size_t)r * ld + k0 + c * 8;
            asm volatile("cp.async.cg.shared.global [%0], [%1], 16;" :: "r"(dst), "l"(src));
        }
        asm volatile("cp.async.commit_group;" ::: "memory");
    };

    float acc[2][8][4];
#pragma unroll
    for (int mt = 0; mt < 2; mt++)
#pragma unroll
        for (int nt = 0; nt < 8; nt++)
#pragma unroll
            for (int q = 0; q < 4; q++) acc[mt][nt][q] = 0.f;

    const int a_row = m_off + (lid & 15);
    const int a_kc  = (lid >> 4) << 3;
    const int b_row = n_off + ((lid >> 4) << 3) + (lid & 7);
    const int b_kc  = ((lid >> 3) & 1) << 3;

    const int NT = K >> 5;
    load_stage(0, 0);
    load_stage(1, 32);
    for (int kt = 0; kt < NT; kt++) {
        if (kt + 1 < NT) asm volatile("cp.async.wait_group 1;" ::: "memory");
        else             asm volatile("cp.async.wait_group 0;" ::: "memory");
        __syncthreads();
        if (kt + 2 < NT) load_stage((kt + 2) % NSTG_, (kt + 2) * 32);

        const uint32_t stg = sbase + (kt % NSTG_) * STAGEB_;
        const uint32_t bA = stg, bB = stg + TILEB_;
#pragma unroll
        for (int k16 = 0; k16 < 2; k16++) {
            const int kb = k16 * 16;
            uint32_t ah[2][4];
#pragma unroll
            for (int mt = 0; mt < 2; mt++)
                ldsm4_(ah[mt], bA + (uint32_t)((a_row + mt * 16) * STRD_ + (kb + a_kc) * 2));
#pragma unroll
            for (int pt = 0; pt < 4; pt++) {
                uint32_t bo = (uint32_t)((b_row + pt * 16) * STRD_ + (kb + b_kc) * 2);
                uint32_t bh[4];
                ldsm4_(bh, bB + bo);
#pragma unroll
                for (int mt = 0; mt < 2; mt++) {
#pragma unroll
                    for (int sub = 0; sub < 2; sub++)
                        mma16816_(acc[mt][pt * 2 + sub], ah[mt], bh[2 * sub], bh[2 * sub + 1]);
                }
            }
        }
    }

    auto ep = [&](float v, float b) -> float {
        if (BIAS) v += b;
        if (ACT == 1) v = softplusf_(v);
        else if (ACT == 2) v = tanhf(v);
        else if (ACT == 3) v = (j0 < 256) ? softplusf_(v) : tanhf(v);
        return v;
    };
#pragma unroll
    for (int mt = 0; mt < 2; mt++) {
        const int r = r0 + m_off + mt * 16 + (lid >> 2);
#pragma unroll
        for (int nt = 0; nt < 8; nt++) {
            const int cc = n_off + nt * 8 + (lid & 3) * 2;
            float b0 = 0.f, b1 = 0.f;
            if (BIAS) { b0 = bias[j0 + cc]; b1 = bias[j0 + cc + 1]; }
            float v0 = ep(acc[mt][nt][0], b0), v1 = ep(acc[mt][nt][1], b1);
            float v2 = ep(acc[mt][nt][2], b0), v3 = ep(acc[mt][nt][3], b1);
            if (HOUT) {
                __half* c0 = (__half*)Cv + (size_t)r * ldc + j0 + cc;
                __half* c1 = (__half*)Cv + (size_t)(r + 8) * ldc + j0 + cc;
                *(__half2*)c0 = __floats2half2_rn(v0, v1);
                *(__half2*)c1 = __floats2half2_rn(v2, v3);
            } else {
                float* c0 = (float*)Cv + (size_t)r * ldc + j0 + cc;
                float* c1 = (float*)Cv + (size_t)(r + 8) * ldc + j0 + cc;
                *(float2*)c0 = make_float2(v0, v1);
                *(float2*)c1 = make_float2(v2, v3);
            }
        }
    }
}

// ---------------- causal depthwise conv (K=4) + SiLU; sig -> Xt cols 0..255 -----
__global__ void conv_silu_kernel(const __half* __restrict__ pr, const float* __restrict__ cw,
                                 const float* __restrict__ cb, __half* __restrict__ x)
{
    int idx = blockIdx.x * blockDim.x + threadIdx.x;
    int c = idx & (INNER_ - 1);
    int bn = idx >> 8;
    float w0 = cw[c * 4 + 0], w1 = cw[c * 4 + 1], w2 = cw[c * 4 + 2], w3 = cw[c * 4 + 3];
    float b = cb[c];
    float s[T_];
    size_t base = (size_t)bn * T_ * 512 + c;
#pragma unroll
    for (int t = 0; t < T_; t++) s[t] = __half2float(pr[base + (size_t)t * 512]);
    size_t ox = (size_t)bn * T_ * XTLD_ + c;
#pragma unroll
    for (int t = 0; t < T_; t++) {
        float a = b + w3 * s[t];
        if (t >= 1) a += w2 * s[t - 1];
        if (t >= 2) a += w1 * s[t - 2];
        if (t >= 3) a += w0 * s[t - 3];
        float v = a * sigmoidf_(a);
        x[ox + (size_t)t * XTLD_] = __float2half_rn(v);
    }
}

// ---------------- selective-scan + gating; reads Xt sig, overwrites with y ------
__global__ void scan_kernel(const __half* __restrict__ dso, const __half* __restrict__ pr,
                            const float* __restrict__ a_log, const float* __restrict__ d_skip,
                            __half* x)
{
    int idx = blockIdx.x * blockDim.x + threadIdx.x;
    int c = idx & (INNER_ - 1);
    int bn = idx >> 8;
    float a = -softplusf_(a_log[c]);
    float dsk = d_skip[c];
    float state = 0.f;
    size_t b768 = (size_t)bn * T_ * 768 + c;
    size_t b512 = (size_t)bn * T_ * 512 + c;
    size_t bx   = (size_t)bn * T_ * XTLD_ + c;
#pragma unroll
    for (int t = 0; t < T_; t++) {
        float xs = __half2float(x  [bx   + (size_t)t * XTLD_]);
        float d  = __half2float(dso[b768 + (size_t)t * 768]);
        float iv = __half2float(dso[b768 + (size_t)t * 768 + 256]);
        float ov = __half2float(dso[b768 + (size_t)t * 768 + 512]);
        float g  = __half2float(pr [b512 + (size_t)t * 512 + INNER_]);
        state = expf(d * a) * state + iv * xs;
        float yy = (ov * state + dsk * xs) * sigmoidf_(g);
        x[bx + (size_t)t * XTLD_] = __float2half_rn(yy);
    }
}

// ---------------- fusion + LayerNorm; also emits Xcat h slice -----------------
__global__ void fuse_ln_kernel(const float* __restrict__ h_in, const float* __restrict__ sp_pre,
                               const float* __restrict__ gcn_b, const float* __restrict__ tp,
                               const float* __restrict__ ln_g, const float* __restrict__ ln_b,
                               float* __restrict__ h_out, __half* __restrict__ xo)
{
    int token = blockIdx.x;
    int d = threadIdx.x;
    int n  = token % N_;
    int bt = token / N_;
    int t  = bt % T_;
    int b  = bt / T_;
    size_t row    = (size_t)token * D_;
    size_t row_tp = ((size_t)(b * N_ + n) * T_ + t) * D_;

    float hv = h_in[row + d];
    float s = sp_pre[row + d] + gcn_b[d];
    s = geluf_(s);
    float tv = tp[row_tp + d];
    float f = hv + s + tv + s * tv;

    __shared__ float red[8];
    float v = f;
#pragma unroll
    for (int o = 16; o > 0; o >>= 1) v += __shfl_xor_sync(0xffffffffu, v, o);
    if ((d & 31) == 0) red[d >> 5] = v;
    __syncthreads();
    float mu = (red[0] + red[1] + red[2] + red[3]) * (1.f / 128.f);
    float dv = f - mu;
    v = dv * dv;
#pragma unroll
    for (int o = 16; o > 0; o >>= 1) v += __shfl_xor_sync(0xffffffffu, v, o);
    if ((d & 31) == 0) red[4 + (d >> 5)] = v;
    __syncthreads();
    float var = (red[4] + red[5] + red[6] + red[7]) * (1.f / 128.f);
    float out = dv * rsqrtf(var + 1e-5f) * ln_g[d] + ln_b[d];
    h_out[row + d] = out;
    xo[(size_t)token * XLD_ + d] = __float2half_rn(out);
}

// ---------------- host launcher ----------------
extern "C" void kernel_launch(void* const* d_in, const int* in_sizes, int n_in,
                              void* d_out, int out_size)
{
    (void)in_sizes; (void)n_in; (void)out_size;
    const float* inputs   = (const float*)d_in[0];
    const float* supports = (const float*)d_in[1];
    const float* gcn_w    = (const float*)d_in[2];
    const float* gcn_b    = (const float*)d_in[3];
    const float* in_w     = (const float*)d_in[4];
    const float* in_b     = (const float*)d_in[5];
    const float* conv_w   = (const float*)d_in[6];
    const float* conv_b   = (const float*)d_in[7];
    const float* delta_w  = (const float*)d_in[8];
    const float* delta_b  = (const float*)d_in[9];
    const float* si_w     = (const float*)d_in[10];
    const float* si_b     = (const float*)d_in[11];
    const float* so_w     = (const float*)d_in[12];
    const float* so_b     = (const float*)d_in[13];
    const float* a_log    = (const float*)d_in[14];
    const float* d_skip   = (const float*)d_in[15];
    const float* out_w    = (const float*)d_in[16];
    const float* out_b    = (const float*)d_in[17];
    const float* ln_g     = (const float*)d_in[18];
    const float* ln_b     = (const float*)d_in[19];

    float *sp, *h2, *tp, *bcat;
    __half *St, *X, *Xt, *Wt, *Ht0, *Ht1, *Ht2, *pr, *dso;
    cudaGetSymbolAddress((void**)&sp,   g_sp);
    cudaGetSymbolAddress((void**)&h2,   g_h2);
    cudaGetSymbolAddress((void**)&tp,   g_tp);
    cudaGetSymbolAddress((void**)&bcat, g_bcat);
    cudaGetSymbolAddress((void**)&St,   g_St);
    cudaGetSymbolAddress((void**)&X,    g_X);
    cudaGetSymbolAddress((void**)&Xt,   g_Xt);
    cudaGetSymbolAddress((void**)&Wt,   g_Wt);
    cudaGetSymbolAddress((void**)&Ht0,  g_Ht0);
    cudaGetSymbolAddress((void**)&Ht1,  g_Ht1);
    cudaGetSymbolAddress((void**)&Ht2,  g_Ht2);
    cudaGetSymbolAddress((void**)&pr,   g_pr);
    cudaGetSymbolAddress((void**)&dso,  g_dso);

    // one-time stream/event setup (created on the uncaptured correctness call;
    // identical launched work on every call)
    static cudaStream_t s1 = nullptr;
    static cudaEvent_t evF[2], evJ[2];
    if (s1 == nullptr) {
        cudaStreamCreateWithFlags(&s1, cudaStreamNonBlocking);
        for (int i = 0; i < 2; i++) {
            cudaEventCreateWithFlags(&evF[i], cudaEventDisableTiming);
            cudaEventCreateWithFlags(&evJ[i], cudaEventDisableTiming);
        }
    }

    cudaFuncSetAttribute(gemm_support2<true >, cudaFuncAttributeMaxDynamicSharedMemorySize, SMEM_MMA);
    cudaFuncSetAttribute(gemm_support2<false>, cudaFuncAttributeMaxDynamicSharedMemorySize, SMEM_MMA);
    cudaFuncSetAttribute(gemm_rows_hmma<0,false,false>, cudaFuncAttributeMaxDynamicSharedMemorySize, SMEM_MMA);
    cudaFuncSetAttribute(gemm_rows_hmma<0,true ,false>, cudaFuncAttributeMaxDynamicSharedMemorySize, SMEM_MMA);
    cudaFuncSetAttribute(gemm_rows_hmma<0,true ,true >, cudaFuncAttributeMaxDynamicSharedMemorySize, SMEM_MMA);
    cudaFuncSetAttribute(gemm_rows_hmma<3,true ,true >, cudaFuncAttributeMaxDynamicSharedMemorySize, SMEM_MMA);

    const dim3 blk(256);
    const dim3 gmma2(32, BT_);
    const dim3 gcvH(64, 4, BT_);
    const dim3 gr1(1, ROWS_ / 128);
    const dim3 gr4(4, ROWS_ / 128);
    const dim3 gr6(6, ROWS_ / 128);
    const int ew_blocks = (BN_ * INNER_) / 256;

    convt_S<<<dim3(64, 64, 2), blk>>>(supports, St);
    for (int l = 0; l < 2; l++) {
        __half* w = Wt + (size_t)l * WSZ_L;
        convt_W<<<dim3(20, 4), blk>>>(gcn_w  + (size_t)l * 640 * 128, 640, 128, w + WOFF_GCN);
        convt_W<<<dim3(4, 16), blk>>>(in_w   + (size_t)l * 128 * 512, 128, 512, w + WOFF_IN);
        convt_W<<<dim3(8, 8),  blk>>>(delta_w + (size_t)l * 256 * 256, 256, 256, w + WOFF_DL);
        convt_W<<<dim3(8, 8),  blk>>>(si_w    + (size_t)l * 256 * 256, 256, 256, w + WOFF_DL + 65536);
        convt_W<<<dim3(8, 8),  blk>>>(so_w    + (size_t)l * 256 * 256, 256, 256, w + WOFF_DL + 131072);
        convt_W<<<dim3(8, 4),  blk>>>(out_w   + (size_t)l * 256 * 128, 256, 128, w + WOFF_OUT);
    }
    bias_cat<<<2, 768>>>(delta_b, si_b, so_b, bcat);
    conv_plain<<<(int)(SZ_H / 512), blk>>>(inputs, X);   // h slice for layer 0

    for (int l = 0; l < 2; l++) {
        const float* h_in  = (l == 0) ? inputs : h2;
        float*       h_out = (l == 0) ? h2 : (float*)d_out;
        const __half* w = Wt + (size_t)l * WSZ_L;
        const float* gb  = gcn_b  + l * 128;
        const float* ib  = in_b   + l * 512;
        const float* cw  = conv_w + (size_t)l * INNER_ * 4;
        const float* cb  = conv_b + l * INNER_;
        const float* al  = a_log  + l * INNER_;
        const float* dsk = d_skip + l * INNER_;
        const float* ob  = out_b + l * 128;
        const float* lg  = ln_g + l * 128;
        const float* lb  = ln_b + l * 128;

        // ---- fork: temporal branch on s1 (depends only on h_in) ----
        cudaEventRecord(evF[l], 0);
        cudaStreamWaitEvent(s1, evF[l], 0);
        transpose_convert_bt<<<(ROWS_ * 32) / 256, 256, 0, s1>>>(h_in, Xt);
        gemm_rows_hmma<0,true,true ><<<gr4, blk, SMEM_MMA, s1>>>(Xt, w + WOFF_IN, ib, pr, 128, XTLD_, 128, 512);
        conv_silu_kernel<<<ew_blocks, 256, 0, s1>>>(pr, cw, cb, Xt);
        gemm_rows_hmma<3,true,true ><<<gr6, blk, SMEM_MMA, s1>>>(Xt, w + WOFF_DL, bcat + l * 768, dso, 256, XTLD_, 256, 768);
        scan_kernel<<<ew_blocks, 256, 0, s1>>>(dso, pr, al, dsk, Xt);
        gemm_rows_hmma<0,true,false><<<gr1, blk, SMEM_MMA, s1>>>(Xt, w + WOFF_OUT, ob, tp, 256, XTLD_, 256, 128);
        cudaEventRecord(evJ[l], s1);

        // ---- spatial branch on default stream ----
        convt_H<<<gcvH, blk>>>(h_in, Ht0);
        gemm_support2<true ><<<gmma2, blk, SMEM_MMA>>>(St, Ht0, Ht0, X, 128, 384, Ht1, Ht2); // S0h, S1h
        gemm_support2<false><<<gmma2, blk, SMEM_MMA>>>(St, Ht1, Ht2, X, 256, 512, nullptr, nullptr); // S0^2h, S1^2h
        gemm_rows_hmma<0,false,false><<<gr1, blk, SMEM_MMA>>>(X, w + WOFF_GCN, nullptr, sp, 640, XLD_, 640, 128);

        // ---- join + fusion/layernorm ----
        cudaStreamWaitEvent(0, evJ[l], 0);
        fuse_ln_kernel<<<ROWS_, 128>>>(h_in, sp, gb, tp, lg, lb, h_out, X);
    }
}

// round 11
// speedup vs baseline: 4.8142x; 1.0464x over previous
#include <cuda_runtime.h>
#include <cuda_fp16.h>
#include <math.h>
#include <stdint.h>

// ---------------- problem constants ----------------
#define B_    16
#define T_    12
#define N_    2048
#define D_    128
#define INNER_ 256
#define BT_   (B_*T_)          // 192
#define ROWS_ (B_*T_*N_)       // 393216
#define BN_   (B_*N_)          // 32768
#define NN_   ((size_t)N_*N_)
#define XLD_  640              // Xcat row stride (spatial concat)
#define XTLD_ 256              // Xt row stride (temporal)

// ---------------- scratch (device globals; ~2.5 GiB) ----------------
#define SZ_H  ((size_t)ROWS_*D_)
#define SZ_PR ((size_t)ROWS_*512)
#define SZ_DSO ((size_t)ROWS_*768)
#define SZ_X  ((size_t)ROWS_*XLD_)
#define SZ_XT ((size_t)ROWS_*XTLD_)
#define SZ_HT ((size_t)BT_*D_*N_)

__device__ __align__(16) float g_sp  [SZ_H];
__device__ __align__(16) float g_h2  [SZ_H];
__device__ __align__(16) float g_tp  [SZ_H];
__device__ __align__(16) float g_bcat[2*768];

__device__ __align__(16) __half g_pr [SZ_PR];   // fp16: cols 0..255 signal, 256..511 gate
__device__ __align__(16) __half g_dso[SZ_DSO];  // fp16: delta | si | so
__device__ __align__(16) __half g_X  [SZ_X];    // spatial concat activations [M][640]
__device__ __align__(16) __half g_Xt [SZ_XT];   // temporal activations [bn*T+t][256]
__device__ __align__(16) __half g_St [2*NN_];   // S^T fp16 [i][m][k]
__device__ __align__(16) __half g_Sh [2*NN_];   // S  fp16 row-major [i][k][n]
__device__ __align__(16) __half g_St2[2*NN_];   // (S^2)^T = St.St  fp16 [i][m][k]
__device__ __align__(16) __half g_Ht0[SZ_HT];   // Ht(h)

// transposed weights per layer (fp16); dl/si/so contiguous => fused N=768 GEMM
#define WOFF_GCN 0
#define WOFF_IN  81920
#define WOFF_DL  147456
#define WOFF_OUT 344064
#define WSZ_L    376832
__device__ __align__(16) __half g_Wt[2*WSZ_L];

// ---------------- helpers ----------------
__device__ __forceinline__ float sigmoidf_(float x) { return 1.f / (1.f + expf(-x)); }
__device__ __forceinline__ float softplusf_(float x) {
    return fmaxf(x, 0.f) + log1pf(expf(-fabsf(x)));
}
__device__ __forceinline__ float geluf_(float x) {
    return 0.5f * x * (1.f + erff(x * 0.7071067811865475f));
}
__device__ __forceinline__ uint32_t smem_u32_(const void* p) {
    uint32_t a;
    asm("{ .reg .u64 t; cvta.to.shared.u64 t, %1; cvt.u32.u64 %0, t; }" : "=r"(a) : "l"(p));
    return a;
}
__device__ __forceinline__ void ldsm4_(uint32_t* r, uint32_t a) {
    asm volatile("ldmatrix.sync.aligned.m8n8.x4.shared.b16 {%0,%1,%2,%3}, [%4];"
        : "=r"(r[0]), "=r"(r[1]), "=r"(r[2]), "=r"(r[3]) : "r"(a));
}
__device__ __forceinline__ void mma16816_(float* d, const uint32_t* a, uint32_t b0, uint32_t b1) {
    asm volatile(
        "mma.sync.aligned.m16n8k16.row.col.f32.f16.f16.f32 "
        "{%0,%1,%2,%3}, {%4,%5,%6,%7}, {%8,%9}, {%0,%1,%2,%3};"
        : "+f"(d[0]), "+f"(d[1]), "+f"(d[2]), "+f"(d[3])
        : "r"(a[0]), "r"(a[1]), "r"(a[2]), "r"(a[3]), "r"(b0), "r"(b1));
}

// ---------------- conversions ----------------
__global__ void convt_S(const float* __restrict__ S, __half* __restrict__ out)
{
    __shared__ float t[32][33];
    const int k0 = blockIdx.x * 32, m0 = blockIdx.y * 32, i = blockIdx.z;
    const int tx = threadIdx.x & 31, ty = threadIdx.x >> 5;
    const float* Si = S + (size_t)i * NN_;
    for (int r = ty; r < 32; r += 8)
        t[r][tx] = Si[(size_t)(k0 + r) * N_ + m0 + tx];
    __syncthreads();
    for (int r = ty; r < 32; r += 8) {
        size_t o = (size_t)i * NN_ + (size_t)(m0 + r) * N_ + k0 + tx;
        out[o] = __float2half_rn(t[tx][r]);
    }
}
__global__ void conv_copy(const float* __restrict__ src, __half* __restrict__ dst)
{
    size_t e = ((size_t)blockIdx.x * blockDim.x + threadIdx.x) * 2;
    float2 v = *(const float2*)(src + e);
    *(__half2*)(dst + e) = __floats2half2_rn(v.x, v.y);
}
__global__ void convt_H(const float* __restrict__ H, __half* __restrict__ out)
{
    __shared__ float t[32][33];
    const int n0 = blockIdx.x * 32, d0 = blockIdx.y * 32, z = blockIdx.z;
    const int tx = threadIdx.x & 31, ty = threadIdx.x >> 5;
    const float* Hz = H + (size_t)z * N_ * D_;
    for (int r = ty; r < 32; r += 8)
        t[r][tx] = Hz[(size_t)(n0 + r) * D_ + d0 + tx];
    __syncthreads();
    for (int r = ty; r < 32; r += 8) {
        size_t o = ((size_t)z * D_ + d0 + r) * N_ + n0 + tx;
        out[o] = __float2half_rn(t[tx][r]);
    }
}
__global__ void convt_W(const float* __restrict__ W, int K, int N, __half* __restrict__ out)
{
    __shared__ float t[32][33];
    const int k0 = blockIdx.x * 32, n0 = blockIdx.y * 32;
    const int tx = threadIdx.x & 31, ty = threadIdx.x >> 5;
    for (int r = ty; r < 32; r += 8)
        t[r][tx] = W[(size_t)(k0 + r) * N + n0 + tx];
    __syncthreads();
    for (int r = ty; r < 32; r += 8) {
        size_t o = (size_t)(n0 + r) * K + k0 + tx;
        out[o] = __float2half_rn(t[tx][r]);
    }
}
__global__ void bias_cat(const float* __restrict__ d, const float* __restrict__ s,
                         const float* __restrict__ o, float* __restrict__ out)
{
    int l = blockIdx.x, t = threadIdx.x;
    const float* src = (t < 256) ? d : ((t < 512) ? s : o);
    out[l * 768 + t] = src[l * 256 + (t & 255)];
}
__global__ void conv_plain(const float* __restrict__ src, __half* __restrict__ x)
{
    size_t e = ((size_t)blockIdx.x * blockDim.x + threadIdx.x) * 2;
    size_t row = e >> 7;
    int col = (int)(e & 127);
    float2 v = *(const float2*)(src + e);
    *(__half2*)(x + row * XLD_ + col) = __floats2half2_rn(v.x, v.y);
}
__global__ void transpose_convert_bt(const float* __restrict__ h, __half* __restrict__ x)
{
    size_t gid = (size_t)blockIdx.x * blockDim.x + threadIdx.x;
    int q = (int)(gid & 31);
    int r = (int)(gid >> 5);
    int t = r % T_;
    int bn = r / T_;
    int n = bn % N_;
    int b = bn / N_;
    size_t src = ((size_t)((b * T_ + t) * N_) + n) * D_ + q * 4;
    float4 v = *(const float4*)(h + src);
    size_t o = (size_t)r * XTLD_ + q * 4;
    *(__half2*)(x + o)     = __floats2half2_rn(v.x, v.y);
    *(__half2*)(x + o + 2) = __floats2half2_rn(v.z, v.w);
}

// ---------------- HMMA GEMM infrastructure ----------------
#define STRD_ 80
#define TILEB_ (128 * STRD_)          // 10240
#define STAGEB_ (2 * TILEB_)          // 20480
#define NSTG_ 3
#define SMEM_MMA (NSTG_ * STAGEB_)    // 61440

// ---------------- 4-way support einsum (one launch, all independent) -----------
// blockIdx.x>>4 selects q in {St0->slot128, St0^2->256, St1->384, St1^2->512};
// C[m][d] = sum_k Aq[m][k] * Ht[z][d][k]; writes Xcat slice.
__global__ void __launch_bounds__(256, 2)
gemm_support4(const __half* __restrict__ A0, const __half* __restrict__ A1,
              const __half* __restrict__ A2, const __half* __restrict__ A3,
              const __half* __restrict__ Bm, __half* __restrict__ Xb)
{
    extern __shared__ char smem[];
    const uint32_t sbase = smem_u32_(smem);
    const int q   = blockIdx.x >> 4;
    const int m0  = (blockIdx.x & 15) * 128;
    const int z   = blockIdx.y;
    const int tid = threadIdx.x;
    const int wid = tid >> 5, lid = tid & 31;
    const int wm = wid & 3, wn = wid >> 2;
    const int m_off = wm * 32, n_off = wn * 64;

    const __half* Aq = (q == 0) ? A0 : (q == 1) ? A1 : (q == 2) ? A2 : A3;
    __half* Xs = Xb + 128 * (q + 1);
    const __half* gp[2] = { Aq + (size_t)m0 * N_, Bm + (size_t)z * D_ * N_ };

    auto load_stage = [&](int buf, int k0) {
        uint32_t base = sbase + buf * STAGEB_;
#pragma unroll
        for (int i = 0; i < 4; i++) {
            int idx = i * 256 + tid;
            int tile = idx >> 9;
            int rem = idx & 511;
            int r = rem >> 2, c = rem & 3;
            uint32_t dst = base + tile * TILEB_ + r * STRD_ + c * 16;
            const void* src = gp[tile] + (size_t)r * N_ + k0 + c * 8;
            asm volatile("cp.async.cg.shared.global [%0], [%1], 16;" :: "r"(dst), "l"(src));
        }
        asm volatile("cp.async.commit_group;" ::: "memory");
    };

    float acc[2][8][4];
#pragma unroll
    for (int mt = 0; mt < 2; mt++)
#pragma unroll
        for (int nt = 0; nt < 8; nt++)
#pragma unroll
            for (int qq = 0; qq < 4; qq++) acc[mt][nt][qq] = 0.f;

    const int a_row = m_off + (lid & 15);
    const int a_kc  = (lid >> 4) << 3;
    const int b_row = n_off + ((lid >> 4) << 3) + (lid & 7);
    const int b_kc  = ((lid >> 3) & 1) << 3;

    const int NT = N_ / 32;
    load_stage(0, 0);
    load_stage(1, 32);
    for (int kt = 0; kt < NT; kt++) {
        if (kt + 1 < NT) asm volatile("cp.async.wait_group 1;" ::: "memory");
        else             asm volatile("cp.async.wait_group 0;" ::: "memory");
        __syncthreads();
        if (kt + 2 < NT) load_stage((kt + 2) % NSTG_, (kt + 2) * 32);

        const uint32_t stg = sbase + (kt % NSTG_) * STAGEB_;
        const uint32_t bA = stg, bB = stg + TILEB_;
#pragma unroll
        for (int k16 = 0; k16 < 2; k16++) {
            const int kb = k16 * 16;
            uint32_t ah[2][4];
#pragma unroll
            for (int mt = 0; mt < 2; mt++)
                ldsm4_(ah[mt], bA + (uint32_t)((a_row + mt * 16) * STRD_ + (kb + a_kc) * 2));
#pragma unroll
            for (int pt = 0; pt < 4; pt++) {
                uint32_t bo = (uint32_t)((b_row + pt * 16) * STRD_ + (kb + b_kc) * 2);
                uint32_t bh[4];
                ldsm4_(bh, bB + bo);
#pragma unroll
                for (int mt = 0; mt < 2; mt++) {
#pragma unroll
                    for (int sub = 0; sub < 2; sub++)
                        mma16816_(acc[mt][pt * 2 + sub], ah[mt], bh[2 * sub], bh[2 * sub + 1]);
                }
            }
        }
    }

    // epilogue: Xcat slice
#pragma unroll
    for (int mt = 0; mt < 2; mt++) {
        const size_t r0 = (size_t)z * N_ + m0 + m_off + mt * 16 + (lid >> 2);
        __half* x0 = Xs + r0 * XLD_;
        __half* x1 = Xs + (r0 + 8) * XLD_;
#pragma unroll
        for (int nt = 0; nt < 8; nt++) {
            const int cc = n_off + nt * 8 + (lid & 3) * 2;
            *(__half2*)(x0 + cc) = __floats2half2_rn(acc[mt][nt][0], acc[mt][nt][1]);
            *(__half2*)(x1 + cc) = __floats2half2_rn(acc[mt][nt][2], acc[mt][nt][3]);
        }
    }
}

// ---------------- rows GEMM: C = act( X·Wt + bias ) ----------
// ACT: 0 none, 1 softplus, 2 tanh, 3 mixed (j0<256 softplus else tanh), 4 gelu.
template <int ACT, bool BIAS, bool HOUT>
__global__ void __launch_bounds__(256, 2)
gemm_rows_hmma(const __half* __restrict__ X, const __half* __restrict__ W,
               const float* __restrict__ bias, void* __restrict__ Cv,
               int K, int lda, int ldb, int ldc)
{
    extern __shared__ char smem[];
    const uint32_t sbase = smem_u32_(smem);
    const int j0  = blockIdx.x * 128;
    const int r0  = blockIdx.y * 128;
    const int tid = threadIdx.x;
    const int wid = tid >> 5, lid = tid & 31;
    const int wm = wid & 3, wn = wid >> 2;
    const int m_off = wm * 32, n_off = wn * 64;

    const __half* gp[2] = { X + (size_t)r0 * lda, W + (size_t)j0 * ldb };

    auto load_stage = [&](int buf, int k0) {
        uint32_t base = sbase + buf * STAGEB_;
#pragma unroll
        for (int i = 0; i < 4; i++) {
            int idx = i * 256 + tid;
            int tile = idx >> 9;
            int rem = idx & 511;
            int r = rem >> 2, c = rem & 3;
            int ld = (tile == 0) ? lda : ldb;
            uint32_t dst = base + tile * TILEB_ + r * STRD_ + c * 16;
            const void* src = gp[tile] + (size_t)r * ld + k0 + c * 8;
            asm volatile("cp.async.cg.shared.global [%0], [%1], 16;" :: "r"(dst), "l"(src));
        }
        asm volatile("cp.async.commit_group;" ::: "memory");
    };

    float acc[2][8][4];
#pragma unroll
    for (int mt = 0; mt < 2; mt++)
#pragma unroll
        for (int nt = 0; nt < 8; nt++)
#pragma unroll
            for (int q = 0; q < 4; q++) acc[mt][nt][q] = 0.f;

    const int a_row = m_off + (lid & 15);
    const int a_kc  = (lid >> 4) << 3;
    const int b_row = n_off + ((lid >> 4) << 3) + (lid & 7);
    const int b_kc  = ((lid >> 3) & 1) << 3;

    const int NT = K >> 5;
    load_stage(0, 0);
    load_stage(1, 32);
    for (int kt = 0; kt < NT; kt++) {
        if (kt + 1 < NT) asm volatile("cp.async.wait_group 1;" ::: "memory");
        else             asm volatile("cp.async.wait_group 0;" ::: "memory");
        __syncthreads();
        if (kt + 2 < NT) load_stage((kt + 2) % NSTG_, (kt + 2) * 32);

        const uint32_t stg = sbase + (kt % NSTG_) * STAGEB_;
        const uint32_t bA = stg, bB = stg + TILEB_;
#pragma unroll
        for (int k16 = 0; k16 < 2; k16++) {
            const int kb = k16 * 16;
            uint32_t ah[2][4];
#pragma unroll
            for (int mt = 0; mt < 2; mt++)
                ldsm4_(ah[mt], bA + (uint32_t)((a_row + mt * 16) * STRD_ + (kb + a_kc) * 2));
#pragma unroll
            for (int pt = 0; pt < 4; pt++) {
                uint32_t bo = (uint32_t)((b_row + pt * 16) * STRD_ + (kb + b_kc) * 2);
                uint32_t bh[4];
                ldsm4_(bh, bB + bo);
#pragma unroll
                for (int mt = 0; mt < 2; mt++) {
#pragma unroll
                    for (int sub = 0; sub < 2; sub++)
                        mma16816_(acc[mt][pt * 2 + sub], ah[mt], bh[2 * sub], bh[2 * sub + 1]);
                }
            }
        }
    }

    auto ep = [&](float v, float b) -> float {
        if (BIAS) v += b;
        if (ACT == 1) v = softplusf_(v);
        else if (ACT == 2) v = tanhf(v);
        else if (ACT == 3) v = (j0 < 256) ? softplusf_(v) : tanhf(v);
        else if (ACT == 4) v = geluf_(v);
        return v;
    };
#pragma unroll
    for (int mt = 0; mt < 2; mt++) {
        const int r = r0 + m_off + mt * 16 + (lid >> 2);
#pragma unroll
        for (int nt = 0; nt < 8; nt++) {
            const int cc = n_off + nt * 8 + (lid & 3) * 2;
            float b0 = 0.f, b1 = 0.f;
            if (BIAS) { b0 = bias[j0 + cc]; b1 = bias[j0 + cc + 1]; }
            float v0 = ep(acc[mt][nt][0], b0), v1 = ep(acc[mt][nt][1], b1);
            float v2 = ep(acc[mt][nt][2], b0), v3 = ep(acc[mt][nt][3], b1);
            if (HOUT) {
                __half* c0 = (__half*)Cv + (size_t)r * ldc + j0 + cc;
                __half* c1 = (__half*)Cv + (size_t)(r + 8) * ldc + j0 + cc;
                *(__half2*)c0 = __floats2half2_rn(v0, v1);
                *(__half2*)c1 = __floats2half2_rn(v2, v3);
            } else {
                float* c0 = (float*)Cv + (size_t)r * ldc + j0 + cc;
                float* c1 = (float*)Cv + (size_t)(r + 8) * ldc + j0 + cc;
                *(float2*)c0 = make_float2(v0, v1);
                *(float2*)c1 = make_float2(v2, v3);
            }
        }
    }
}

// ---------------- causal depthwise conv (K=4) + SiLU; sig -> Xt cols 0..255 -----
__global__ void conv_silu_kernel(const __half* __restrict__ pr, const float* __restrict__ cw,
                                 const float* __restrict__ cb, __half* __restrict__ x)
{
    int idx = blockIdx.x * blockDim.x + threadIdx.x;
    int c = idx & (INNER_ - 1);
    int bn = idx >> 8;
    float w0 = cw[c * 4 + 0], w1 = cw[c * 4 + 1], w2 = cw[c * 4 + 2], w3 = cw[c * 4 + 3];
    float b = cb[c];
    float s[T_];
    size_t base = (size_t)bn * T_ * 512 + c;
#pragma unroll
    for (int t = 0; t < T_; t++) s[t] = __half2float(pr[base + (size_t)t * 512]);
    size_t ox = (size_t)bn * T_ * XTLD_ + c;
#pragma unroll
    for (int t = 0; t < T_; t++) {
        float a = b + w3 * s[t];
        if (t >= 1) a += w2 * s[t - 1];
        if (t >= 2) a += w1 * s[t - 2];
        if (t >= 3) a += w0 * s[t - 3];
        float v = a * sigmoidf_(a);
        x[ox + (size_t)t * XTLD_] = __float2half_rn(v);
    }
}

// ---------------- selective-scan + gating; reads Xt sig, overwrites with y ------
__global__ void scan_kernel(const __half* __restrict__ dso, const __half* __restrict__ pr,
                            const float* __restrict__ a_log, const float* __restrict__ d_skip,
                            __half* x)
{
    int idx = blockIdx.x * blockDim.x + threadIdx.x;
    int c = idx & (INNER_ - 1);
    int bn = idx >> 8;
    float a = -softplusf_(a_log[c]);
    float dsk = d_skip[c];
    float state = 0.f;
    size_t b768 = (size_t)bn * T_ * 768 + c;
    size_t b512 = (size_t)bn * T_ * 512 + c;
    size_t bx   = (size_t)bn * T_ * XTLD_ + c;
#pragma unroll
    for (int t = 0; t < T_; t++) {
        float xs = __half2float(x  [bx   + (size_t)t * XTLD_]);
        float d  = __half2float(dso[b768 + (size_t)t * 768]);
        float iv = __half2float(dso[b768 + (size_t)t * 768 + 256]);
        float ov = __half2float(dso[b768 + (size_t)t * 768 + 512]);
        float g  = __half2float(pr [b512 + (size_t)t * 512 + INNER_]);
        state = expf(d * a) * state + iv * xs;
        float yy = (ov * state + dsk * xs) * sigmoidf_(g);
        x[bx + (size_t)t * XTLD_] = __float2half_rn(yy);
    }
}

// ---------------- fusion + LayerNorm (sp already gelu'd); emits Xcat h slice ----
__global__ void fuse_ln_kernel(const float* __restrict__ h_in, const float* __restrict__ sp,
                               const float* __restrict__ tp,
                               const float* __restrict__ ln_g, const float* __restrict__ ln_b,
                               float* __restrict__ h_out, __half* __restrict__ xo)
{
    int token = blockIdx.x;
    int d = threadIdx.x;
    int n  = token % N_;
    int bt = token / N_;
    int t  = bt % T_;
    int b  = bt / T_;
    size_t row    = (size_t)token * D_;
    size_t row_tp = ((size_t)(b * N_ + n) * T_ + t) * D_;

    float hv = h_in[row + d];
    float s = sp[row + d];
    float tv = tp[row_tp + d];
    float f = hv + s + tv + s * tv;

    __shared__ float red[8];
    float v = f;
#pragma unroll
    for (int o = 16; o > 0; o >>= 1) v += __shfl_xor_sync(0xffffffffu, v, o);
    if ((d & 31) == 0) red[d >> 5] = v;
    __syncthreads();
    float mu = (red[0] + red[1] + red[2] + red[3]) * (1.f / 128.f);
    float dv = f - mu;
    v = dv * dv;
#pragma unroll
    for (int o = 16; o > 0; o >>= 1) v += __shfl_xor_sync(0xffffffffu, v, o);
    if ((d & 31) == 0) red[4 + (d >> 5)] = v;
    __syncthreads();
    float var = (red[4] + red[5] + red[6] + red[7]) * (1.f / 128.f);
    float out = dv * rsqrtf(var + 1e-5f) * ln_g[d] + ln_b[d];
    h_out[row + d] = out;
    xo[(size_t)token * XLD_ + d] = __float2half_rn(out);
}

// ---------------- host launcher ----------------
extern "C" void kernel_launch(void* const* d_in, const int* in_sizes, int n_in,
                              void* d_out, int out_size)
{
    (void)in_sizes; (void)n_in; (void)out_size;
    const float* inputs   = (const float*)d_in[0];
    const float* supports = (const float*)d_in[1];
    const float* gcn_w    = (const float*)d_in[2];
    const float* gcn_b    = (const float*)d_in[3];
    const float* in_w     = (const float*)d_in[4];
    const float* in_b     = (const float*)d_in[5];
    const float* conv_w   = (const float*)d_in[6];
    const float* conv_b   = (const float*)d_in[7];
    const float* delta_w  = (const float*)d_in[8];
    const float* delta_b  = (const float*)d_in[9];
    const float* si_w     = (const float*)d_in[10];
    const float* si_b     = (const float*)d_in[11];
    const float* so_w     = (const float*)d_in[12];
    const float* so_b     = (const float*)d_in[13];
    const float* a_log    = (const float*)d_in[14];
    const float* d_skip   = (const float*)d_in[15];
    const float* out_w    = (const float*)d_in[16];
    const float* out_b    = (const float*)d_in[17];
    const float* ln_g     = (const float*)d_in[18];
    const float* ln_b     = (const float*)d_in[19];

    float *sp, *h2, *tp, *bcat;
    __half *St, *Sh, *St2, *X, *Xt, *Wt, *Ht0, *pr, *dso;
    cudaGetSymbolAddress((void**)&sp,   g_sp);
    cudaGetSymbolAddress((void**)&h2,   g_h2);
    cudaGetSymbolAddress((void**)&tp,   g_tp);
    cudaGetSymbolAddress((void**)&bcat, g_bcat);
    cudaGetSymbolAddress((void**)&St,   g_St);
    cudaGetSymbolAddress((void**)&Sh,   g_Sh);
    cudaGetSymbolAddress((void**)&St2,  g_St2);
    cudaGetSymbolAddress((void**)&X,    g_X);
    cudaGetSymbolAddress((void**)&Xt,   g_Xt);
    cudaGetSymbolAddress((void**)&Wt,   g_Wt);
    cudaGetSymbolAddress((void**)&Ht0,  g_Ht0);
    cudaGetSymbolAddress((void**)&pr,   g_pr);
    cudaGetSymbolAddress((void**)&dso,  g_dso);

    static cudaStream_t s1 = nullptr;
    static cudaEvent_t evF[2], evJ[2];
    if (s1 == nullptr) {
        cudaStreamCreateWithFlags(&s1, cudaStreamNonBlocking);
        for (int i = 0; i < 2; i++) {
            cudaEventCreateWithFlags(&evF[i], cudaEventDisableTiming);
            cudaEventCreateWithFlags(&evJ[i], cudaEventDisableTiming);
        }
    }

    cudaFuncSetAttribute(gemm_support4, cudaFuncAttributeMaxDynamicSharedMemorySize, SMEM_MMA);
    cudaFuncSetAttribute(gemm_rows_hmma<0,true ,false>, cudaFuncAttributeMaxDynamicSharedMemorySize, SMEM_MMA);
    cudaFuncSetAttribute(gemm_rows_hmma<0,false,true >, cudaFuncAttributeMaxDynamicSharedMemorySize, SMEM_MMA);
    cudaFuncSetAttribute(gemm_rows_hmma<0,true ,true >, cudaFuncAttributeMaxDynamicSharedMemorySize, SMEM_MMA);
    cudaFuncSetAttribute(gemm_rows_hmma<3,true ,true >, cudaFuncAttributeMaxDynamicSharedMemorySize, SMEM_MMA);
    cudaFuncSetAttribute(gemm_rows_hmma<4,true ,false>, cudaFuncAttributeMaxDynamicSharedMemorySize, SMEM_MMA);

    const dim3 blk(256);
    const dim3 gmma4(64, BT_);
    const dim3 gcvH(64, 4, BT_);
    const dim3 gr1(1, ROWS_ / 128);
    const dim3 gr4(4, ROWS_ / 128);
    const dim3 gr6(6, ROWS_ / 128);
    const int ew_blocks = (BN_ * INNER_) / 256;

    // ---- prologue: conversions + S^2 precompute ----
    convt_S<<<dim3(64, 64, 2), blk>>>(supports, St);
    conv_copy<<<(int)(2 * NN_ / 512), blk>>>(supports, Sh);
    for (int l = 0; l < 2; l++) {
        __half* w = Wt + (size_t)l * WSZ_L;
        convt_W<<<dim3(20, 4), blk>>>(gcn_w  + (size_t)l * 640 * 128, 640, 128, w + WOFF_GCN);
        convt_W<<<dim3(4, 16), blk>>>(in_w   + (size_t)l * 128 * 512, 128, 512, w + WOFF_IN);
        convt_W<<<dim3(8, 8),  blk>>>(delta_w + (size_t)l * 256 * 256, 256, 256, w + WOFF_DL);
        convt_W<<<dim3(8, 8),  blk>>>(si_w    + (size_t)l * 256 * 256, 256, 256, w + WOFF_DL + 65536);
        convt_W<<<dim3(8, 8),  blk>>>(so_w    + (size_t)l * 256 * 256, 256, 256, w + WOFF_DL + 131072);
        convt_W<<<dim3(8, 4),  blk>>>(out_w   + (size_t)l * 256 * 128, 256, 128, w + WOFF_OUT);
    }
    bias_cat<<<2, 768>>>(delta_b, si_b, so_b, bcat);
    conv_plain<<<(int)(SZ_H / 512), blk>>>(inputs, X);
    // St2_i = St_i · S_i  (fp16 out): C[m,p] = sum_k St[m,k]·S[p,k]
    gemm_rows_hmma<0,false,true><<<dim3(16, 16), blk, SMEM_MMA>>>(St,       Sh,       nullptr, St2,       2048, 2048, 2048, 2048);
    gemm_rows_hmma<0,false,true><<<dim3(16, 16), blk, SMEM_MMA>>>(St + NN_, Sh + NN_, nullptr, St2 + NN_, 2048, 2048, 2048, 2048);

    for (int l = 0; l < 2; l++) {
        const float* h_in  = (l == 0) ? inputs : h2;
        float*       h_out = (l == 0) ? h2 : (float*)d_out;
        const __half* w = Wt + (size_t)l * WSZ_L;
        const float* gb  = gcn_b  + l * 128;
        const float* ib  = in_b   + l * 512;
        const float* cw  = conv_w + (size_t)l * INNER_ * 4;
        const float* cb  = conv_b + l * INNER_;
        const float* al  = a_log  + l * INNER_;
        const float* dsk = d_skip + l * INNER_;
        const float* ob  = out_b + l * 128;
        const float* lg  = ln_g + l * 128;
        const float* lb  = ln_b + l * 128;

        // ---- fork: temporal branch on s1 ----
        cudaEventRecord(evF[l], 0);
        cudaStreamWaitEvent(s1, evF[l], 0);
        transpose_convert_bt<<<(ROWS_ * 32) / 256, 256, 0, s1>>>(h_in, Xt);
        gemm_rows_hmma<0,true,true ><<<gr4, blk, SMEM_MMA, s1>>>(Xt, w + WOFF_IN, ib, pr, 128, XTLD_, 128, 512);
        conv_silu_kernel<<<ew_blocks, 256, 0, s1>>>(pr, cw, cb, Xt);
        gemm_rows_hmma<3,true,true ><<<gr6, blk, SMEM_MMA, s1>>>(Xt, w + WOFF_DL, bcat + l * 768, dso, 256, XTLD_, 256, 768);
        scan_kernel<<<ew_blocks, 256, 0, s1>>>(dso, pr, al, dsk, Xt);
        gemm_rows_hmma<0,true,false><<<gr1, blk, SMEM_MMA, s1>>>(Xt, w + WOFF_OUT, ob, tp, 256, XTLD_, 256, 128);
        cudaEventRecord(evJ[l], s1);

        // ---- spatial branch: convt_H -> ONE 4-way einsum -> gcn GEMM (bias+gelu) ----
        convt_H<<<gcvH, blk>>>(h_in, Ht0);
        gemm_support4<<<gmma4, blk, SMEM_MMA>>>(St, St2, St + NN_, St2 + NN_, Ht0, X);
        gemm_rows_hmma<4,true,false><<<gr1, blk, SMEM_MMA>>>(X, w + WOFF_GCN, gb, sp, 640, XLD_, 640, 128);

        // ---- join + fusion/layernorm ----
        cudaStreamWaitEvent(0, evJ[l], 0);
        fuse_ln_kernel<<<ROWS_, 128>>>(h_in, sp, tp, lg, lb, h_out, X);
    }
}

// round 12
// speedup vs baseline: 5.4303x; 1.1280x over previous
#include <cuda_runtime.h>
#include <cuda_fp16.h>
#include <math.h>
#include <stdint.h>

// ---------------- problem constants ----------------
#define B_    16
#define T_    12
#define N_    2048
#define D_    128
#define INNER_ 256
#define BT_   (B_*T_)          // 192
#define ROWS_ (B_*T_*N_)       // 393216
#define BN_   (B_*N_)          // 32768
#define NN_   ((size_t)N_*N_)
#define XLD_  640              // Xcat row stride (spatial concat)
#define XTLD_ 256              // Xt row stride (temporal)

// ---------------- scratch (device globals) ----------------
#define SZ_H  ((size_t)ROWS_*D_)
#define SZ_PR ((size_t)ROWS_*512)
#define SZ_DSO ((size_t)ROWS_*768)
#define SZ_X  ((size_t)ROWS_*XLD_)
#define SZ_XT ((size_t)ROWS_*XTLD_)
#define SZ_HT ((size_t)BT_*D_*N_)

__device__ __align__(16) float g_h2  [SZ_H];
__device__ __align__(16) float g_bcat[2*768];

__device__ __align__(16) __half g_sp [SZ_H];    // fp16 spatial branch output (post-gelu)
__device__ __align__(16) __half g_tp [SZ_H];    // fp16 temporal branch output
__device__ __align__(16) __half g_pr [SZ_PR];   // fp16: cols 0..255 signal, 256..511 gate
__device__ __align__(16) __half g_dso[SZ_DSO];  // fp16: delta | si | so
__device__ __align__(16) __half g_X  [SZ_X];    // spatial concat activations [M][640]
__device__ __align__(16) __half g_Xt [SZ_XT];   // temporal activations [bn*T+t][256]
__device__ __align__(16) __half g_St [2*NN_];   // S^T fp16 [i][m][k]
__device__ __align__(16) __half g_Sh [2*NN_];   // S  fp16 row-major [i][k][n]
__device__ __align__(16) __half g_St2[2*NN_];   // (S^2)^T fp16 [i][m][k]
__device__ __align__(16) __half g_Ht0[SZ_HT];   // Ht(h)

// transposed weights per layer (fp16); dl/si/so contiguous => fused N=768 GEMM
#define WOFF_GCN 0
#define WOFF_IN  81920
#define WOFF_DL  147456
#define WOFF_OUT 344064
#define WSZ_L    376832
__device__ __align__(16) __half g_Wt[2*WSZ_L];

// ---------------- helpers ----------------
__device__ __forceinline__ float sigmoidf_(float x) { return 1.f / (1.f + expf(-x)); }
__device__ __forceinline__ float softplusf_(float x) {
    return fmaxf(x, 0.f) + log1pf(expf(-fabsf(x)));
}
__device__ __forceinline__ float geluf_(float x) {
    return 0.5f * x * (1.f + erff(x * 0.7071067811865475f));
}
__device__ __forceinline__ uint32_t smem_u32_(const void* p) {
    uint32_t a;
    asm("{ .reg .u64 t; cvta.to.shared.u64 t, %1; cvt.u32.u64 %0, t; }" : "=r"(a) : "l"(p));
    return a;
}
__device__ __forceinline__ void ldsm4_(uint32_t* r, uint32_t a) {
    asm volatile("ldmatrix.sync.aligned.m8n8.x4.shared.b16 {%0,%1,%2,%3}, [%4];"
        : "=r"(r[0]), "=r"(r[1]), "=r"(r[2]), "=r"(r[3]) : "r"(a));
}
__device__ __forceinline__ void mma16816_(float* d, const uint32_t* a, uint32_t b0, uint32_t b1) {
    asm volatile(
        "mma.sync.aligned.m16n8k16.row.col.f32.f16.f16.f32 "
        "{%0,%1,%2,%3}, {%4,%5,%6,%7}, {%8,%9}, {%0,%1,%2,%3};"
        : "+f"(d[0]), "+f"(d[1]), "+f"(d[2]), "+f"(d[3])
        : "r"(a[0]), "r"(a[1]), "r"(a[2]), "r"(a[3]), "r"(b0), "r"(b1));
}
// swizzled tile address: tile is 128 rows x 64 k fp16 (128B/row, 8 granules of 16B)
__device__ __forceinline__ uint32_t swadr_(uint32_t base, int row, int g) {
    return base + (uint32_t)(row * 128 + ((g ^ (row & 7)) << 4));
}

// ---------------- conversions ----------------
__global__ void convt_S(const float* __restrict__ S, __half* __restrict__ out)
{
    __shared__ float t[32][33];
    const int k0 = blockIdx.x * 32, m0 = blockIdx.y * 32, i = blockIdx.z;
    const int tx = threadIdx.x & 31, ty = threadIdx.x >> 5;
    const float* Si = S + (size_t)i * NN_;
    for (int r = ty; r < 32; r += 8)
        t[r][tx] = Si[(size_t)(k0 + r) * N_ + m0 + tx];
    __syncthreads();
    for (int r = ty; r < 32; r += 8) {
        size_t o = (size_t)i * NN_ + (size_t)(m0 + r) * N_ + k0 + tx;
        out[o] = __float2half_rn(t[tx][r]);
    }
}
__global__ void conv_copy(const float* __restrict__ src, __half* __restrict__ dst)
{
    size_t e = ((size_t)blockIdx.x * blockDim.x + threadIdx.x) * 2;
    float2 v = *(const float2*)(src + e);
    *(__half2*)(dst + e) = __floats2half2_rn(v.x, v.y);
}
__global__ void convt_H(const float* __restrict__ H, __half* __restrict__ out)
{
    __shared__ float t[32][33];
    const int n0 = blockIdx.x * 32, d0 = blockIdx.y * 32, z = blockIdx.z;
    const int tx = threadIdx.x & 31, ty = threadIdx.x >> 5;
    const float* Hz = H + (size_t)z * N_ * D_;
    for (int r = ty; r < 32; r += 8)
        t[r][tx] = Hz[(size_t)(n0 + r) * D_ + d0 + tx];
    __syncthreads();
    for (int r = ty; r < 32; r += 8) {
        size_t o = ((size_t)z * D_ + d0 + r) * N_ + n0 + tx;
        out[o] = __float2half_rn(t[tx][r]);
    }
}
__global__ void convt_W(const float* __restrict__ W, int K, int N, __half* __restrict__ out)
{
    __shared__ float t[32][33];
    const int k0 = blockIdx.x * 32, n0 = blockIdx.y * 32;
    const int tx = threadIdx.x & 31, ty = threadIdx.x >> 5;
    for (int r = ty; r < 32; r += 8)
        t[r][tx] = W[(size_t)(k0 + r) * N + n0 + tx];
    __syncthreads();
    for (int r = ty; r < 32; r += 8) {
        size_t o = (size_t)(n0 + r) * K + k0 + tx;
        out[o] = __float2half_rn(t[tx][r]);
    }
}
__global__ void bias_cat(const float* __restrict__ d, const float* __restrict__ s,
                         const float* __restrict__ o, float* __restrict__ out)
{
    int l = blockIdx.x, t = threadIdx.x;
    const float* src = (t < 256) ? d : ((t < 512) ? s : o);
    out[l * 768 + t] = src[l * 256 + (t & 255)];
}
__global__ void conv_plain(const float* __restrict__ src, __half* __restrict__ x)
{
    size_t e = ((size_t)blockIdx.x * blockDim.x + threadIdx.x) * 2;
    size_t row = e >> 7;
    int col = (int)(e & 127);
    float2 v = *(const float2*)(src + e);
    *(__half2*)(x + row * XLD_ + col) = __floats2half2_rn(v.x, v.y);
}
__global__ void transpose_convert_bt(const float* __restrict__ h, __half* __restrict__ x)
{
    size_t gid = (size_t)blockIdx.x * blockDim.x + threadIdx.x;
    int q = (int)(gid & 31);
    int r = (int)(gid >> 5);
    int t = r % T_;
    int bn = r / T_;
    int n = bn % N_;
    int b = bn / N_;
    size_t src = ((size_t)((b * T_ + t) * N_) + n) * D_ + q * 4;
    float4 v = *(const float4*)(h + src);
    size_t o = (size_t)r * XTLD_ + q * 4;
    *(__half2*)(x + o)     = __floats2half2_rn(v.x, v.y);
    *(__half2*)(x + o + 2) = __floats2half2_rn(v.z, v.w);
}

// ---------------- HMMA GEMM infrastructure (k64, swizzled, 3-stage) ----------------
#define TILEB_ 16384                  // 128 rows x 128B
#define STAGEB_ (2 * TILEB_)          // 32768
#define NSTG_ 3
#define SMEM_MMA (NSTG_ * STAGEB_)    // 98304

// ---------------- 4-way support einsum (one launch, all independent) -----------
__global__ void __launch_bounds__(256, 2)
gemm_support4(const __half* __restrict__ A0, const __half* __restrict__ A1,
              const __half* __restrict__ A2, const __half* __restrict__ A3,
              const __half* __restrict__ Bm, __half* __restrict__ Xb)
{
    extern __shared__ char smem[];
    const uint32_t sbase = smem_u32_(smem);
    const int q   = blockIdx.x >> 4;
    const int m0  = (blockIdx.x & 15) * 128;
    const int z   = blockIdx.y;
    const int tid = threadIdx.x;
    const int wid = tid >> 5, lid = tid & 31;
    const int wm = wid & 3, wn = wid >> 2;
    const int m_off = wm * 32, n_off = wn * 64;

    const __half* Aq = (q == 0) ? A0 : (q == 1) ? A1 : (q == 2) ? A2 : A3;
    __half* Xs = Xb + 128 * (q + 1);
    const __half* gp[2] = { Aq + (size_t)m0 * N_, Bm + (size_t)z * D_ * N_ };

    auto load_stage = [&](int buf, int k0) {
        uint32_t base = sbase + buf * STAGEB_;
#pragma unroll
        for (int i = 0; i < 8; i++) {
            int idx = i * 256 + tid;          // 0..2047
            int tile = idx >> 10;
            int rem = idx & 1023;
            int r = rem >> 3, g = rem & 7;
            uint32_t dst = swadr_(base + tile * TILEB_, r, g);
            const void* src = gp[tile] + (size_t)r * N_ + k0 + g * 8;
            asm volatile("cp.async.cg.shared.global [%0], [%1], 16;" :: "r"(dst), "l"(src));
        }
        asm volatile("cp.async.commit_group;" ::: "memory");
    };

    float acc[2][8][4];
#pragma unroll
    for (int mt = 0; mt < 2; mt++)
#pragma unroll
        for (int nt = 0; nt < 8; nt++)
#pragma unroll
            for (int qq = 0; qq < 4; qq++) acc[mt][nt][qq] = 0.f;

    const int a_row = m_off + (lid & 15);
    const int a_g   = (lid >> 4);             // granule offset within k16 (8 fp16 = 1 granule)
    const int b_row = n_off + ((lid >> 4) << 3) + (lid & 7);
    const int b_g   = ((lid >> 3) & 1);

    const int NT = N_ / 64;                   // 32
    load_stage(0, 0);
    load_stage(1, 64);
    for (int kt = 0; kt < NT; kt++) {
        if (kt + 1 < NT) asm volatile("cp.async.wait_group 1;" ::: "memory");
        else             asm volatile("cp.async.wait_group 0;" ::: "memory");
        __syncthreads();
        if (kt + 2 < NT) load_stage((kt + 2) % NSTG_, (kt + 2) * 64);

        const uint32_t stg = sbase + (kt % NSTG_) * STAGEB_;
        const uint32_t bA = stg, bB = stg + TILEB_;
#pragma unroll
        for (int k16 = 0; k16 < 4; k16++) {
            const int gb = k16 * 2;           // granule base for this k16
            uint32_t ah[2][4];
#pragma unroll
            for (int mt = 0; mt < 2; mt++)
                ldsm4_(ah[mt], swadr_(bA, a_row + mt * 16, gb + a_g));
#pragma unroll
            for (int pt = 0; pt < 4; pt++) {
                uint32_t bh[4];
                ldsm4_(bh, swadr_(bB, b_row + pt * 16, gb + b_g));
#pragma unroll
                for (int mt = 0; mt < 2; mt++) {
#pragma unroll
                    for (int sub = 0; sub < 2; sub++)
                        mma16816_(acc[mt][pt * 2 + sub], ah[mt], bh[2 * sub], bh[2 * sub + 1]);
                }
            }
        }
    }

    // epilogue: Xcat slice
#pragma unroll
    for (int mt = 0; mt < 2; mt++) {
        const size_t r0 = (size_t)z * N_ + m0 + m_off + mt * 16 + (lid >> 2);
        __half* x0 = Xs + r0 * XLD_;
        __half* x1 = Xs + (r0 + 8) * XLD_;
#pragma unroll
        for (int nt = 0; nt < 8; nt++) {
            const int cc = n_off + nt * 8 + (lid & 3) * 2;
            *(__half2*)(x0 + cc) = __floats2half2_rn(acc[mt][nt][0], acc[mt][nt][1]);
            *(__half2*)(x1 + cc) = __floats2half2_rn(acc[mt][nt][2], acc[mt][nt][3]);
        }
    }
}

// ---------------- rows GEMM: C = act( X·Wt + bias ) ----------
// ACT: 0 none, 1 softplus, 2 tanh, 3 mixed (j0<256 softplus else tanh), 4 gelu.
template <int ACT, bool BIAS, bool HOUT>
__global__ void __launch_bounds__(256, 2)
gemm_rows_hmma(const __half* __restrict__ X, const __half* __restrict__ W,
               const float* __restrict__ bias, void* __restrict__ Cv,
               int K, int lda, int ldb, int ldc)
{
    extern __shared__ char smem[];
    const uint32_t sbase = smem_u32_(smem);
    const int j0  = blockIdx.x * 128;
    const int r0  = blockIdx.y * 128;
    const int tid = threadIdx.x;
    const int wid = tid >> 5, lid = tid & 31;
    const int wm = wid & 3, wn = wid >> 2;
    const int m_off = wm * 32, n_off = wn * 64;

    const __half* gp[2] = { X + (size_t)r0 * lda, W + (size_t)j0 * ldb };

    auto load_stage = [&](int buf, int k0) {
        uint32_t base = sbase + buf * STAGEB_;
#pragma unroll
        for (int i = 0; i < 8; i++) {
            int idx = i * 256 + tid;
            int tile = idx >> 10;
            int rem = idx & 1023;
            int r = rem >> 3, g = rem & 7;
            int ld = (tile == 0) ? lda : ldb;
            uint32_t dst = swadr_(base + tile * TILEB_, r, g);
            const void* src = gp[tile] + (size_t)r * ld + k0 + g * 8;
            asm volatile("cp.async.cg.shared.global [%0], [%1], 16;" :: "r"(dst), "l"(src));
        }
        asm volatile("cp.async.commit_group;" ::: "memory");
    };

    float acc[2][8][4];
#pragma unroll
    for (int mt = 0; mt < 2; mt++)
#pragma unroll
        for (int nt = 0; nt < 8; nt++)
#pragma unroll
            for (int q = 0; q < 4; q++) acc[mt][nt][q] = 0.f;

    const int a_row = m_off + (lid & 15);
    const int a_g   = (lid >> 4);
    const int b_row = n_off + ((lid >> 4) << 3) + (lid & 7);
    const int b_g   = ((lid >> 3) & 1);

    const int NT = K >> 6;
    load_stage(0, 0);
    load_stage(1, 64);
    for (int kt = 0; kt < NT; kt++) {
        if (kt + 1 < NT) asm volatile("cp.async.wait_group 1;" ::: "memory");
        else             asm volatile("cp.async.wait_group 0;" ::: "memory");
        __syncthreads();
        if (kt + 2 < NT) load_stage((kt + 2) % NSTG_, (kt + 2) * 64);

        const uint32_t stg = sbase + (kt % NSTG_) * STAGEB_;
        const uint32_t bA = stg, bB = stg + TILEB_;
#pragma unroll
        for (int k16 = 0; k16 < 4; k16++) {
            const int gb = k16 * 2;
            uint32_t ah[2][4];
#pragma unroll
            for (int mt = 0; mt < 2; mt++)
                ldsm4_(ah[mt], swadr_(bA, a_row + mt * 16, gb + a_g));
#pragma unroll
            for (int pt = 0; pt < 4; pt++) {
                uint32_t bh[4];
                ldsm4_(bh, swadr_(bB, b_row + pt * 16, gb + b_g));
#pragma unroll
                for (int mt = 0; mt < 2; mt++) {
#pragma unroll
                    for (int sub = 0; sub < 2; sub++)
                        mma16816_(acc[mt][pt * 2 + sub], ah[mt], bh[2 * sub], bh[2 * sub + 1]);
                }
            }
        }
    }

    auto ep = [&](float v, float b) -> float {
        if (BIAS) v += b;
        if (ACT == 1) v = softplusf_(v);
        else if (ACT == 2) v = tanhf(v);
        else if (ACT == 3) v = (j0 < 256) ? softplusf_(v) : tanhf(v);
        else if (ACT == 4) v = geluf_(v);
        return v;
    };
#pragma unroll
    for (int mt = 0; mt < 2; mt++) {
        const int r = r0 + m_off + mt * 16 + (lid >> 2);
#pragma unroll
        for (int nt = 0; nt < 8; nt++) {
            const int cc = n_off + nt * 8 + (lid & 3) * 2;
            float b0 = 0.f, b1 = 0.f;
            if (BIAS) { b0 = bias[j0 + cc]; b1 = bias[j0 + cc + 1]; }
            float v0 = ep(acc[mt][nt][0], b0), v1 = ep(acc[mt][nt][1], b1);
            float v2 = ep(acc[mt][nt][2], b0), v3 = ep(acc[mt][nt][3], b1);
            if (HOUT) {
                __half* c0 = (__half*)Cv + (size_t)r * ldc + j0 + cc;
                __half* c1 = (__half*)Cv + (size_t)(r + 8) * ldc + j0 + cc;
                *(__half2*)c0 = __floats2half2_rn(v0, v1);
                *(__half2*)c1 = __floats2half2_rn(v2, v3);
            } else {
                float* c0 = (float*)Cv + (size_t)r * ldc + j0 + cc;
                float* c1 = (float*)Cv + (size_t)(r + 8) * ldc + j0 + cc;
                *(float2*)c0 = make_float2(v0, v1);
                *(float2*)c1 = make_float2(v2, v3);
            }
        }
    }
}

// ---------------- causal depthwise conv (K=4) + SiLU; sig -> Xt cols 0..255 -----
__global__ void conv_silu_kernel(const __half* __restrict__ pr, const float* __restrict__ cw,
                                 const float* __restrict__ cb, __half* __restrict__ x)
{
    int idx = blockIdx.x * blockDim.x + threadIdx.x;
    int c = idx & (INNER_ - 1);
    int bn = idx >> 8;
    float w0 = cw[c * 4 + 0], w1 = cw[c * 4 + 1], w2 = cw[c * 4 + 2], w3 = cw[c * 4 + 3];
    float b = cb[c];
    float s[T_];
    size_t base = (size_t)bn * T_ * 512 + c;
#pragma unroll
    for (int t = 0; t < T_; t++) s[t] = __half2float(pr[base + (size_t)t * 512]);
    size_t ox = (size_t)bn * T_ * XTLD_ + c;
#pragma unroll
    for (int t = 0; t < T_; t++) {
        float a = b + w3 * s[t];
        if (t >= 1) a += w2 * s[t - 1];
        if (t >= 2) a += w1 * s[t - 2];
        if (t >= 3) a += w0 * s[t - 3];
        float v = a * sigmoidf_(a);
        x[ox + (size_t)t * XTLD_] = __float2half_rn(v);
    }
}

// ---------------- selective-scan + gating; reads Xt sig, overwrites with y ------
__global__ void scan_kernel(const __half* __restrict__ dso, const __half* __restrict__ pr,
                            const float* __restrict__ a_log, const float* __restrict__ d_skip,
                            __half* x)
{
    int idx = blockIdx.x * blockDim.x + threadIdx.x;
    int c = idx & (INNER_ - 1);
    int bn = idx >> 8;
    float a = -softplusf_(a_log[c]);
    float dsk = d_skip[c];
    float state = 0.f;
    size_t b768 = (size_t)bn * T_ * 768 + c;
    size_t b512 = (size_t)bn * T_ * 512 + c;
    size_t bx   = (size_t)bn * T_ * XTLD_ + c;
#pragma unroll
    for (int t = 0; t < T_; t++) {
        float xs = __half2float(x  [bx   + (size_t)t * XTLD_]);
        float d  = __half2float(dso[b768 + (size_t)t * 768]);
        float iv = __half2float(dso[b768 + (size_t)t * 768 + 256]);
        float ov = __half2float(dso[b768 + (size_t)t * 768 + 512]);
        float g  = __half2float(pr [b512 + (size_t)t * 512 + INNER_]);
        state = expf(d * a) * state + iv * xs;
        float yy = (ov * state + dsk * xs) * sigmoidf_(g);
        x[bx + (size_t)t * XTLD_] = __float2half_rn(yy);
    }
}

// ---------------- fusion + LayerNorm (sp gelu'd fp16, tp fp16); emits X h slice --
__global__ void fuse_ln_kernel(const float* __restrict__ h_in, const __half* __restrict__ sp,
                               const __half* __restrict__ tp,
                               const float* __restrict__ ln_g, const float* __restrict__ ln_b,
                               float* __restrict__ h_out, __half* __restrict__ xo)
{
    int token = blockIdx.x;
    int d = threadIdx.x;
    int n  = token % N_;
    int bt = token / N_;
    int t  = bt % T_;
    int b  = bt / T_;
    size_t row    = (size_t)token * D_;
    size_t row_tp = ((size_t)(b * N_ + n) * T_ + t) * D_;

    float hv = h_in[row + d];
    float s = __half2float(sp[row + d]);
    float tv = __half2float(tp[row_tp + d]);
    float f = hv + s + tv + s * tv;

    __shared__ float red[8];
    float v = f;
#pragma unroll
    for (int o = 16; o > 0; o >>= 1) v += __shfl_xor_sync(0xffffffffu, v, o);
    if ((d & 31) == 0) red[d >> 5] = v;
    __syncthreads();
    float mu = (red[0] + red[1] + red[2] + red[3]) * (1.f / 128.f);
    float dv = f - mu;
    v = dv * dv;
#pragma unroll
    for (int o = 16; o > 0; o >>= 1) v += __shfl_xor_sync(0xffffffffu, v, o);
    if ((d & 31) == 0) red[4 + (d >> 5)] = v;
    __syncthreads();
    float var = (red[4] + red[5] + red[6] + red[7]) * (1.f / 128.f);
    float out = dv * rsqrtf(var + 1e-5f) * ln_g[d] + ln_b[d];
    h_out[row + d] = out;
    xo[(size_t)token * XLD_ + d] = __float2half_rn(out);
}

// ---------------- host launcher ----------------
extern "C" void kernel_launch(void* const* d_in, const int* in_sizes, int n_in,
                              void* d_out, int out_size)
{
    (void)in_sizes; (void)n_in; (void)out_size;
    const float* inputs   = (const float*)d_in[0];
    const float* supports = (const float*)d_in[1];
    const float* gcn_w    = (const float*)d_in[2];
    const float* gcn_b    = (const float*)d_in[3];
    const float* in_w     = (const float*)d_in[4];
    const float* in_b     = (const float*)d_in[5];
    const float* conv_w   = (const float*)d_in[6];
    const float* conv_b   = (const float*)d_in[7];
    const float* delta_w  = (const float*)d_in[8];
    const float* delta_b  = (const float*)d_in[9];
    const float* si_w     = (const float*)d_in[10];
    const float* si_b     = (const float*)d_in[11];
    const float* so_w     = (const float*)d_in[12];
    const float* so_b     = (const float*)d_in[13];
    const float* a_log    = (const float*)d_in[14];
    const float* d_skip   = (const float*)d_in[15];
    const float* out_w    = (const float*)d_in[16];
    const float* out_b    = (const float*)d_in[17];
    const float* ln_g     = (const float*)d_in[18];
    const float* ln_b     = (const float*)d_in[19];

    float *h2, *bcat;
    __half *sp, *tp, *St, *Sh, *St2, *X, *Xt, *Wt, *Ht0, *pr, *dso;
    cudaGetSymbolAddress((void**)&h2,   g_h2);
    cudaGetSymbolAddress((void**)&bcat, g_bcat);
    cudaGetSymbolAddress((void**)&sp,   g_sp);
    cudaGetSymbolAddress((void**)&tp,   g_tp);
    cudaGetSymbolAddress((void**)&St,   g_St);
    cudaGetSymbolAddress((void**)&Sh,   g_Sh);
    cudaGetSymbolAddress((void**)&St2,  g_St2);
    cudaGetSymbolAddress((void**)&X,    g_X);
    cudaGetSymbolAddress((void**)&Xt,   g_Xt);
    cudaGetSymbolAddress((void**)&Wt,   g_Wt);
    cudaGetSymbolAddress((void**)&Ht0,  g_Ht0);
    cudaGetSymbolAddress((void**)&pr,   g_pr);
    cudaGetSymbolAddress((void**)&dso,  g_dso);

    static cudaStream_t s1 = nullptr;
    static cudaEvent_t evF[2], evJ[2];
    if (s1 == nullptr) {
        cudaStreamCreateWithFlags(&s1, cudaStreamNonBlocking);
        for (int i = 0; i < 2; i++) {
            cudaEventCreateWithFlags(&evF[i], cudaEventDisableTiming);
            cudaEventCreateWithFlags(&evJ[i], cudaEventDisableTiming);
        }
    }

    cudaFuncSetAttribute(gemm_support4, cudaFuncAttributeMaxDynamicSharedMemorySize, SMEM_MMA);
    cudaFuncSetAttribute(gemm_rows_hmma<0,true ,true >, cudaFuncAttributeMaxDynamicSharedMemorySize, SMEM_MMA);
    cudaFuncSetAttribute(gemm_rows_hmma<0,false,true >, cudaFuncAttributeMaxDynamicSharedMemorySize, SMEM_MMA);
    cudaFuncSetAttribute(gemm_rows_hmma<3,true ,true >, cudaFuncAttributeMaxDynamicSharedMemorySize, SMEM_MMA);
    cudaFuncSetAttribute(gemm_rows_hmma<4,true ,true >, cudaFuncAttributeMaxDynamicSharedMemorySize, SMEM_MMA);

    const dim3 blk(256);
    const dim3 gmma4(64, BT_);
    const dim3 gcvH(64, 4, BT_);
    const dim3 gr1(1, ROWS_ / 128);
    const dim3 gr4(4, ROWS_ / 128);
    const dim3 gr6(6, ROWS_ / 128);
    const int ew_blocks = (BN_ * INNER_) / 256;

    // ---- prologue phase 1: temporal-needed conversions, then fork layer-0 temporal ----
    for (int l = 0; l < 2; l++) {
        __half* w = Wt + (size_t)l * WSZ_L;
        convt_W<<<dim3(4, 16), blk>>>(in_w   + (size_t)l * 128 * 512, 128, 512, w + WOFF_IN);
        convt_W<<<dim3(8, 8),  blk>>>(delta_w + (size_t)l * 256 * 256, 256, 256, w + WOFF_DL);
        convt_W<<<dim3(8, 8),  blk>>>(si_w    + (size_t)l * 256 * 256, 256, 256, w + WOFF_DL + 65536);
        convt_W<<<dim3(8, 8),  blk>>>(so_w    + (size_t)l * 256 * 256, 256, 256, w + WOFF_DL + 131072);
        convt_W<<<dim3(8, 4),  blk>>>(out_w   + (size_t)l * 256 * 128, 256, 128, w + WOFF_OUT);
    }
    bias_cat<<<2, 768>>>(delta_b, si_b, so_b, bcat);
    cudaEventRecord(evF[0], 0);

    // ---- prologue phase 2: spatial setup (overlaps layer-0 temporal) ----
    for (int l = 0; l < 2; l++)
        convt_W<<<dim3(20, 4), blk>>>(gcn_w + (size_t)l * 640 * 128, 640, 128,
                                      Wt + (size_t)l * WSZ_L + WOFF_GCN);
    convt_S<<<dim3(64, 64, 2), blk>>>(supports, St);
    conv_copy<<<(int)(2 * NN_ / 512), blk>>>(supports, Sh);
    conv_plain<<<(int)(SZ_H / 512), blk>>>(inputs, X);
    gemm_rows_hmma<0,false,true><<<dim3(16, 16), blk, SMEM_MMA>>>(St,       Sh,       nullptr, St2,       2048, 2048, 2048, 2048);
    gemm_rows_hmma<0,false,true><<<dim3(16, 16), blk, SMEM_MMA>>>(St + NN_, Sh + NN_, nullptr, St2 + NN_, 2048, 2048, 2048, 2048);

    for (int l = 0; l < 2; l++) {
        const float* h_in  = (l == 0) ? inputs : h2;
        float*       h_out = (l == 0) ? h2 : (float*)d_out;
        const __half* w = Wt + (size_t)l * WSZ_L;
        const float* gb  = gcn_b  + l * 128;
        const float* ib  = in_b   + l * 512;
        const float* cw  = conv_w + (size_t)l * INNER_ * 4;
        const float* cb  = conv_b + l * INNER_;
        const float* al  = a_log  + l * INNER_;
        const float* dsk = d_skip + l * INNER_;
        const float* ob  = out_b + l * 128;
        const float* lg  = ln_g + l * 128;
        const float* lb  = ln_b + l * 128;

        // ---- fork: temporal branch on s1 ----
        if (l > 0) cudaEventRecord(evF[l], 0);
        cudaStreamWaitEvent(s1, evF[l], 0);
        transpose_convert_bt<<<(ROWS_ * 32) / 256, 256, 0, s1>>>(h_in, Xt);
        gemm_rows_hmma<0,true,true ><<<gr4, blk, SMEM_MMA, s1>>>(Xt, w + WOFF_IN, ib, pr, 128, XTLD_, 128, 512);
        conv_silu_kernel<<<ew_blocks, 256, 0, s1>>>(pr, cw, cb, Xt);
        gemm_rows_hmma<3,true,true ><<<gr6, blk, SMEM_MMA, s1>>>(Xt, w + WOFF_DL, bcat + l * 768, dso, 256, XTLD_, 256, 768);
        scan_kernel<<<ew_blocks, 256, 0, s1>>>(dso, pr, al, dsk, Xt);
        gemm_rows_hmma<0,true,true ><<<gr1, blk, SMEM_MMA, s1>>>(Xt, w + WOFF_OUT, ob, tp, 256, XTLD_, 256, 128);
        cudaEventRecord(evJ[l], s1);

        // ---- spatial branch: convt_H -> 4-way einsum -> gcn GEMM (bias+gelu, fp16 out) ----
        convt_H<<<gcvH, blk>>>(h_in, Ht0);
        gemm_support4<<<gmma4, blk, SMEM_MMA>>>(St, St2, St + NN_, St2 + NN_, Ht0, X);
        gemm_rows_hmma<4,true,true><<<gr1, blk, SMEM_MMA>>>(X, w + WOFF_GCN, gb, sp, 640, XLD_, 640, 128);

        // ---- join + fusion/layernorm ----
        cudaStreamWaitEvent(0, evJ[l], 0);
        fuse_ln_kernel<<<ROWS_, 128>>>(h_in, sp, tp, lg, lb, h_out, X);
    }
}